// round 11
// baseline (speedup 1.0000x reference)
#include <cuda_runtime.h>
#include <cuda_bf16.h>
#include <math.h>
#include <stdint.h>

#define BATCH 512
#define FS 24
#define QDIM 11
#define HID 256
#define OBJ 25
#define EPS 1e-5f

// -------------------- scratch (device globals; no allocation) --------------
__device__ __align__(16) float g_buf1[BATCH * FS * 40 * 40];
__device__ __align__(16) float g_buf2[BATCH * FS * 20 * 20];
__device__ __align__(16) float g_buf3[BATCH * FS * 10 * 10];
__device__ __align__(16) float g_buf4[BATCH * FS * 5 * 5];
__device__ float g_obj[BATCH * OBJ * 26];
__device__ __align__(16) float g_A[BATCH * OBJ * HID];
__device__ __align__(16) float g_B[BATCH * OBJ * HID];
__device__ __align__(16) float g_Cb[BATCH * HID];
__device__ __align__(16) float g_wt[3][HID * HID];   // tf32-rounded weights
__device__ float g_xg[BATCH * HID];
__device__ float g_xf1[BATCH * HID];
__device__ float g_xf2[BATCH * HID];
__device__ double g_psum[4 * 24];
__device__ double g_psq[4 * 24];
__device__ float g_stats[4 * 48];
// g2 output (g3 input)
__device__ __align__(16) float g_hbufB[BATCH * OBJ * OBJ * HID];

// ===================== helpers ==============================================
__device__ __forceinline__ uint32_t smem_u32(const void* p) {
    uint32_t a;
    asm("{ .reg .u64 tmp; cvta.to.shared.u64 tmp, %1; cvt.u32.u64 %0, tmp; }"
        : "=r"(a) : "l"(p));
    return a;
}

#define CP_ASYNC16(dst, src) \
    asm volatile("cp.async.cg.shared.global [%0], [%1], 16;" :: "r"(dst), "l"(src))
#define CP_COMMIT() asm volatile("cp.async.commit_group;")
#define CP_WAIT1() asm volatile("cp.async.wait_group 1;")
#define CP_WAIT0() asm volatile("cp.async.wait_group 0;")

__device__ __forceinline__ float tf32r(float x) {
    uint32_t u;
    asm("cvt.rna.tf32.f32 %0, %1;" : "=r"(u) : "f"(x));
    return __uint_as_float(u);
}

__device__ __forceinline__ void mma_tf32(float* d, const uint32_t* a, const uint32_t* b) {
    asm volatile(
        "mma.sync.aligned.m16n8k8.row.col.f32.tf32.tf32.f32 "
        "{%0,%1,%2,%3}, {%4,%5,%6,%7}, {%8,%9}, {%0,%1,%2,%3};"
        : "+f"(d[0]), "+f"(d[1]), "+f"(d[2]), "+f"(d[3])
        : "r"(a[0]), "r"(a[1]), "r"(a[2]), "r"(a[3]), "r"(b[0]), "r"(b[1]));
}

// -------------------- zero / prep kernels -----------------------------------
__global__ void zerof_k(float* p, int n) {
    int i = blockIdx.x * blockDim.x + threadIdx.x;
    if (i < n) p[i] = 0.f;
}
__global__ void zerod_k(double* p, int n) {
    int i = blockIdx.x * blockDim.x + threadIdx.x;
    if (i < n) p[i] = 0.0;
}
__global__ void wtf32_all(const float* __restrict__ w2, const float* __restrict__ w3,
                          const float* __restrict__ w4, float* __restrict__ o) {
    int idx = blockIdx.x * blockDim.x + threadIdx.x;
    if (idx >= 3 * HID * HID) return;
    int sel = idx >> 16;
    int off = idx & 0xFFFF;
    const float* src = (sel == 0) ? w2 : (sel == 1) ? w3 : w4;
    o[idx] = tf32r(src[off]);
}

// -------------------- conv1: Cin=3, 80->40, P=4 pixels/thread ---------------
__global__ void __launch_bounds__(256)
conv1_f4(const float* __restrict__ in, const float* __restrict__ w,
         const float* __restrict__ bias, float* __restrict__ out,
         double* __restrict__ psum, double* __restrict__ psq) {
    __shared__ float ws[648];
    __shared__ float bs[24];
    __shared__ float srs[8][24];
    __shared__ float srq[8][24];
    int tid = threadIdx.x;
    for (int i = tid; i < 648; i += 256) ws[i] = w[i];
    if (tid < 24) bs[tid] = bias[tid];
    __syncthreads();

    int idx = blockIdx.x * 256 + tid;
    int chunk = idx % 400;
    int b = idx / 400;
    int oy = chunk / 10;
    int ox0 = (chunk % 10) * 4;
    int iy0 = 2 * oy - 1;
    int ix0 = 2 * ox0 - 1;

    float acc[24][4];
#pragma unroll
    for (int c = 0; c < 24; c++)
#pragma unroll
        for (int p = 0; p < 4; p++) acc[c][p] = bs[c];

    const float* ip = in + (size_t)b * 3 * 6400;
#pragma unroll
    for (int ci = 0; ci < 3; ci++) {
        const float* ic = ip + ci * 6400;
#pragma unroll
        for (int ky = 0; ky < 3; ky++) {
            int iy = iy0 + ky;
            bool vy = (unsigned)iy < 80u;
            float iv[9];
#pragma unroll
            for (int j = 0; j < 9; j++) {
                int ix = ix0 + j;
                iv[j] = (vy && (unsigned)ix < 80u) ? ic[iy * 80 + ix] : 0.f;
            }
#pragma unroll
            for (int kx = 0; kx < 3; kx++) {
                int t = ci * 9 + ky * 3 + kx;
#pragma unroll
                for (int co = 0; co < 24; co++) {
                    float wv = ws[co * 27 + t];
#pragma unroll
                    for (int p = 0; p < 4; p++)
                        acc[co][p] = fmaf(iv[2 * p + kx], wv, acc[co][p]);
                }
            }
        }
    }

    int wid = tid >> 5, lane = tid & 31;
    float* op = out + (size_t)b * 24 * 1600 + oy * 40 + ox0;
#pragma unroll
    for (int co = 0; co < 24; co++) {
        float4 y4;
        float* yp = (float*)&y4;
        float s = 0.f, q = 0.f;
#pragma unroll
        for (int p = 0; p < 4; p++) {
            float y = fmaxf(acc[co][p], 0.f);
            yp[p] = y;
            s += y; q += y * y;
        }
        *(float4*)(op + co * 1600) = y4;
#pragma unroll
        for (int off = 16; off > 0; off >>= 1) {
            s += __shfl_xor_sync(0xffffffffu, s, off);
            q += __shfl_xor_sync(0xffffffffu, q, off);
        }
        if (lane == 0) { srs[wid][co] = s; srq[wid][co] = q; }
    }
    __syncthreads();
    if (tid < 24) {
        double S = 0.0, Q = 0.0;
#pragma unroll
        for (int wk = 0; wk < 8; wk++) { S += srs[wk][tid]; Q += srq[wk][tid]; }
        atomicAdd(&psum[tid], S);
        atomicAdd(&psq[tid], Q);
    }
}

// -------------------- convN: Cin=24, P pixels/thread, BN fused --------------
template <int HIN, int HOUT, int P>
__global__ void __launch_bounds__(256)
conv24_fP(const float* __restrict__ in, const float* __restrict__ w,
          const float* __restrict__ bias,
          const float* __restrict__ statsPrev, const float* __restrict__ betaPrev,
          float* __restrict__ out,
          double* __restrict__ psum, double* __restrict__ psq) {
    __shared__ float ws[5184];
    __shared__ float bs[24];
    __shared__ float ab[24];
    __shared__ float dd[24];
    __shared__ float srs[8][24];
    __shared__ float srq[8][24];
    int tid = threadIdx.x;
    for (int i = tid; i < 5184; i += 256) ws[i] = w[i];
    if (tid < 24) {
        bs[tid] = bias[tid];
        float sc = statsPrev[24 + tid];
        ab[tid] = sc;
        dd[tid] = betaPrev[tid] - statsPrev[tid] * sc;
    }
    __syncthreads();

    const int PIX = HOUT * HOUT;
    const int CHW = HOUT / P;
    int idx = blockIdx.x * 256 + tid;
    int chunk = idx % (PIX / P);
    int b = idx / (PIX / P);
    int oy = chunk / CHW;
    int ox0 = (chunk % CHW) * P;
    int iy0 = 2 * oy - 1;
    int ix0 = 2 * ox0 - 1;

    float acc[24][P];
#pragma unroll
    for (int c = 0; c < 24; c++)
#pragma unroll
        for (int p = 0; p < P; p++) acc[c][p] = bs[c];

    const float* ip = in + (size_t)b * 24 * HIN * HIN;
    for (int ci = 0; ci < 24; ci++) {
        float ai = ab[ci], di = dd[ci];
        const float* ic = ip + ci * HIN * HIN;
#pragma unroll
        for (int ky = 0; ky < 3; ky++) {
            int iy = iy0 + ky;
            bool vy = (unsigned)iy < (unsigned)HIN;
            float iv[2 * P + 1];
#pragma unroll
            for (int j = 0; j < 2 * P + 1; j++) {
                int ix = ix0 + j;
                iv[j] = (vy && (unsigned)ix < (unsigned)HIN)
                            ? fmaf(ic[iy * HIN + ix], ai, di) : 0.f;
            }
#pragma unroll
            for (int kx = 0; kx < 3; kx++) {
                int t = ci * 9 + ky * 3 + kx;
#pragma unroll
                for (int co = 0; co < 24; co++) {
                    float wv = ws[co * 216 + t];
#pragma unroll
                    for (int p = 0; p < P; p++)
                        acc[co][p] = fmaf(iv[2 * p + kx], wv, acc[co][p]);
                }
            }
        }
    }

    int wid = tid >> 5, lane = tid & 31;
    float* op = out + (size_t)b * 24 * PIX + oy * HOUT + ox0;
#pragma unroll
    for (int co = 0; co < 24; co++) {
        float yv[P];
        float s = 0.f, q = 0.f;
#pragma unroll
        for (int p = 0; p < P; p++) {
            float y = fmaxf(acc[co][p], 0.f);
            yv[p] = y;
            s += y; q += y * y;
        }
        if (P == 4) {
            float4 y4 = {yv[0], yv[1], yv[2], yv[3]};
            *(float4*)(op + co * PIX) = y4;
        } else if (P == 2) {
            float2 y2 = {yv[0], yv[1]};
            *(float2*)(op + co * PIX) = y2;
        } else {
#pragma unroll
            for (int p = 0; p < P; p++) op[co * PIX + p] = yv[p];
        }
#pragma unroll
        for (int off = 16; off > 0; off >>= 1) {
            s += __shfl_xor_sync(0xffffffffu, s, off);
            q += __shfl_xor_sync(0xffffffffu, q, off);
        }
        if (lane == 0) { srs[wid][co] = s; srq[wid][co] = q; }
    }
    __syncthreads();
    if (tid < 24) {
        double S = 0.0, Q = 0.0;
#pragma unroll
        for (int wk = 0; wk < 8; wk++) { S += srs[wk][tid]; Q += srq[wk][tid]; }
        atomicAdd(&psum[tid], S);
        atomicAdd(&psq[tid], Q);
    }
}

// -------------------- finalize BN stats -------------------------------------
__global__ void bn_final_f(const double* __restrict__ psum, const double* __restrict__ psq,
                           double N, const float* __restrict__ gamma,
                           float* __restrict__ stats) {
    int c = threadIdx.x;
    if (c >= 24) return;
    double mean = psum[c] / N;
    double var = psq[c] / N - mean * mean;
    stats[c] = (float)mean;
    stats[24 + c] = gamma[c] * rsqrtf((float)var + EPS);
}

// -------------------- object extraction (applies BN4) -----------------------
__global__ void obj_f(const float* __restrict__ x4, const float* __restrict__ stats4,
                      const float* __restrict__ beta4, float* __restrict__ obj) {
    int idx = blockIdx.x * blockDim.x + threadIdx.x;
    const int total = BATCH * OBJ * 26;
    if (idx >= total) return;
    int f = idx % 26; int t = idx / 26;
    int o = t % OBJ; int b = t / OBJ;
    float v;
    if (f < FS) {
        float y = x4[((size_t)b * FS + f) * OBJ + o];
        v = (y - stats4[f]) * stats4[24 + f] + beta4[f];
    } else if (f == FS) v = ((float)(o / 5) - 2.f) * 0.5f;
    else v = ((float)(o % 5) - 2.f) * 0.5f;
    obj[idx] = v;
}

// -------------------- g1 decomposition --------------------------------------
__global__ void ab_k(const float* __restrict__ obj, const float* __restrict__ g1w,
                     float* __restrict__ A, float* __restrict__ B) {
    int m = blockIdx.x;
    int n = threadIdx.x;
    __shared__ float os[26];
    if (n < 26) os[n] = obj[m * 26 + n];
    __syncthreads();
    const float* wr = g1w + n * 63;
    float sa = 0.f, sb = 0.f;
#pragma unroll
    for (int f = 0; f < 26; f++) {
        float o = os[f];
        sa += o * __ldg(&wr[f]);
        sb += o * __ldg(&wr[26 + f]);
    }
    A[m * HID + n] = sa;
    B[m * HID + n] = sb;
}

__global__ void cb_k(const float* __restrict__ qst, const float* __restrict__ g1w,
                     const float* __restrict__ g1b, float* __restrict__ Cb) {
    int b = blockIdx.x;
    int n = threadIdx.x;
    __shared__ float qs[QDIM];
    if (n < QDIM) qs[n] = qst[n * BATCH + b];
    __syncthreads();
    const float* wr = g1w + n * 63 + 52;
    float s = g1b[n];
#pragma unroll
    for (int d = 0; d < QDIM; d++) s += qs[d] * __ldg(&wr[d]);
    Cb[b * HID + n] = s;
}

// ==================== g2: fused h1 build + tf32 GEMM ========================
#define TPAD 20
#define L2PAD 260
#define GL2_SMEM ((128 * L2PAD + 2 * 128 * TPAD + 128) * 4)

__global__ void __launch_bounds__(256, 1)
gmlp_l2(const float* __restrict__ Ag, const float* __restrict__ Bg,
        const float* __restrict__ Cg, const float* __restrict__ W,
        const float* __restrict__ bias, float* __restrict__ Y) {
    extern __shared__ float sm[];
    float* h1s = sm;
    float* Ws = sm + 128 * L2PAD;
    float* biasS = Ws + 2 * 128 * TPAD;

    const int tid = threadIdx.x;
    const int wid = tid >> 5;
    const int lane = tid & 31;
    const int wm = wid >> 2;
    const int wn = wid & 3;
    const int n0 = blockIdx.x * 128;
    const size_t mBase = (size_t)blockIdx.y * 128;

    if (tid < 128) biasS[tid] = __ldg(&bias[n0 + tid]);

    const int lr = tid >> 1;
    const int lh = tid & 1;
    {
        int r = (int)mBase + lr;
        int b = r / 625;
        int rem = r - b * 625;
        int ko = rem / 25;
        int ii = rem - ko * 25;
        const float4* pA = (const float4*)(Ag + (b * 25 + ii) * 256);
        const float4* pB = (const float4*)(Bg + (b * 25 + ko) * 256);
        const float4* pC = (const float4*)(Cg + b * 256);
#pragma unroll 4
        for (int j = 0; j < 16; j++) {
            int col = lh * 8 + j * 16;
            int c4 = col >> 2;
            float4 a0 = __ldg(pA + c4), a1 = __ldg(pA + c4 + 1);
            float4 b0 = __ldg(pB + c4), b1 = __ldg(pB + c4 + 1);
            float4 c0 = __ldg(pC + c4), c1 = __ldg(pC + c4 + 1);
            float4 o0, o1;
            o0.x = tf32r(fmaxf(a0.x + b0.x + c0.x, 0.f));
            o0.y = tf32r(fmaxf(a0.y + b0.y + c0.y, 0.f));
            o0.z = tf32r(fmaxf(a0.z + b0.z + c0.z, 0.f));
            o0.w = tf32r(fmaxf(a0.w + b0.w + c0.w, 0.f));
            o1.x = tf32r(fmaxf(a1.x + b1.x + c1.x, 0.f));
            o1.y = tf32r(fmaxf(a1.y + b1.y + c1.y, 0.f));
            o1.z = tf32r(fmaxf(a1.z + b1.z + c1.z, 0.f));
            o1.w = tf32r(fmaxf(a1.w + b1.w + c1.w, 0.f));
            *(float4*)&h1s[lr * L2PAD + col] = o0;
            *(float4*)&h1s[lr * L2PAD + col + 4] = o1;
        }
    }

    const float* Wt = W + (size_t)n0 * 256;
    const uint32_t wRaw = smem_u32(Ws);
    auto issue = [&](int buf, int k0) {
        uint32_t bd = wRaw + buf * (128 * TPAD * 4) + lr * (TPAD * 4) + lh * 32;
        const float* wsrc = Wt + lr * 256 + k0 + lh * 8;
        CP_ASYNC16(bd, wsrc);
        CP_ASYNC16(bd + 16, wsrc + 4);
    };

    float acc[4][4][4];
#pragma unroll
    for (int i = 0; i < 4; i++)
#pragma unroll
        for (int j = 0; j < 4; j++)
#pragma unroll
            for (int r = 0; r < 4; r++) acc[i][j][r] = 0.f;

    issue(0, 0);
    CP_COMMIT();
    __syncthreads();

    const int lq = lane >> 2;
    const int lk = lane & 3;

#pragma unroll 1
    for (int kt = 0; kt < 16; kt++) {
        int buf = kt & 1;
        if (kt < 15) { issue(buf ^ 1, (kt + 1) * 16); CP_COMMIT(); CP_WAIT1(); }
        else CP_WAIT0();
        __syncthreads();

#pragma unroll
        for (int ks = 0; ks < 2; ks++) {
            int kk = kt * 16 + ks * 8 + lk;
            uint32_t af[4][4];
#pragma unroll
            for (int mf = 0; mf < 4; mf++) {
                const float* ap = &h1s[(wm * 64 + mf * 16 + lq) * L2PAD + kk];
                af[mf][0] = __float_as_uint(ap[0]);
                af[mf][1] = __float_as_uint(ap[8 * L2PAD]);
                af[mf][2] = __float_as_uint(ap[4]);
                af[mf][3] = __float_as_uint(ap[8 * L2PAD + 4]);
            }
            int kw = ks * 8 + lk;
            uint32_t bfr[4][2];
#pragma unroll
            for (int nf = 0; nf < 4; nf++) {
                const float* bp = &Ws[buf * 128 * TPAD + (wn * 32 + nf * 8 + lq) * TPAD + kw];
                bfr[nf][0] = __float_as_uint(bp[0]);
                bfr[nf][1] = __float_as_uint(bp[4]);
            }
#pragma unroll
            for (int mf = 0; mf < 4; mf++)
#pragma unroll
                for (int nf = 0; nf < 4; nf++)
                    mma_tf32(acc[mf][nf], af[mf], bfr[nf]);
        }
        __syncthreads();
    }

#pragma unroll
    for (int mf = 0; mf < 4; mf++) {
        size_t r0 = mBase + wm * 64 + mf * 16 + lq;
        float* y0 = Y + r0 * 256 + n0;
        float* y1 = y0 + 8 * 256;
#pragma unroll
        for (int nf = 0; nf < 4; nf++) {
            int col = wn * 32 + nf * 8 + 2 * lk;
            float b0 = biasS[col], b1 = biasS[col + 1];
            float v0 = tf32r(fmaxf(acc[mf][nf][0] + b0, 0.f));
            float v1 = tf32r(fmaxf(acc[mf][nf][1] + b1, 0.f));
            float v2 = tf32r(fmaxf(acc[mf][nf][2] + b0, 0.f));
            float v3 = tf32r(fmaxf(acc[mf][nf][3] + b1, 0.f));
            float2 p0 = {v0, v1};
            float2 p1 = {v2, v3};
            *(float2*)(y0 + col) = p0;
            *(float2*)(y1 + col) = p1;
        }
    }
}

// ==================== g3+g4 fused: X -> relu(XW3+b3) -> relu(.W4+b4) -> pairsum
// MT=64 rows per CTA, N=256. 2 CTAs/SM. K-chunk = 8 (dbuf cp.async).
#define XPAD 12
#define WPAD3 12
#define H3PAD 258
// floats: Xs 2*64*12=1536, Ws 2*256*12=6144, H3 64*258=16512, bias 512
#define L34_SMEM ((1536 + 6144 + 16512 + 512) * 4)

__global__ void __launch_bounds__(256, 2)
gmlp_l34(const float* __restrict__ X, const float* __restrict__ W3,
         const float* __restrict__ W4, const float* __restrict__ b3,
         const float* __restrict__ b4, float* __restrict__ xg) {
    extern __shared__ float sm[];
    float* Xs = sm;                        // [2][64*XPAD]
    float* Ws = sm + 2 * 64 * XPAD;        // [2][256*WPAD3]
    float* H3 = Ws + 2 * 256 * WPAD3;      // [64*H3PAD]
    float* biasS = H3 + 64 * H3PAD;        // [512] = b3 | b4

    const int tid = threadIdx.x;
    const int wid = tid >> 5, lane = tid & 31;
    const int wm = wid >> 2, wn = wid & 3;
    const int lq = lane >> 2, lk = lane & 3;
    const int mBase = blockIdx.x * 64;

    biasS[tid] = __ldg(&b3[tid]);
    biasS[256 + tid] = __ldg(&b4[tid]);

    const float* Xt = X + (size_t)mBase * 256;
    const uint32_t xRaw = smem_u32(Xs);
    const uint32_t wRaw = smem_u32(Ws);

    auto issueX = [&](int buf, int k0) {
        if (tid < 128) {
            int row = tid >> 1, h = tid & 1;
            CP_ASYNC16(xRaw + buf * (64 * XPAD * 4) + row * (XPAD * 4) + h * 16,
                       Xt + row * 256 + k0 + h * 4);
        }
    };
    auto issueW = [&](const float* Wg, int buf, int k0) {
        uint32_t d = wRaw + buf * (256 * WPAD3 * 4) + tid * (WPAD3 * 4);
        const float* s = Wg + tid * 256 + k0;
        CP_ASYNC16(d, s);
        CP_ASYNC16(d + 16, s + 4);
    };

    float acc[2][8][4];
#pragma unroll
    for (int i = 0; i < 2; i++)
#pragma unroll
        for (int j = 0; j < 8; j++)
#pragma unroll
            for (int r = 0; r < 4; r++) acc[i][j][r] = 0.f;

    // ---------------- GEMM3: acc = X @ W3^T ----------------
    issueX(0, 0); issueW(W3, 0, 0);
    CP_COMMIT();
#pragma unroll 1
    for (int kt = 0; kt < 32; kt++) {
        int buf = kt & 1;
        if (kt < 31) {
            issueX(buf ^ 1, (kt + 1) * 8);
            issueW(W3, buf ^ 1, (kt + 1) * 8);
            CP_COMMIT(); CP_WAIT1();
        } else CP_WAIT0();
        __syncthreads();

        uint32_t af[2][4];
#pragma unroll
        for (int mf = 0; mf < 2; mf++) {
            const float* ap = &Xs[buf * (64 * XPAD) + (wm * 32 + mf * 16 + lq) * XPAD + lk];
            af[mf][0] = __float_as_uint(ap[0]);
            af[mf][1] = __float_as_uint(ap[8 * XPAD]);
            af[mf][2] = __float_as_uint(ap[4]);
            af[mf][3] = __float_as_uint(ap[8 * XPAD + 4]);
        }
#pragma unroll
        for (int nf = 0; nf < 8; nf++) {
            const float* bp = &Ws[buf * (256 * WPAD3) + (wn * 64 + nf * 8 + lq) * WPAD3 + lk];
            uint32_t bfr[2];
            bfr[0] = __float_as_uint(bp[0]);
            bfr[1] = __float_as_uint(bp[4]);
            mma_tf32(acc[0][nf], af[0], bfr);
            mma_tf32(acc[1][nf], af[1], bfr);
        }
        __syncthreads();
    }

    // ---------------- epilogue g3 -> H3 (bias+relu+tf32r) ----------------
#pragma unroll
    for (int mf = 0; mf < 2; mf++) {
        int r = wm * 32 + mf * 16 + lq;
#pragma unroll
        for (int nf = 0; nf < 8; nf++) {
            int col = wn * 64 + nf * 8 + 2 * lk;
            float b0v = biasS[col], b1v = biasS[col + 1];
            float v0 = tf32r(fmaxf(acc[mf][nf][0] + b0v, 0.f));
            float v1 = tf32r(fmaxf(acc[mf][nf][1] + b1v, 0.f));
            float v2 = tf32r(fmaxf(acc[mf][nf][2] + b0v, 0.f));
            float v3 = tf32r(fmaxf(acc[mf][nf][3] + b1v, 0.f));
            float2 p0 = {v0, v1};
            float2 p1 = {v2, v3};
            *(float2*)&H3[r * H3PAD + col] = p0;
            *(float2*)&H3[(r + 8) * H3PAD + col] = p1;
        }
    }
    __syncthreads();

    // ---------------- GEMM4: acc = H3 @ W4^T ----------------
#pragma unroll
    for (int i = 0; i < 2; i++)
#pragma unroll
        for (int j = 0; j < 8; j++)
#pragma unroll
            for (int r = 0; r < 4; r++) acc[i][j][r] = 0.f;

    issueW(W4, 0, 0);
    CP_COMMIT();
#pragma unroll 1
    for (int kt = 0; kt < 32; kt++) {
        int buf = kt & 1;
        if (kt < 31) {
            issueW(W4, buf ^ 1, (kt + 1) * 8);
            CP_COMMIT(); CP_WAIT1();
        } else CP_WAIT0();
        __syncthreads();

        int kkH = kt * 8 + lk;
        uint32_t af[2][4];
#pragma unroll
        for (int mf = 0; mf < 2; mf++) {
            const float* ap = &H3[(wm * 32 + mf * 16 + lq) * H3PAD + kkH];
            af[mf][0] = __float_as_uint(ap[0]);
            af[mf][1] = __float_as_uint(ap[8 * H3PAD]);
            af[mf][2] = __float_as_uint(ap[4]);
            af[mf][3] = __float_as_uint(ap[8 * H3PAD + 4]);
        }
#pragma unroll
        for (int nf = 0; nf < 8; nf++) {
            const float* bp = &Ws[buf * (256 * WPAD3) + (wn * 64 + nf * 8 + lq) * WPAD3 + lk];
            uint32_t bfr[2];
            bfr[0] = __float_as_uint(bp[0]);
            bfr[1] = __float_as_uint(bp[4]);
            mma_tf32(acc[0][nf], af[0], bfr);
            mma_tf32(acc[1][nf], af[1], bfr);
        }
        __syncthreads();
    }

    // ---------------- fused pairsum epilogue ----------------
    const float* b4s = biasS + 256;
    int b0 = mBase / 625;
    int split = (b0 + 1) * 625;
    bool hasSplit = split < mBase + 64;

    float cs0[8][2], cs1[8][2];
#pragma unroll
    for (int nf = 0; nf < 8; nf++) { cs0[nf][0] = cs0[nf][1] = 0.f; cs1[nf][0] = cs1[nf][1] = 0.f; }

#pragma unroll
    for (int mf = 0; mf < 2; mf++) {
        int rA = mBase + wm * 32 + mf * 16 + lq;
        int rB = rA + 8;
        bool pA = rA >= split;
        bool pB = rB >= split;
#pragma unroll
        for (int nf = 0; nf < 8; nf++) {
            int col = wn * 64 + nf * 8 + 2 * lk;
            float bb0 = b4s[col], bb1 = b4s[col + 1];
            float v0 = fmaxf(acc[mf][nf][0] + bb0, 0.f);
            float v1 = fmaxf(acc[mf][nf][1] + bb1, 0.f);
            float v2 = fmaxf(acc[mf][nf][2] + bb0, 0.f);
            float v3 = fmaxf(acc[mf][nf][3] + bb1, 0.f);
            if (pA) { cs1[nf][0] += v0; cs1[nf][1] += v1; }
            else    { cs0[nf][0] += v0; cs0[nf][1] += v1; }
            if (pB) { cs1[nf][0] += v2; cs1[nf][1] += v3; }
            else    { cs0[nf][0] += v2; cs0[nf][1] += v3; }
        }
    }
#pragma unroll
    for (int off = 4; off <= 16; off <<= 1) {
#pragma unroll
        for (int nf = 0; nf < 8; nf++) {
            cs0[nf][0] += __shfl_xor_sync(0xffffffffu, cs0[nf][0], off);
            cs0[nf][1] += __shfl_xor_sync(0xffffffffu, cs0[nf][1], off);
            cs1[nf][0] += __shfl_xor_sync(0xffffffffu, cs1[nf][0], off);
            cs1[nf][1] += __shfl_xor_sync(0xffffffffu, cs1[nf][1], off);
        }
    }
    if (lq == 0) {
#pragma unroll
        for (int nf = 0; nf < 8; nf++) {
#pragma unroll
            for (int p = 0; p < 2; p++) {
                int col = wn * 64 + nf * 8 + 2 * lk + p;
                atomicAdd(&xg[b0 * 256 + col], cs0[nf][p]);
                if (hasSplit) atomicAdd(&xg[(b0 + 1) * 256 + col], cs1[nf][p]);
            }
        }
    }
}

// -------------------- fp32 SGEMM (small f-layers) ---------------------------
__global__ void sgemm256(const float* __restrict__ X, const float* __restrict__ W,
                         const float* __restrict__ bias, float* __restrict__ out,
                         int doRelu) {
    __shared__ float Xs[16][128];
    __shared__ float Ws[16][64];
    int bm = blockIdx.y * 128;
    int bn = blockIdx.x * 64;
    int tid = threadIdx.x;
    int tx = tid & 15, ty = tid >> 4;
    float acc[8][4];
#pragma unroll
    for (int i = 0; i < 8; i++)
#pragma unroll
        for (int j = 0; j < 4; j++) acc[i][j] = 0.f;

    int r0 = tid >> 2;
    int c0 = (tid & 3) * 4;
    const float* Xp = X + (size_t)bm * 256;

    for (int k0 = 0; k0 < 256; k0 += 16) {
        float4 x0 = *(const float4*)(Xp + (size_t)r0 * 256 + k0 + c0);
        float4 x1 = *(const float4*)(Xp + (size_t)(r0 + 64) * 256 + k0 + c0);
        float4 wv = *(const float4*)(W + (size_t)(bn + r0) * 256 + k0 + c0);
        Xs[c0 + 0][r0] = x0.x; Xs[c0 + 1][r0] = x0.y; Xs[c0 + 2][r0] = x0.z; Xs[c0 + 3][r0] = x0.w;
        Xs[c0 + 0][r0 + 64] = x1.x; Xs[c0 + 1][r0 + 64] = x1.y; Xs[c0 + 2][r0 + 64] = x1.z; Xs[c0 + 3][r0 + 64] = x1.w;
        Ws[c0 + 0][r0] = wv.x; Ws[c0 + 1][r0] = wv.y; Ws[c0 + 2][r0] = wv.z; Ws[c0 + 3][r0] = wv.w;
        __syncthreads();
#pragma unroll
        for (int k = 0; k < 16; k++) {
            float4 a0 = *(const float4*)&Xs[k][ty * 8];
            float4 a1 = *(const float4*)&Xs[k][ty * 8 + 4];
            float4 b = *(const float4*)&Ws[k][tx * 4];
            acc[0][0] += a0.x * b.x; acc[0][1] += a0.x * b.y; acc[0][2] += a0.x * b.z; acc[0][3] += a0.x * b.w;
            acc[1][0] += a0.y * b.x; acc[1][1] += a0.y * b.y; acc[1][2] += a0.y * b.z; acc[1][3] += a0.y * b.w;
            acc[2][0] += a0.z * b.x; acc[2][1] += a0.z * b.y; acc[2][2] += a0.z * b.z; acc[2][3] += a0.z * b.w;
            acc[3][0] += a0.w * b.x; acc[3][1] += a0.w * b.y; acc[3][2] += a0.w * b.z; acc[3][3] += a0.w * b.w;
            acc[4][0] += a1.x * b.x; acc[4][1] += a1.x * b.y; acc[4][2] += a1.x * b.z; acc[4][3] += a1.x * b.w;
            acc[5][0] += a1.y * b.x; acc[5][1] += a1.y * b.y; acc[5][2] += a1.y * b.z; acc[5][3] += a1.y * b.w;
            acc[6][0] += a1.z * b.x; acc[6][1] += a1.z * b.y; acc[6][2] += a1.z * b.z; acc[6][3] += a1.z * b.w;
            acc[7][0] += a1.w * b.x; acc[7][1] += a1.w * b.y; acc[7][2] += a1.w * b.z; acc[7][3] += a1.w * b.w;
        }
        __syncthreads();
    }
    float4 bv = *(const float4*)&bias[bn + tx * 4];
#pragma unroll
    for (int i = 0; i < 8; i++) {
        int m = bm + ty * 8 + i;
        float4 v;
        v.x = acc[i][0] + bv.x; v.y = acc[i][1] + bv.y;
        v.z = acc[i][2] + bv.z; v.w = acc[i][3] + bv.w;
        if (doRelu) {
            v.x = fmaxf(v.x, 0.f); v.y = fmaxf(v.y, 0.f);
            v.z = fmaxf(v.z, 0.f); v.w = fmaxf(v.w, 0.f);
        }
        *(float4*)(out + (size_t)m * 256 + bn + tx * 4) = v;
    }
}

// -------------------- fc3 + log_softmax -------------------------------------
__global__ void fc3_k(const float* __restrict__ x, const float* __restrict__ w,
                      const float* __restrict__ bias, float* __restrict__ out) {
    int b = blockIdx.x;
    int tid = threadIdx.x; // 320
    int j = tid >> 5, lane = tid & 31;
    __shared__ float lg[10];
    __shared__ float lse;
    const float* xr = x + b * HID;
    const float* wr = w + j * HID;
    float s = 0.f;
    for (int k = lane; k < HID; k += 32) s += xr[k] * wr[k];
#pragma unroll
    for (int o = 16; o > 0; o >>= 1) s += __shfl_xor_sync(0xffffffffu, s, o);
    if (lane == 0) lg[j] = s + bias[j];
    __syncthreads();
    if (tid == 0) {
        float m = lg[0];
#pragma unroll
        for (int t = 1; t < 10; t++) m = fmaxf(m, lg[t]);
        float se = 0.f;
#pragma unroll
        for (int t = 0; t < 10; t++) se += expf(lg[t] - m);
        lse = m + logf(se);
    }
    __syncthreads();
    if (tid < 10) out[b * 10 + tid] = lg[tid] - lse;
}

// ---------------------------------------------------------------------------
extern "C" void kernel_launch(void* const* d_in, const int* in_sizes, int n_in,
                              void* d_out, int out_size) {
    const float* img = (const float*)d_in[0];
    const float* qst = (const float*)d_in[1];
    const float* cw[4] = {(const float*)d_in[2], (const float*)d_in[6], (const float*)d_in[10], (const float*)d_in[14]};
    const float* cb[4] = {(const float*)d_in[3], (const float*)d_in[7], (const float*)d_in[11], (const float*)d_in[15]};
    const float* bg[4] = {(const float*)d_in[4], (const float*)d_in[8], (const float*)d_in[12], (const float*)d_in[16]};
    const float* bb[4] = {(const float*)d_in[5], (const float*)d_in[9], (const float*)d_in[13], (const float*)d_in[17]};
    const float* g1w = (const float*)d_in[18]; const float* g1b = (const float*)d_in[19];
    const float* g2w = (const float*)d_in[20]; const float* g2b = (const float*)d_in[21];
    const float* g3w = (const float*)d_in[22]; const float* g3b = (const float*)d_in[23];
    const float* g4w = (const float*)d_in[24]; const float* g4b = (const float*)d_in[25];
    const float* f1w = (const float*)d_in[26]; const float* f1b = (const float*)d_in[27];
    const float* fc2w = (const float*)d_in[28]; const float* fc2b = (const float*)d_in[29];
    const float* fc3w = (const float*)d_in[30]; const float* fc3b = (const float*)d_in[31];
    float* out = (float*)d_out;

    float *buf1, *buf2, *buf3, *buf4, *obj, *A, *B, *Cb, *xg, *xf1, *xf2, *stats, *wt, *hB;
    double *psum, *psq;
    cudaGetSymbolAddress((void**)&buf1, g_buf1);
    cudaGetSymbolAddress((void**)&buf2, g_buf2);
    cudaGetSymbolAddress((void**)&buf3, g_buf3);
    cudaGetSymbolAddress((void**)&buf4, g_buf4);
    cudaGetSymbolAddress((void**)&obj, g_obj);
    cudaGetSymbolAddress((void**)&A, g_A);
    cudaGetSymbolAddress((void**)&B, g_B);
    cudaGetSymbolAddress((void**)&Cb, g_Cb);
    cudaGetSymbolAddress((void**)&xg, g_xg);
    cudaGetSymbolAddress((void**)&xf1, g_xf1);
    cudaGetSymbolAddress((void**)&xf2, g_xf2);
    cudaGetSymbolAddress((void**)&stats, g_stats);
    cudaGetSymbolAddress((void**)&psum, g_psum);
    cudaGetSymbolAddress((void**)&psq, g_psq);
    cudaGetSymbolAddress((void**)&wt, g_wt);
    cudaGetSymbolAddress((void**)&hB, g_hbufB);

    cudaFuncSetAttribute(gmlp_l2, cudaFuncAttributeMaxDynamicSharedMemorySize, GL2_SMEM);
    cudaFuncSetAttribute(gmlp_l34, cudaFuncAttributeMaxDynamicSharedMemorySize, L34_SMEM);

    // ---- zero accumulators + weight prep ----
    zerod_k<<<1, 128>>>(psum, 96);
    zerod_k<<<1, 128>>>(psq, 96);
    zerof_k<<<512, 256>>>(xg, BATCH * HID);
    wtf32_all<<<768, 256>>>(g2w, g3w, g4w, wt);

    // ---- conv stack (fused BN, pixel-blocked) ----
    conv1_f4<<<800, 256>>>(img, cw[0], cb[0], buf1, psum, psq);
    bn_final_f<<<1, 32>>>(psum, psq, 512.0 * 1600.0, bg[0], stats);
    conv24_fP<40, 20, 4><<<200, 256>>>(buf1, cw[1], cb[1], stats, bb[0], buf2, psum + 24, psq + 24);
    bn_final_f<<<1, 32>>>(psum + 24, psq + 24, 512.0 * 400.0, bg[1], stats + 48);
    conv24_fP<20, 10, 2><<<100, 256>>>(buf2, cw[2], cb[2], stats + 48, bb[1], buf3, psum + 48, psq + 48);
    bn_final_f<<<1, 32>>>(psum + 48, psq + 48, 512.0 * 100.0, bg[2], stats + 96);
    conv24_fP<10, 5, 1><<<50, 256>>>(buf3, cw[3], cb[3], stats + 96, bb[2], buf4, psum + 72, psq + 72);
    bn_final_f<<<1, 32>>>(psum + 72, psq + 72, 512.0 * 25.0, bg[3], stats + 144);

    // ---- objects + decomposed g1 ----
    obj_f<<<(BATCH * OBJ * 26 + 255) / 256, 256>>>(buf4, stats + 144, bb[3], obj);
    ab_k<<<BATCH * OBJ, 256>>>(obj, g1w, A, B);
    cb_k<<<BATCH, 256>>>(qst, g1w, g1b, Cb);

    // ---- g2 (fused h1) -> fused g3+g4+pairsum ----
    dim3 ggrid(2, BATCH * OBJ * OBJ / 128);  // (2, 2500)
    gmlp_l2<<<ggrid, 256, GL2_SMEM>>>(A, B, Cb, wt, g2b, hB);
    gmlp_l34<<<BATCH * OBJ * OBJ / 64, 256, L34_SMEM>>>(
        hB, wt + HID * HID, wt + 2 * HID * HID, g3b, g4b, xg);

    // ---- f-MLP (fp32) ----
    dim3 fgrid(256 / 64, BATCH / 128);
    sgemm256<<<fgrid, 256>>>(xg, f1w, f1b, xf1, 1);
    sgemm256<<<fgrid, 256>>>(xf1, fc2w, fc2b, xf2, 1);
    fc3_k<<<BATCH, 320>>>(xf2, fc3w, fc3b, out);
}

// round 12
// speedup vs baseline: 1.1447x; 1.1447x over previous
#include <cuda_runtime.h>
#include <cuda_bf16.h>
#include <math.h>
#include <stdint.h>

#define BATCH 512
#define FS 24
#define QDIM 11
#define HID 256
#define OBJ 25
#define EPS 1e-5f

// -------------------- scratch (device globals; no allocation) --------------
__device__ __align__(16) float g_buf1[BATCH * FS * 40 * 40];
__device__ __align__(16) float g_buf2[BATCH * FS * 20 * 20];
__device__ __align__(16) float g_buf3[BATCH * FS * 10 * 10];
__device__ __align__(16) float g_buf4[BATCH * FS * 5 * 5];
__device__ float g_obj[BATCH * OBJ * 26];
__device__ __align__(16) float g_A[BATCH * OBJ * HID];
__device__ __align__(16) float g_B[BATCH * OBJ * HID];
__device__ __align__(16) float g_Cb[BATCH * HID];
__device__ __align__(16) float g_wt[3][HID * HID];   // tf32-rounded weights
__device__ float g_xg[BATCH * HID];
__device__ float g_xf1[BATCH * HID];
__device__ float g_xf2[BATCH * HID];
__device__ double g_psum[4 * 24];
__device__ double g_psq[4 * 24];
__device__ float g_stats[4 * 48];
// big intermediate activation buffers (g2 out / g3 out)
__device__ __align__(16) float g_hbufA[BATCH * OBJ * OBJ * HID];
__device__ __align__(16) float g_hbufB[BATCH * OBJ * OBJ * HID];

// ===================== helpers ==============================================
__device__ __forceinline__ uint32_t smem_u32(const void* p) {
    uint32_t a;
    asm("{ .reg .u64 tmp; cvta.to.shared.u64 tmp, %1; cvt.u32.u64 %0, tmp; }"
        : "=r"(a) : "l"(p));
    return a;
}

#define CP_ASYNC16(dst, src) \
    asm volatile("cp.async.cg.shared.global [%0], [%1], 16;" :: "r"(dst), "l"(src))
#define CP_COMMIT() asm volatile("cp.async.commit_group;")
#define CP_WAIT1() asm volatile("cp.async.wait_group 1;")
#define CP_WAIT0() asm volatile("cp.async.wait_group 0;")

__device__ __forceinline__ float tf32r(float x) {
    uint32_t u;
    asm("cvt.rna.tf32.f32 %0, %1;" : "=r"(u) : "f"(x));
    return __uint_as_float(u);
}

__device__ __forceinline__ void mma_tf32(float* d, const uint32_t* a, const uint32_t* b) {
    asm volatile(
        "mma.sync.aligned.m16n8k8.row.col.f32.tf32.tf32.f32 "
        "{%0,%1,%2,%3}, {%4,%5,%6,%7}, {%8,%9}, {%0,%1,%2,%3};"
        : "+f"(d[0]), "+f"(d[1]), "+f"(d[2]), "+f"(d[3])
        : "r"(a[0]), "r"(a[1]), "r"(a[2]), "r"(a[3]), "r"(b[0]), "r"(b[1]));
}

// -------------------- zero / prep kernels -----------------------------------
__global__ void zerof_k(float* p, int n) {
    int i = blockIdx.x * blockDim.x + threadIdx.x;
    if (i < n) p[i] = 0.f;
}
__global__ void zerod_k(double* p, int n) {
    int i = blockIdx.x * blockDim.x + threadIdx.x;
    if (i < n) p[i] = 0.0;
}
__global__ void wtf32_all(const float* __restrict__ w2, const float* __restrict__ w3,
                          const float* __restrict__ w4, float* __restrict__ o) {
    int idx = blockIdx.x * blockDim.x + threadIdx.x;
    if (idx >= 3 * HID * HID) return;
    int sel = idx >> 16;
    int off = idx & 0xFFFF;
    const float* src = (sel == 0) ? w2 : (sel == 1) ? w3 : w4;
    o[idx] = tf32r(src[off]);
}

// -------------------- conv1: Cin=3, 80->40, P=4 pixels/thread ---------------
__global__ void __launch_bounds__(256)
conv1_f4(const float* __restrict__ in, const float* __restrict__ w,
         const float* __restrict__ bias, float* __restrict__ out,
         double* __restrict__ psum, double* __restrict__ psq) {
    __shared__ float ws[648];
    __shared__ float bs[24];
    __shared__ float srs[8][24];
    __shared__ float srq[8][24];
    int tid = threadIdx.x;
    for (int i = tid; i < 648; i += 256) ws[i] = w[i];
    if (tid < 24) bs[tid] = bias[tid];
    __syncthreads();

    int idx = blockIdx.x * 256 + tid;
    int chunk = idx % 400;
    int b = idx / 400;
    int oy = chunk / 10;
    int ox0 = (chunk % 10) * 4;
    int iy0 = 2 * oy - 1;
    int ix0 = 2 * ox0 - 1;

    float acc[24][4];
#pragma unroll
    for (int c = 0; c < 24; c++)
#pragma unroll
        for (int p = 0; p < 4; p++) acc[c][p] = bs[c];

    const float* ip = in + (size_t)b * 3 * 6400;
#pragma unroll
    for (int ci = 0; ci < 3; ci++) {
        const float* ic = ip + ci * 6400;
#pragma unroll
        for (int ky = 0; ky < 3; ky++) {
            int iy = iy0 + ky;
            bool vy = (unsigned)iy < 80u;
            float iv[9];
#pragma unroll
            for (int j = 0; j < 9; j++) {
                int ix = ix0 + j;
                iv[j] = (vy && (unsigned)ix < 80u) ? ic[iy * 80 + ix] : 0.f;
            }
#pragma unroll
            for (int kx = 0; kx < 3; kx++) {
                int t = ci * 9 + ky * 3 + kx;
#pragma unroll
                for (int co = 0; co < 24; co++) {
                    float wv = ws[co * 27 + t];
#pragma unroll
                    for (int p = 0; p < 4; p++)
                        acc[co][p] = fmaf(iv[2 * p + kx], wv, acc[co][p]);
                }
            }
        }
    }

    int wid = tid >> 5, lane = tid & 31;
    float* op = out + (size_t)b * 24 * 1600 + oy * 40 + ox0;
#pragma unroll
    for (int co = 0; co < 24; co++) {
        float4 y4;
        float* yp = (float*)&y4;
        float s = 0.f, q = 0.f;
#pragma unroll
        for (int p = 0; p < 4; p++) {
            float y = fmaxf(acc[co][p], 0.f);
            yp[p] = y;
            s += y; q += y * y;
        }
        *(float4*)(op + co * 1600) = y4;
#pragma unroll
        for (int off = 16; off > 0; off >>= 1) {
            s += __shfl_xor_sync(0xffffffffu, s, off);
            q += __shfl_xor_sync(0xffffffffu, q, off);
        }
        if (lane == 0) { srs[wid][co] = s; srq[wid][co] = q; }
    }
    __syncthreads();
    if (tid < 24) {
        double S = 0.0, Q = 0.0;
#pragma unroll
        for (int wk = 0; wk < 8; wk++) { S += srs[wk][tid]; Q += srq[wk][tid]; }
        atomicAdd(&psum[tid], S);
        atomicAdd(&psq[tid], Q);
    }
}

// -------------------- convN: Cin=24, P pixels/thread, BN fused --------------
template <int HIN, int HOUT, int P>
__global__ void __launch_bounds__(256)
conv24_fP(const float* __restrict__ in, const float* __restrict__ w,
          const float* __restrict__ bias,
          const float* __restrict__ statsPrev, const float* __restrict__ betaPrev,
          float* __restrict__ out,
          double* __restrict__ psum, double* __restrict__ psq) {
    __shared__ float ws[5184];
    __shared__ float bs[24];
    __shared__ float ab[24];
    __shared__ float dd[24];
    __shared__ float srs[8][24];
    __shared__ float srq[8][24];
    int tid = threadIdx.x;
    for (int i = tid; i < 5184; i += 256) ws[i] = w[i];
    if (tid < 24) {
        bs[tid] = bias[tid];
        float sc = statsPrev[24 + tid];
        ab[tid] = sc;
        dd[tid] = betaPrev[tid] - statsPrev[tid] * sc;
    }
    __syncthreads();

    const int PIX = HOUT * HOUT;
    const int CHW = HOUT / P;
    int idx = blockIdx.x * 256 + tid;
    int chunk = idx % (PIX / P);
    int b = idx / (PIX / P);
    int oy = chunk / CHW;
    int ox0 = (chunk % CHW) * P;
    int iy0 = 2 * oy - 1;
    int ix0 = 2 * ox0 - 1;

    float acc[24][P];
#pragma unroll
    for (int c = 0; c < 24; c++)
#pragma unroll
        for (int p = 0; p < P; p++) acc[c][p] = bs[c];

    const float* ip = in + (size_t)b * 24 * HIN * HIN;
    for (int ci = 0; ci < 24; ci++) {
        float ai = ab[ci], di = dd[ci];
        const float* ic = ip + ci * HIN * HIN;
#pragma unroll
        for (int ky = 0; ky < 3; ky++) {
            int iy = iy0 + ky;
            bool vy = (unsigned)iy < (unsigned)HIN;
            float iv[2 * P + 1];
#pragma unroll
            for (int j = 0; j < 2 * P + 1; j++) {
                int ix = ix0 + j;
                iv[j] = (vy && (unsigned)ix < (unsigned)HIN)
                            ? fmaf(ic[iy * HIN + ix], ai, di) : 0.f;
            }
#pragma unroll
            for (int kx = 0; kx < 3; kx++) {
                int t = ci * 9 + ky * 3 + kx;
#pragma unroll
                for (int co = 0; co < 24; co++) {
                    float wv = ws[co * 216 + t];
#pragma unroll
                    for (int p = 0; p < P; p++)
                        acc[co][p] = fmaf(iv[2 * p + kx], wv, acc[co][p]);
                }
            }
        }
    }

    int wid = tid >> 5, lane = tid & 31;
    float* op = out + (size_t)b * 24 * PIX + oy * HOUT + ox0;
#pragma unroll
    for (int co = 0; co < 24; co++) {
        float yv[P];
        float s = 0.f, q = 0.f;
#pragma unroll
        for (int p = 0; p < P; p++) {
            float y = fmaxf(acc[co][p], 0.f);
            yv[p] = y;
            s += y; q += y * y;
        }
        if (P == 4) {
            float4 y4 = {yv[0], yv[1], yv[2], yv[3]};
            *(float4*)(op + co * PIX) = y4;
        } else if (P == 2) {
            float2 y2 = {yv[0], yv[1]};
            *(float2*)(op + co * PIX) = y2;
        } else {
#pragma unroll
            for (int p = 0; p < P; p++) op[co * PIX + p] = yv[p];
        }
#pragma unroll
        for (int off = 16; off > 0; off >>= 1) {
            s += __shfl_xor_sync(0xffffffffu, s, off);
            q += __shfl_xor_sync(0xffffffffu, q, off);
        }
        if (lane == 0) { srs[wid][co] = s; srq[wid][co] = q; }
    }
    __syncthreads();
    if (tid < 24) {
        double S = 0.0, Q = 0.0;
#pragma unroll
        for (int wk = 0; wk < 8; wk++) { S += srs[wk][tid]; Q += srq[wk][tid]; }
        atomicAdd(&psum[tid], S);
        atomicAdd(&psq[tid], Q);
    }
}

// -------------------- finalize BN stats -------------------------------------
__global__ void bn_final_f(const double* __restrict__ psum, const double* __restrict__ psq,
                           double N, const float* __restrict__ gamma,
                           float* __restrict__ stats) {
    int c = threadIdx.x;
    if (c >= 24) return;
    double mean = psum[c] / N;
    double var = psq[c] / N - mean * mean;
    stats[c] = (float)mean;
    stats[24 + c] = gamma[c] * rsqrtf((float)var + EPS);
}

// -------------------- object extraction (applies BN4) -----------------------
__global__ void obj_f(const float* __restrict__ x4, const float* __restrict__ stats4,
                      const float* __restrict__ beta4, float* __restrict__ obj) {
    int idx = blockIdx.x * blockDim.x + threadIdx.x;
    const int total = BATCH * OBJ * 26;
    if (idx >= total) return;
    int f = idx % 26; int t = idx / 26;
    int o = t % OBJ; int b = t / OBJ;
    float v;
    if (f < FS) {
        float y = x4[((size_t)b * FS + f) * OBJ + o];
        v = (y - stats4[f]) * stats4[24 + f] + beta4[f];
    } else if (f == FS) v = ((float)(o / 5) - 2.f) * 0.5f;
    else v = ((float)(o % 5) - 2.f) * 0.5f;
    obj[idx] = v;
}

// -------------------- g1 decomposition --------------------------------------
__global__ void ab_k(const float* __restrict__ obj, const float* __restrict__ g1w,
                     float* __restrict__ A, float* __restrict__ B) {
    int m = blockIdx.x;
    int n = threadIdx.x;
    __shared__ float os[26];
    if (n < 26) os[n] = obj[m * 26 + n];
    __syncthreads();
    const float* wr = g1w + n * 63;
    float sa = 0.f, sb = 0.f;
#pragma unroll
    for (int f = 0; f < 26; f++) {
        float o = os[f];
        sa += o * __ldg(&wr[f]);
        sb += o * __ldg(&wr[26 + f]);
    }
    A[m * HID + n] = sa;
    B[m * HID + n] = sb;
}

__global__ void cb_k(const float* __restrict__ qst, const float* __restrict__ g1w,
                     const float* __restrict__ g1b, float* __restrict__ Cb) {
    int b = blockIdx.x;
    int n = threadIdx.x;
    __shared__ float qs[QDIM];
    if (n < QDIM) qs[n] = qst[n * BATCH + b];
    __syncthreads();
    const float* wr = g1w + n * 63 + 52;
    float s = g1b[n];
#pragma unroll
    for (int d = 0; d < QDIM; d++) s += qs[d] * __ldg(&wr[d]);
    Cb[b * HID + n] = s;
}

// ==================== tf32 mma GEMM (generic, g3) ===========================
#define TPAD 20
#define TBUF (128 * TPAD)

__global__ void __launch_bounds__(256, 2)
gmlp_tf32(const float* __restrict__ X, const float* __restrict__ W,
          const float* __restrict__ bias, float* __restrict__ Y, int doRound) {
    __shared__ __align__(16) float As[2][TBUF];
    __shared__ __align__(16) float Bs[2][TBUF];
    __shared__ float biasS[128];

    const int tid = threadIdx.x;
    const int wid = tid >> 5;
    const int lane = tid & 31;
    const int wm = wid >> 2;
    const int wn = wid & 3;
    const int n0 = blockIdx.x * 128;
    const size_t mBase = (size_t)blockIdx.y * 128;

    if (tid < 128) biasS[tid] = __ldg(&bias[n0 + tid]);

    const uint32_t aRaw = smem_u32(As);
    const uint32_t bRaw = smem_u32(Bs);
    const float* Xt = X + mBase * 256;
    const float* Wt = W + (size_t)n0 * 256;

    const int lr = tid >> 1;
    const int lh = tid & 1;

    auto issue = [&](int buf, int k0) {
        uint32_t ad = aRaw + buf * (TBUF * 4) + lr * (TPAD * 4) + lh * 32;
        uint32_t bd = bRaw + buf * (TBUF * 4) + lr * (TPAD * 4) + lh * 32;
        const float* xs = Xt + lr * 256 + k0 + lh * 8;
        const float* wsrc = Wt + lr * 256 + k0 + lh * 8;
        CP_ASYNC16(ad, xs);
        CP_ASYNC16(ad + 16, xs + 4);
        CP_ASYNC16(bd, wsrc);
        CP_ASYNC16(bd + 16, wsrc + 4);
    };

    float acc[4][4][4];
#pragma unroll
    for (int i = 0; i < 4; i++)
#pragma unroll
        for (int j = 0; j < 4; j++)
#pragma unroll
            for (int r = 0; r < 4; r++) acc[i][j][r] = 0.f;

    issue(0, 0);
    CP_COMMIT();

    const int lq = lane >> 2;
    const int lk = lane & 3;

#pragma unroll 1
    for (int kt = 0; kt < 16; kt++) {
        int buf = kt & 1;
        if (kt < 15) { issue(buf ^ 1, (kt + 1) * 16); CP_COMMIT(); CP_WAIT1(); }
        else CP_WAIT0();
        __syncthreads();

#pragma unroll
        for (int ks = 0; ks < 2; ks++) {
            int kk = ks * 8 + lk;
            uint32_t af[4][4];
#pragma unroll
            for (int mf = 0; mf < 4; mf++) {
                const float* ap = &As[buf][(wm * 64 + mf * 16 + lq) * TPAD + kk];
                af[mf][0] = __float_as_uint(ap[0]);
                af[mf][1] = __float_as_uint(ap[8 * TPAD]);
                af[mf][2] = __float_as_uint(ap[4]);
                af[mf][3] = __float_as_uint(ap[8 * TPAD + 4]);
            }
            uint32_t bfr[4][2];
#pragma unroll
            for (int nf = 0; nf < 4; nf++) {
                const float* bp = &Bs[buf][(wn * 32 + nf * 8 + lq) * TPAD + kk];
                bfr[nf][0] = __float_as_uint(bp[0]);
                bfr[nf][1] = __float_as_uint(bp[4]);
            }
#pragma unroll
            for (int mf = 0; mf < 4; mf++)
#pragma unroll
                for (int nf = 0; nf < 4; nf++)
                    mma_tf32(acc[mf][nf], af[mf], bfr[nf]);
        }
        __syncthreads();
    }

#pragma unroll
    for (int mf = 0; mf < 4; mf++) {
        size_t r0 = mBase + wm * 64 + mf * 16 + lq;
        float* y0 = Y + r0 * 256 + n0;
        float* y1 = y0 + 8 * 256;
#pragma unroll
        for (int nf = 0; nf < 4; nf++) {
            int col = wn * 32 + nf * 8 + 2 * lk;
            float b0 = biasS[col], b1 = biasS[col + 1];
            float v0 = fmaxf(acc[mf][nf][0] + b0, 0.f);
            float v1 = fmaxf(acc[mf][nf][1] + b1, 0.f);
            float v2 = fmaxf(acc[mf][nf][2] + b0, 0.f);
            float v3 = fmaxf(acc[mf][nf][3] + b1, 0.f);
            if (doRound) {
                v0 = tf32r(v0); v1 = tf32r(v1);
                v2 = tf32r(v2); v3 = tf32r(v3);
            }
            float2 p0 = {v0, v1};
            float2 p1 = {v2, v3};
            *(float2*)(y0 + col) = p0;
            *(float2*)(y1 + col) = p1;
        }
    }
}

// ==================== g2: fused h1 build + tf32 GEMM, full N=256, 512 thr ===
// Grid (2500). 16 warps: wm = wid>>2 (M 4x32), wn = wid&3 (N 4x64).
// h1 tile built ONCE per M-tile (vs twice in the (2,2500) version).
#define L2PAD 260
#define GL2_SMEM ((128 * L2PAD + 2 * 256 * TPAD + 256) * 4)

__global__ void __launch_bounds__(512, 1)
gmlp_l2(const float* __restrict__ Ag, const float* __restrict__ Bg,
        const float* __restrict__ Cg, const float* __restrict__ W,
        const float* __restrict__ bias, float* __restrict__ Y) {
    extern __shared__ float sm[];
    float* h1s = sm;                       // [128 * L2PAD]
    float* Ws = sm + 128 * L2PAD;          // [2][256 * TPAD]
    float* biasS = Ws + 2 * 256 * TPAD;    // [256]

    const int tid = threadIdx.x;
    const int wid = tid >> 5;
    const int lane = tid & 31;
    const int wm = wid >> 2;               // 0..3
    const int wn = wid & 3;                // 0..3
    const size_t mBase = (size_t)blockIdx.x * 128;

    if (tid < 256) biasS[tid] = __ldg(&bias[tid]);

    // ---- build h1 tile (each thread: one row, 64 cols) ----
    {
        int row = tid >> 2;
        int lc = (tid & 3) * 64;
        int r = (int)mBase + row;
        int b = r / 625;
        int rem = r - b * 625;
        int ko = rem / 25;
        int ii = rem - ko * 25;
        const float4* pA = (const float4*)(Ag + (b * 25 + ii) * 256) + (lc >> 2);
        const float4* pB = (const float4*)(Bg + (b * 25 + ko) * 256) + (lc >> 2);
        const float4* pC = (const float4*)(Cg + b * 256) + (lc >> 2);
        float* hrow = h1s + row * L2PAD + lc;
#pragma unroll 4
        for (int j = 0; j < 16; j++) {
            float4 a = __ldg(pA + j), bb = __ldg(pB + j), c = __ldg(pC + j);
            float4 o;
            o.x = tf32r(fmaxf(a.x + bb.x + c.x, 0.f));
            o.y = tf32r(fmaxf(a.y + bb.y + c.y, 0.f));
            o.z = tf32r(fmaxf(a.z + bb.z + c.z, 0.f));
            o.w = tf32r(fmaxf(a.w + bb.w + c.w, 0.f));
            *(float4*)(hrow + j * 4) = o;
        }
    }

    const uint32_t wRaw = smem_u32(Ws);
    const int lrw = tid >> 1;              // 0..255 (W row)
    const int lh = tid & 1;
    auto issue = [&](int buf, int k0) {
        uint32_t bd = wRaw + buf * (256 * TPAD * 4) + lrw * (TPAD * 4) + lh * 32;
        const float* wsrc = W + lrw * 256 + k0 + lh * 8;
        CP_ASYNC16(bd, wsrc);
        CP_ASYNC16(bd + 16, wsrc + 4);
    };

    float acc[2][8][4];
#pragma unroll
    for (int i = 0; i < 2; i++)
#pragma unroll
        for (int j = 0; j < 8; j++)
#pragma unroll
            for (int r = 0; r < 4; r++) acc[i][j][r] = 0.f;

    issue(0, 0);
    CP_COMMIT();
    __syncthreads();   // h1s visible

    const int lq = lane >> 2;
    const int lk = lane & 3;

#pragma unroll 1
    for (int kt = 0; kt < 16; kt++) {
        int buf = kt & 1;
        if (kt < 15) { issue(buf ^ 1, (kt + 1) * 16); CP_COMMIT(); CP_WAIT1(); }
        else CP_WAIT0();
        __syncthreads();

#pragma unroll
        for (int ks = 0; ks < 2; ks++) {
            int kk = kt * 16 + ks * 8 + lk;
            int kw = ks * 8 + lk;
            uint32_t af[2][4];
#pragma unroll
            for (int mf = 0; mf < 2; mf++) {
                const float* ap = &h1s[(wm * 32 + mf * 16 + lq) * L2PAD + kk];
                af[mf][0] = __float_as_uint(ap[0]);
                af[mf][1] = __float_as_uint(ap[8 * L2PAD]);
                af[mf][2] = __float_as_uint(ap[4]);
                af[mf][3] = __float_as_uint(ap[8 * L2PAD + 4]);
            }
#pragma unroll
            for (int nf = 0; nf < 8; nf++) {
                const float* bp = &Ws[buf * (256 * TPAD) + (wn * 64 + nf * 8 + lq) * TPAD + kw];
                uint32_t bfr[2];
                bfr[0] = __float_as_uint(bp[0]);
                bfr[1] = __float_as_uint(bp[4]);
                mma_tf32(acc[0][nf], af[0], bfr);
                mma_tf32(acc[1][nf], af[1], bfr);
            }
        }
        __syncthreads();
    }

#pragma unroll
    for (int mf = 0; mf < 2; mf++) {
        size_t r0 = mBase + wm * 32 + mf * 16 + lq;
        float* y0 = Y + r0 * 256;
        float* y1 = y0 + 8 * 256;
#pragma unroll
        for (int nf = 0; nf < 8; nf++) {
            int col = wn * 64 + nf * 8 + 2 * lk;
            float b0 = biasS[col], b1 = biasS[col + 1];
            float v0 = tf32r(fmaxf(acc[mf][nf][0] + b0, 0.f));
            float v1 = tf32r(fmaxf(acc[mf][nf][1] + b1, 0.f));
            float v2 = tf32r(fmaxf(acc[mf][nf][2] + b0, 0.f));
            float v3 = tf32r(fmaxf(acc[mf][nf][3] + b1, 0.f));
            float2 p0 = {v0, v1};
            float2 p1 = {v2, v3};
            *(float2*)(y0 + col) = p0;
            *(float2*)(y1 + col) = p1;
        }
    }
}

// ==================== g4: tf32 GEMM + fused pairsum (atomic) ================
__global__ void __launch_bounds__(256, 2)
gmlp_l4(const float* __restrict__ X, const float* __restrict__ W,
        const float* __restrict__ bias, float* __restrict__ xg) {
    __shared__ __align__(16) float As[2][TBUF];
    __shared__ __align__(16) float Bs[2][TBUF];
    __shared__ float biasS[128];

    const int tid = threadIdx.x;
    const int wid = tid >> 5;
    const int lane = tid & 31;
    const int wm = wid >> 2;
    const int wn = wid & 3;
    const int n0 = blockIdx.x * 128;
    const size_t mBase = (size_t)blockIdx.y * 128;

    if (tid < 128) biasS[tid] = __ldg(&bias[n0 + tid]);

    const uint32_t aRaw = smem_u32(As);
    const uint32_t bRaw = smem_u32(Bs);
    const float* Xt = X + mBase * 256;
    const float* Wt = W + (size_t)n0 * 256;

    const int lr = tid >> 1;
    const int lh = tid & 1;

    auto issue = [&](int buf, int k0) {
        uint32_t ad = aRaw + buf * (TBUF * 4) + lr * (TPAD * 4) + lh * 32;
        uint32_t bd = bRaw + buf * (TBUF * 4) + lr * (TPAD * 4) + lh * 32;
        const float* xs = Xt + lr * 256 + k0 + lh * 8;
        const float* wsrc = Wt + lr * 256 + k0 + lh * 8;
        CP_ASYNC16(ad, xs);
        CP_ASYNC16(ad + 16, xs + 4);
        CP_ASYNC16(bd, wsrc);
        CP_ASYNC16(bd + 16, wsrc + 4);
    };

    float acc[4][4][4];
#pragma unroll
    for (int i = 0; i < 4; i++)
#pragma unroll
        for (int j = 0; j < 4; j++)
#pragma unroll
            for (int r = 0; r < 4; r++) acc[i][j][r] = 0.f;

    issue(0, 0);
    CP_COMMIT();

    const int lq = lane >> 2;
    const int lk = lane & 3;

#pragma unroll 1
    for (int kt = 0; kt < 16; kt++) {
        int buf = kt & 1;
        if (kt < 15) { issue(buf ^ 1, (kt + 1) * 16); CP_COMMIT(); CP_WAIT1(); }
        else CP_WAIT0();
        __syncthreads();

#pragma unroll
        for (int ks = 0; ks < 2; ks++) {
            int kk = ks * 8 + lk;
            uint32_t af[4][4];
#pragma unroll
            for (int mf = 0; mf < 4; mf++) {
                const float* ap = &As[buf][(wm * 64 + mf * 16 + lq) * TPAD + kk];
                af[mf][0] = __float_as_uint(ap[0]);
                af[mf][1] = __float_as_uint(ap[8 * TPAD]);
                af[mf][2] = __float_as_uint(ap[4]);
                af[mf][3] = __float_as_uint(ap[8 * TPAD + 4]);
            }
            uint32_t bfr[4][2];
#pragma unroll
            for (int nf = 0; nf < 4; nf++) {
                const float* bp = &Bs[buf][(wn * 32 + nf * 8 + lq) * TPAD + kk];
                bfr[nf][0] = __float_as_uint(bp[0]);
                bfr[nf][1] = __float_as_uint(bp[4]);
            }
#pragma unroll
            for (int mf = 0; mf < 4; mf++)
#pragma unroll
                for (int nf = 0; nf < 4; nf++)
                    mma_tf32(acc[mf][nf], af[mf], bfr[nf]);
        }
        __syncthreads();
    }

    // ---- fused pairsum epilogue ----
    int b0 = (int)(mBase / 625);
    int split = (b0 + 1) * 625;
    bool hasSplit = split < (int)mBase + 128;

    float cs0[4][2], cs1[4][2];
#pragma unroll
    for (int nf = 0; nf < 4; nf++) { cs0[nf][0] = cs0[nf][1] = 0.f; cs1[nf][0] = cs1[nf][1] = 0.f; }

#pragma unroll
    for (int mf = 0; mf < 4; mf++) {
        int rA = (int)mBase + wm * 64 + mf * 16 + lq;
        int rB = rA + 8;
        bool pA = rA >= split;
        bool pB = rB >= split;
#pragma unroll
        for (int nf = 0; nf < 4; nf++) {
            int col = wn * 32 + nf * 8 + 2 * lk;
            float bb0 = biasS[col], bb1 = biasS[col + 1];
            float v0 = fmaxf(acc[mf][nf][0] + bb0, 0.f);
            float v1 = fmaxf(acc[mf][nf][1] + bb1, 0.f);
            float v2 = fmaxf(acc[mf][nf][2] + bb0, 0.f);
            float v3 = fmaxf(acc[mf][nf][3] + bb1, 0.f);
            if (pA) { cs1[nf][0] += v0; cs1[nf][1] += v1; }
            else    { cs0[nf][0] += v0; cs0[nf][1] += v1; }
            if (pB) { cs1[nf][0] += v2; cs1[nf][1] += v3; }
            else    { cs0[nf][0] += v2; cs0[nf][1] += v3; }
        }
    }
#pragma unroll
    for (int off = 4; off <= 16; off <<= 1) {
#pragma unroll
        for (int nf = 0; nf < 4; nf++) {
            cs0[nf][0] += __shfl_xor_sync(0xffffffffu, cs0[nf][0], off);
            cs0[nf][1] += __shfl_xor_sync(0xffffffffu, cs0[nf][1], off);
            cs1[nf][0] += __shfl_xor_sync(0xffffffffu, cs1[nf][0], off);
            cs1[nf][1] += __shfl_xor_sync(0xffffffffu, cs1[nf][1], off);
        }
    }
    if (lq == 0) {
#pragma unroll
        for (int nf = 0; nf < 4; nf++) {
#pragma unroll
            for (int p = 0; p < 2; p++) {
                int col = n0 + wn * 32 + nf * 8 + 2 * lk + p;
                atomicAdd(&xg[b0 * 256 + col], cs0[nf][p]);
                if (hasSplit) atomicAdd(&xg[(b0 + 1) * 256 + col], cs1[nf][p]);
            }
        }
    }
}

// -------------------- fp32 SGEMM (small f-layers) ---------------------------
__global__ void sgemm256(const float* __restrict__ X, const float* __restrict__ W,
                         const float* __restrict__ bias, float* __restrict__ out,
                         int doRelu) {
    __shared__ float Xs[16][128];
    __shared__ float Ws[16][64];
    int bm = blockIdx.y * 128;
    int bn = blockIdx.x * 64;
    int tid = threadIdx.x;
    int tx = tid & 15, ty = tid >> 4;
    float acc[8][4];
#pragma unroll
    for (int i = 0; i < 8; i++)
#pragma unroll
        for (int j = 0; j < 4; j++) acc[i][j] = 0.f;

    int r0 = tid >> 2;
    int c0 = (tid & 3) * 4;
    const float* Xp = X + (size_t)bm * 256;

    for (int k0 = 0; k0 < 256; k0 += 16) {
        float4 x0 = *(const float4*)(Xp + (size_t)r0 * 256 + k0 + c0);
        float4 x1 = *(const float4*)(Xp + (size_t)(r0 + 64) * 256 + k0 + c0);
        float4 wv = *(const float4*)(W + (size_t)(bn + r0) * 256 + k0 + c0);
        Xs[c0 + 0][r0] = x0.x; Xs[c0 + 1][r0] = x0.y; Xs[c0 + 2][r0] = x0.z; Xs[c0 + 3][r0] = x0.w;
        Xs[c0 + 0][r0 + 64] = x1.x; Xs[c0 + 1][r0 + 64] = x1.y; Xs[c0 + 2][r0 + 64] = x1.z; Xs[c0 + 3][r0 + 64] = x1.w;
        Ws[c0 + 0][r0] = wv.x; Ws[c0 + 1][r0] = wv.y; Ws[c0 + 2][r0] = wv.z; Ws[c0 + 3][r0] = wv.w;
        __syncthreads();
#pragma unroll
        for (int k = 0; k < 16; k++) {
            float4 a0 = *(const float4*)&Xs[k][ty * 8];
            float4 a1 = *(const float4*)&Xs[k][ty * 8 + 4];
            float4 b = *(const float4*)&Ws[k][tx * 4];
            acc[0][0] += a0.x * b.x; acc[0][1] += a0.x * b.y; acc[0][2] += a0.x * b.z; acc[0][3] += a0.x * b.w;
            acc[1][0] += a0.y * b.x; acc[1][1] += a0.y * b.y; acc[1][2] += a0.y * b.z; acc[1][3] += a0.y * b.w;
            acc[2][0] += a0.z * b.x; acc[2][1] += a0.z * b.y; acc[2][2] += a0.z * b.z; acc[2][3] += a0.z * b.w;
            acc[3][0] += a0.w * b.x; acc[3][1] += a0.w * b.y; acc[3][2] += a0.w * b.z; acc[3][3] += a0.w * b.w;
            acc[4][0] += a1.x * b.x; acc[4][1] += a1.x * b.y; acc[4][2] += a1.x * b.z; acc[4][3] += a1.x * b.w;
            acc[5][0] += a1.y * b.x; acc[5][1] += a1.y * b.y; acc[5][2] += a1.y * b.z; acc[5][3] += a1.y * b.w;
            acc[6][0] += a1.z * b.x; acc[6][1] += a1.z * b.y; acc[6][2] += a1.z * b.z; acc[6][3] += a1.z * b.w;
            acc[7][0] += a1.w * b.x; acc[7][1] += a1.w * b.y; acc[7][2] += a1.w * b.z; acc[7][3] += a1.w * b.w;
        }
        __syncthreads();
    }
    float4 bv = *(const float4*)&bias[bn + tx * 4];
#pragma unroll
    for (int i = 0; i < 8; i++) {
        int m = bm + ty * 8 + i;
        float4 v;
        v.x = acc[i][0] + bv.x; v.y = acc[i][1] + bv.y;
        v.z = acc[i][2] + bv.z; v.w = acc[i][3] + bv.w;
        if (doRelu) {
            v.x = fmaxf(v.x, 0.f); v.y = fmaxf(v.y, 0.f);
            v.z = fmaxf(v.z, 0.f); v.w = fmaxf(v.w, 0.f);
        }
        *(float4*)(out + (size_t)m * 256 + bn + tx * 4) = v;
    }
}

// -------------------- fc3 + log_softmax -------------------------------------
__global__ void fc3_k(const float* __restrict__ x, const float* __restrict__ w,
                      const float* __restrict__ bias, float* __restrict__ out) {
    int b = blockIdx.x;
    int tid = threadIdx.x; // 320
    int j = tid >> 5, lane = tid & 31;
    __shared__ float lg[10];
    __shared__ float lse;
    const float* xr = x + b * HID;
    const float* wr = w + j * HID;
    float s = 0.f;
    for (int k = lane; k < HID; k += 32) s += xr[k] * wr[k];
#pragma unroll
    for (int o = 16; o > 0; o >>= 1) s += __shfl_xor_sync(0xffffffffu, s, o);
    if (lane == 0) lg[j] = s + bias[j];
    __syncthreads();
    if (tid == 0) {
        float m = lg[0];
#pragma unroll
        for (int t = 1; t < 10; t++) m = fmaxf(m, lg[t]);
        float se = 0.f;
#pragma unroll
        for (int t = 0; t < 10; t++) se += expf(lg[t] - m);
        lse = m + logf(se);
    }
    __syncthreads();
    if (tid < 10) out[b * 10 + tid] = lg[tid] - lse;
}

// ---------------------------------------------------------------------------
extern "C" void kernel_launch(void* const* d_in, const int* in_sizes, int n_in,
                              void* d_out, int out_size) {
    const float* img = (const float*)d_in[0];
    const float* qst = (const float*)d_in[1];
    const float* cw[4] = {(const float*)d_in[2], (const float*)d_in[6], (const float*)d_in[10], (const float*)d_in[14]};
    const float* cb[4] = {(const float*)d_in[3], (const float*)d_in[7], (const float*)d_in[11], (const float*)d_in[15]};
    const float* bg[4] = {(const float*)d_in[4], (const float*)d_in[8], (const float*)d_in[12], (const float*)d_in[16]};
    const float* bb[4] = {(const float*)d_in[5], (const float*)d_in[9], (const float*)d_in[13], (const float*)d_in[17]};
    const float* g1w = (const float*)d_in[18]; const float* g1b = (const float*)d_in[19];
    const float* g2w = (const float*)d_in[20]; const float* g2b = (const float*)d_in[21];
    const float* g3w = (const float*)d_in[22]; const float* g3b = (const float*)d_in[23];
    const float* g4w = (const float*)d_in[24]; const float* g4b = (const float*)d_in[25];
    const float* f1w = (const float*)d_in[26]; const float* f1b = (const float*)d_in[27];
    const float* fc2w = (const float*)d_in[28]; const float* fc2b = (const float*)d_in[29];
    const float* fc3w = (const float*)d_in[30]; const float* fc3b = (const float*)d_in[31];
    float* out = (float*)d_out;

    float *buf1, *buf2, *buf3, *buf4, *obj, *A, *B, *Cb, *xg, *xf1, *xf2, *stats, *wt;
    float *hA, *hB;
    double *psum, *psq;
    cudaGetSymbolAddress((void**)&buf1, g_buf1);
    cudaGetSymbolAddress((void**)&buf2, g_buf2);
    cudaGetSymbolAddress((void**)&buf3, g_buf3);
    cudaGetSymbolAddress((void**)&buf4, g_buf4);
    cudaGetSymbolAddress((void**)&obj, g_obj);
    cudaGetSymbolAddress((void**)&A, g_A);
    cudaGetSymbolAddress((void**)&B, g_B);
    cudaGetSymbolAddress((void**)&Cb, g_Cb);
    cudaGetSymbolAddress((void**)&xg, g_xg);
    cudaGetSymbolAddress((void**)&xf1, g_xf1);
    cudaGetSymbolAddress((void**)&xf2, g_xf2);
    cudaGetSymbolAddress((void**)&stats, g_stats);
    cudaGetSymbolAddress((void**)&psum, g_psum);
    cudaGetSymbolAddress((void**)&psq, g_psq);
    cudaGetSymbolAddress((void**)&wt, g_wt);
    cudaGetSymbolAddress((void**)&hA, g_hbufA);
    cudaGetSymbolAddress((void**)&hB, g_hbufB);

    cudaFuncSetAttribute(gmlp_l2, cudaFuncAttributeMaxDynamicSharedMemorySize, GL2_SMEM);

    // ---- zero accumulators + weight prep ----
    zerod_k<<<1, 128>>>(psum, 96);
    zerod_k<<<1, 128>>>(psq, 96);
    zerof_k<<<512, 256>>>(xg, BATCH * HID);
    wtf32_all<<<768, 256>>>(g2w, g3w, g4w, wt);

    // ---- conv stack (fused BN, pixel-blocked) ----
    conv1_f4<<<800, 256>>>(img, cw[0], cb[0], buf1, psum, psq);
    bn_final_f<<<1, 32>>>(psum, psq, 512.0 * 1600.0, bg[0], stats);
    conv24_fP<40, 20, 4><<<200, 256>>>(buf1, cw[1], cb[1], stats, bb[0], buf2, psum + 24, psq + 24);
    bn_final_f<<<1, 32>>>(psum + 24, psq + 24, 512.0 * 400.0, bg[1], stats + 48);
    conv24_fP<20, 10, 2><<<100, 256>>>(buf2, cw[2], cb[2], stats + 48, bb[1], buf3, psum + 48, psq + 48);
    bn_final_f<<<1, 32>>>(psum + 48, psq + 48, 512.0 * 100.0, bg[2], stats + 96);
    conv24_fP<10, 5, 1><<<50, 256>>>(buf3, cw[3], cb[3], stats + 96, bb[2], buf4, psum + 72, psq + 72);
    bn_final_f<<<1, 32>>>(psum + 72, psq + 72, 512.0 * 25.0, bg[3], stats + 144);

    // ---- objects + decomposed g1 ----
    obj_f<<<(BATCH * OBJ * 26 + 255) / 256, 256>>>(buf4, stats + 144, bb[3], obj);
    ab_k<<<BATCH * OBJ, 256>>>(obj, g1w, A, B);
    cb_k<<<BATCH, 256>>>(qst, g1w, g1b, Cb);

    // ---- g2 (fused h1, full-N) -> g3 -> g4 (fused pairsum) ----
    dim3 ggrid(2, BATCH * OBJ * OBJ / 128);  // (2, 2500)
    gmlp_l2<<<BATCH * OBJ * OBJ / 128, 512, GL2_SMEM>>>(A, B, Cb, wt, g2b, hB);
    gmlp_tf32<<<ggrid, 256>>>(hB, wt + HID * HID, g3b, hA, 1);
    gmlp_l4<<<ggrid, 256>>>(hA, wt + 2 * HID * HID, g4b, xg);

    // ---- f-MLP (fp32) ----
    dim3 fgrid(256 / 64, BATCH / 128);
    sgemm256<<<fgrid, 256>>>(xg, f1w, f1b, xf1, 1);
    sgemm256<<<fgrid, 256>>>(xf1, fc2w, fc2b, xf2, 1);
    fc3_k<<<BATCH, 320>>>(xf2, fc3w, fc3b, out);
}

// round 13
// speedup vs baseline: 1.2095x; 1.0566x over previous
#include <cuda_runtime.h>
#include <cuda_bf16.h>
#include <math.h>
#include <stdint.h>

#define BATCH 512
#define FS 24
#define QDIM 11
#define HID 256
#define OBJ 25
#define EPS 1e-5f

// -------------------- scratch (device globals; no allocation) --------------
__device__ __align__(16) float g_buf1[BATCH * FS * 40 * 40];
__device__ __align__(16) float g_buf2[BATCH * FS * 20 * 20];
__device__ __align__(16) float g_buf3[BATCH * FS * 10 * 10];
__device__ __align__(16) float g_buf4[BATCH * FS * 5 * 5];
__device__ float g_obj[BATCH * OBJ * 26];
__device__ __align__(16) float g_A[BATCH * OBJ * HID];
__device__ __align__(16) float g_B[BATCH * OBJ * HID];
__device__ __align__(16) float g_Cb[BATCH * HID];
__device__ __align__(16) float g_wt[3][HID * HID];   // tf32-rounded weights
__device__ float g_xg[BATCH * HID];
__device__ float g_xf1[BATCH * HID];
__device__ float g_xf2[BATCH * HID];
__device__ double g_psum[4 * 24];
__device__ double g_psq[4 * 24];
__device__ float g_stats[4 * 48];
// intermediate activations in bf16 (g2 out / g3 out), 164 MB each
__device__ __align__(16) __nv_bfloat16 g_hbufA[BATCH * OBJ * OBJ * HID];
__device__ __align__(16) __nv_bfloat16 g_hbufB[BATCH * OBJ * OBJ * HID];

// ===================== helpers ==============================================
__device__ __forceinline__ uint32_t smem_u32(const void* p) {
    uint32_t a;
    asm("{ .reg .u64 tmp; cvta.to.shared.u64 tmp, %1; cvt.u32.u64 %0, tmp; }"
        : "=r"(a) : "l"(p));
    return a;
}

#define CP_ASYNC16(dst, src) \
    asm volatile("cp.async.cg.shared.global [%0], [%1], 16;" :: "r"(dst), "l"(src))
#define CP_COMMIT() asm volatile("cp.async.commit_group;")
#define CP_WAIT1() asm volatile("cp.async.wait_group 1;")
#define CP_WAIT0() asm volatile("cp.async.wait_group 0;")

__device__ __forceinline__ float tf32r(float x) {
    uint32_t u;
    asm("cvt.rna.tf32.f32 %0, %1;" : "=r"(u) : "f"(x));
    return __uint_as_float(u);
}

__device__ __forceinline__ void mma_tf32(float* d, const uint32_t* a, const uint32_t* b) {
    asm volatile(
        "mma.sync.aligned.m16n8k8.row.col.f32.tf32.tf32.f32 "
        "{%0,%1,%2,%3}, {%4,%5,%6,%7}, {%8,%9}, {%0,%1,%2,%3};"
        : "+f"(d[0]), "+f"(d[1]), "+f"(d[2]), "+f"(d[3])
        : "r"(a[0]), "r"(a[1]), "r"(a[2]), "r"(a[3]), "r"(b[0]), "r"(b[1]));
}

// bf16 (top half of fp32) -> fp32 bits
__device__ __forceinline__ uint32_t bf2f(const __nv_bfloat16* p) {
    return ((uint32_t)(*(const unsigned short*)p)) << 16;
}

// -------------------- zero / prep kernels -----------------------------------
__global__ void zerof_k(float* p, int n) {
    int i = blockIdx.x * blockDim.x + threadIdx.x;
    if (i < n) p[i] = 0.f;
}
__global__ void zerod_k(double* p, int n) {
    int i = blockIdx.x * blockDim.x + threadIdx.x;
    if (i < n) p[i] = 0.0;
}
__global__ void wtf32_all(const float* __restrict__ w2, const float* __restrict__ w3,
                          const float* __restrict__ w4, float* __restrict__ o) {
    int idx = blockIdx.x * blockDim.x + threadIdx.x;
    if (idx >= 3 * HID * HID) return;
    int sel = idx >> 16;
    int off = idx & 0xFFFF;
    const float* src = (sel == 0) ? w2 : (sel == 1) ? w3 : w4;
    o[idx] = tf32r(src[off]);
}

// -------------------- conv1: Cin=3, 80->40, P=4 pixels/thread ---------------
__global__ void __launch_bounds__(256)
conv1_f4(const float* __restrict__ in, const float* __restrict__ w,
         const float* __restrict__ bias, float* __restrict__ out,
         double* __restrict__ psum, double* __restrict__ psq) {
    __shared__ float ws[648];
    __shared__ float bs[24];
    __shared__ float srs[8][24];
    __shared__ float srq[8][24];
    int tid = threadIdx.x;
    for (int i = tid; i < 648; i += 256) ws[i] = w[i];
    if (tid < 24) bs[tid] = bias[tid];
    __syncthreads();

    int idx = blockIdx.x * 256 + tid;
    int chunk = idx % 400;
    int b = idx / 400;
    int oy = chunk / 10;
    int ox0 = (chunk % 10) * 4;
    int iy0 = 2 * oy - 1;
    int ix0 = 2 * ox0 - 1;

    float acc[24][4];
#pragma unroll
    for (int c = 0; c < 24; c++)
#pragma unroll
        for (int p = 0; p < 4; p++) acc[c][p] = bs[c];

    const float* ip = in + (size_t)b * 3 * 6400;
#pragma unroll
    for (int ci = 0; ci < 3; ci++) {
        const float* ic = ip + ci * 6400;
#pragma unroll
        for (int ky = 0; ky < 3; ky++) {
            int iy = iy0 + ky;
            bool vy = (unsigned)iy < 80u;
            float iv[9];
#pragma unroll
            for (int j = 0; j < 9; j++) {
                int ix = ix0 + j;
                iv[j] = (vy && (unsigned)ix < 80u) ? ic[iy * 80 + ix] : 0.f;
            }
#pragma unroll
            for (int kx = 0; kx < 3; kx++) {
                int t = ci * 9 + ky * 3 + kx;
#pragma unroll
                for (int co = 0; co < 24; co++) {
                    float wv = ws[co * 27 + t];
#pragma unroll
                    for (int p = 0; p < 4; p++)
                        acc[co][p] = fmaf(iv[2 * p + kx], wv, acc[co][p]);
                }
            }
        }
    }

    int wid = tid >> 5, lane = tid & 31;
    float* op = out + (size_t)b * 24 * 1600 + oy * 40 + ox0;
#pragma unroll
    for (int co = 0; co < 24; co++) {
        float4 y4;
        float* yp = (float*)&y4;
        float s = 0.f, q = 0.f;
#pragma unroll
        for (int p = 0; p < 4; p++) {
            float y = fmaxf(acc[co][p], 0.f);
            yp[p] = y;
            s += y; q += y * y;
        }
        *(float4*)(op + co * 1600) = y4;
#pragma unroll
        for (int off = 16; off > 0; off >>= 1) {
            s += __shfl_xor_sync(0xffffffffu, s, off);
            q += __shfl_xor_sync(0xffffffffu, q, off);
        }
        if (lane == 0) { srs[wid][co] = s; srq[wid][co] = q; }
    }
    __syncthreads();
    if (tid < 24) {
        double S = 0.0, Q = 0.0;
#pragma unroll
        for (int wk = 0; wk < 8; wk++) { S += srs[wk][tid]; Q += srq[wk][tid]; }
        atomicAdd(&psum[tid], S);
        atomicAdd(&psq[tid], Q);
    }
}

// -------------------- convN: Cin=24, P pixels/thread, BN fused --------------
template <int HIN, int HOUT, int P>
__global__ void __launch_bounds__(256)
conv24_fP(const float* __restrict__ in, const float* __restrict__ w,
          const float* __restrict__ bias,
          const float* __restrict__ statsPrev, const float* __restrict__ betaPrev,
          float* __restrict__ out,
          double* __restrict__ psum, double* __restrict__ psq) {
    __shared__ float ws[5184];
    __shared__ float bs[24];
    __shared__ float ab[24];
    __shared__ float dd[24];
    __shared__ float srs[8][24];
    __shared__ float srq[8][24];
    int tid = threadIdx.x;
    for (int i = tid; i < 5184; i += 256) ws[i] = w[i];
    if (tid < 24) {
        bs[tid] = bias[tid];
        float sc = statsPrev[24 + tid];
        ab[tid] = sc;
        dd[tid] = betaPrev[tid] - statsPrev[tid] * sc;
    }
    __syncthreads();

    const int PIX = HOUT * HOUT;
    const int CHW = HOUT / P;
    int idx = blockIdx.x * 256 + tid;
    int chunk = idx % (PIX / P);
    int b = idx / (PIX / P);
    int oy = chunk / CHW;
    int ox0 = (chunk % CHW) * P;
    int iy0 = 2 * oy - 1;
    int ix0 = 2 * ox0 - 1;

    float acc[24][P];
#pragma unroll
    for (int c = 0; c < 24; c++)
#pragma unroll
        for (int p = 0; p < P; p++) acc[c][p] = bs[c];

    const float* ip = in + (size_t)b * 24 * HIN * HIN;
    for (int ci = 0; ci < 24; ci++) {
        float ai = ab[ci], di = dd[ci];
        const float* ic = ip + ci * HIN * HIN;
#pragma unroll
        for (int ky = 0; ky < 3; ky++) {
            int iy = iy0 + ky;
            bool vy = (unsigned)iy < (unsigned)HIN;
            float iv[2 * P + 1];
#pragma unroll
            for (int j = 0; j < 2 * P + 1; j++) {
                int ix = ix0 + j;
                iv[j] = (vy && (unsigned)ix < (unsigned)HIN)
                            ? fmaf(ic[iy * HIN + ix], ai, di) : 0.f;
            }
#pragma unroll
            for (int kx = 0; kx < 3; kx++) {
                int t = ci * 9 + ky * 3 + kx;
#pragma unroll
                for (int co = 0; co < 24; co++) {
                    float wv = ws[co * 216 + t];
#pragma unroll
                    for (int p = 0; p < P; p++)
                        acc[co][p] = fmaf(iv[2 * p + kx], wv, acc[co][p]);
                }
            }
        }
    }

    int wid = tid >> 5, lane = tid & 31;
    float* op = out + (size_t)b * 24 * PIX + oy * HOUT + ox0;
#pragma unroll
    for (int co = 0; co < 24; co++) {
        float yv[P];
        float s = 0.f, q = 0.f;
#pragma unroll
        for (int p = 0; p < P; p++) {
            float y = fmaxf(acc[co][p], 0.f);
            yv[p] = y;
            s += y; q += y * y;
        }
        if (P == 4) {
            float4 y4 = {yv[0], yv[1], yv[2], yv[3]};
            *(float4*)(op + co * PIX) = y4;
        } else if (P == 2) {
            float2 y2 = {yv[0], yv[1]};
            *(float2*)(op + co * PIX) = y2;
        } else {
#pragma unroll
            for (int p = 0; p < P; p++) op[co * PIX + p] = yv[p];
        }
#pragma unroll
        for (int off = 16; off > 0; off >>= 1) {
            s += __shfl_xor_sync(0xffffffffu, s, off);
            q += __shfl_xor_sync(0xffffffffu, q, off);
        }
        if (lane == 0) { srs[wid][co] = s; srq[wid][co] = q; }
    }
    __syncthreads();
    if (tid < 24) {
        double S = 0.0, Q = 0.0;
#pragma unroll
        for (int wk = 0; wk < 8; wk++) { S += srs[wk][tid]; Q += srq[wk][tid]; }
        atomicAdd(&psum[tid], S);
        atomicAdd(&psq[tid], Q);
    }
}

// -------------------- finalize BN stats -------------------------------------
__global__ void bn_final_f(const double* __restrict__ psum, const double* __restrict__ psq,
                           double N, const float* __restrict__ gamma,
                           float* __restrict__ stats) {
    int c = threadIdx.x;
    if (c >= 24) return;
    double mean = psum[c] / N;
    double var = psq[c] / N - mean * mean;
    stats[c] = (float)mean;
    stats[24 + c] = gamma[c] * rsqrtf((float)var + EPS);
}

// -------------------- object extraction (applies BN4) -----------------------
__global__ void obj_f(const float* __restrict__ x4, const float* __restrict__ stats4,
                      const float* __restrict__ beta4, float* __restrict__ obj) {
    int idx = blockIdx.x * blockDim.x + threadIdx.x;
    const int total = BATCH * OBJ * 26;
    if (idx >= total) return;
    int f = idx % 26; int t = idx / 26;
    int o = t % OBJ; int b = t / OBJ;
    float v;
    if (f < FS) {
        float y = x4[((size_t)b * FS + f) * OBJ + o];
        v = (y - stats4[f]) * stats4[24 + f] + beta4[f];
    } else if (f == FS) v = ((float)(o / 5) - 2.f) * 0.5f;
    else v = ((float)(o % 5) - 2.f) * 0.5f;
    obj[idx] = v;
}

// -------------------- g1 decomposition --------------------------------------
__global__ void ab_k(const float* __restrict__ obj, const float* __restrict__ g1w,
                     float* __restrict__ A, float* __restrict__ B) {
    int m = blockIdx.x;
    int n = threadIdx.x;
    __shared__ float os[26];
    if (n < 26) os[n] = obj[m * 26 + n];
    __syncthreads();
    const float* wr = g1w + n * 63;
    float sa = 0.f, sb = 0.f;
#pragma unroll
    for (int f = 0; f < 26; f++) {
        float o = os[f];
        sa += o * __ldg(&wr[f]);
        sb += o * __ldg(&wr[26 + f]);
    }
    A[m * HID + n] = sa;
    B[m * HID + n] = sb;
}

__global__ void cb_k(const float* __restrict__ qst, const float* __restrict__ g1w,
                     const float* __restrict__ g1b, float* __restrict__ Cb) {
    int b = blockIdx.x;
    int n = threadIdx.x;
    __shared__ float qs[QDIM];
    if (n < QDIM) qs[n] = qst[n * BATCH + b];
    __syncthreads();
    const float* wr = g1w + n * 63 + 52;
    float s = g1b[n];
#pragma unroll
    for (int d = 0; d < QDIM; d++) s += qs[d] * __ldg(&wr[d]);
    Cb[b * HID + n] = s;
}

// ==================== g2: fused h1 build + tf32 GEMM, bf16 out ==============
#define TPAD 20
#define TBUF (128 * TPAD)
#define L2PAD 260
#define GL2_SMEM ((128 * L2PAD + 2 * 128 * TPAD + 128) * 4)

__global__ void __launch_bounds__(256, 1)
gmlp_l2(const float* __restrict__ Ag, const float* __restrict__ Bg,
        const float* __restrict__ Cg, const float* __restrict__ W,
        const float* __restrict__ bias, __nv_bfloat16* __restrict__ Y) {
    extern __shared__ float sm[];
    float* h1s = sm;
    float* Ws = sm + 128 * L2PAD;
    float* biasS = Ws + 2 * 128 * TPAD;

    const int tid = threadIdx.x;
    const int wid = tid >> 5;
    const int lane = tid & 31;
    const int wm = wid >> 2;
    const int wn = wid & 3;
    const int n0 = blockIdx.x * 128;
    const size_t mBase = (size_t)blockIdx.y * 128;

    if (tid < 128) biasS[tid] = __ldg(&bias[n0 + tid]);

    const int lr = tid >> 1;
    const int lh = tid & 1;
    {
        int r = (int)mBase + lr;
        int b = r / 625;
        int rem = r - b * 625;
        int ko = rem / 25;
        int ii = rem - ko * 25;
        const float4* pA = (const float4*)(Ag + (b * 25 + ii) * 256);
        const float4* pB = (const float4*)(Bg + (b * 25 + ko) * 256);
        const float4* pC = (const float4*)(Cg + b * 256);
#pragma unroll 4
        for (int j = 0; j < 16; j++) {
            int col = lh * 8 + j * 16;
            int c4 = col >> 2;
            float4 a0 = __ldg(pA + c4), a1 = __ldg(pA + c4 + 1);
            float4 b0 = __ldg(pB + c4), b1 = __ldg(pB + c4 + 1);
            float4 c0 = __ldg(pC + c4), c1 = __ldg(pC + c4 + 1);
            float4 o0, o1;
            o0.x = tf32r(fmaxf(a0.x + b0.x + c0.x, 0.f));
            o0.y = tf32r(fmaxf(a0.y + b0.y + c0.y, 0.f));
            o0.z = tf32r(fmaxf(a0.z + b0.z + c0.z, 0.f));
            o0.w = tf32r(fmaxf(a0.w + b0.w + c0.w, 0.f));
            o1.x = tf32r(fmaxf(a1.x + b1.x + c1.x, 0.f));
            o1.y = tf32r(fmaxf(a1.y + b1.y + c1.y, 0.f));
            o1.z = tf32r(fmaxf(a1.z + b1.z + c1.z, 0.f));
            o1.w = tf32r(fmaxf(a1.w + b1.w + c1.w, 0.f));
            *(float4*)&h1s[lr * L2PAD + col] = o0;
            *(float4*)&h1s[lr * L2PAD + col + 4] = o1;
        }
    }

    const float* Wt = W + (size_t)n0 * 256;
    const uint32_t wRaw = smem_u32(Ws);
    auto issue = [&](int buf, int k0) {
        uint32_t bd = wRaw + buf * (128 * TPAD * 4) + lr * (TPAD * 4) + lh * 32;
        const float* wsrc = Wt + lr * 256 + k0 + lh * 8;
        CP_ASYNC16(bd, wsrc);
        CP_ASYNC16(bd + 16, wsrc + 4);
    };

    float acc[4][4][4];
#pragma unroll
    for (int i = 0; i < 4; i++)
#pragma unroll
        for (int j = 0; j < 4; j++)
#pragma unroll
            for (int r = 0; r < 4; r++) acc[i][j][r] = 0.f;

    issue(0, 0);
    CP_COMMIT();
    __syncthreads();

    const int lq = lane >> 2;
    const int lk = lane & 3;

#pragma unroll 1
    for (int kt = 0; kt < 16; kt++) {
        int buf = kt & 1;
        if (kt < 15) { issue(buf ^ 1, (kt + 1) * 16); CP_COMMIT(); CP_WAIT1(); }
        else CP_WAIT0();
        __syncthreads();

#pragma unroll
        for (int ks = 0; ks < 2; ks++) {
            int kk = kt * 16 + ks * 8 + lk;
            uint32_t af[4][4];
#pragma unroll
            for (int mf = 0; mf < 4; mf++) {
                const float* ap = &h1s[(wm * 64 + mf * 16 + lq) * L2PAD + kk];
                af[mf][0] = __float_as_uint(ap[0]);
                af[mf][1] = __float_as_uint(ap[8 * L2PAD]);
                af[mf][2] = __float_as_uint(ap[4]);
                af[mf][3] = __float_as_uint(ap[8 * L2PAD + 4]);
            }
            int kw = ks * 8 + lk;
            uint32_t bfr[4][2];
#pragma unroll
            for (int nf = 0; nf < 4; nf++) {
                const float* bp = &Ws[buf * 128 * TPAD + (wn * 32 + nf * 8 + lq) * TPAD + kw];
                bfr[nf][0] = __float_as_uint(bp[0]);
                bfr[nf][1] = __float_as_uint(bp[4]);
            }
#pragma unroll
            for (int mf = 0; mf < 4; mf++)
#pragma unroll
                for (int nf = 0; nf < 4; nf++)
                    mma_tf32(acc[mf][nf], af[mf], bfr[nf]);
        }
        __syncthreads();
    }

#pragma unroll
    for (int mf = 0; mf < 4; mf++) {
        size_t r0 = mBase + wm * 64 + mf * 16 + lq;
        __nv_bfloat16* y0 = Y + r0 * 256 + n0;
        __nv_bfloat16* y1 = y0 + 8 * 256;
#pragma unroll
        for (int nf = 0; nf < 4; nf++) {
            int col = wn * 32 + nf * 8 + 2 * lk;
            float b0 = biasS[col], b1 = biasS[col + 1];
            float v0 = fmaxf(acc[mf][nf][0] + b0, 0.f);
            float v1 = fmaxf(acc[mf][nf][1] + b1, 0.f);
            float v2 = fmaxf(acc[mf][nf][2] + b0, 0.f);
            float v3 = fmaxf(acc[mf][nf][3] + b1, 0.f);
            __nv_bfloat162 p0 = __floats2bfloat162_rn(v0, v1);
            __nv_bfloat162 p1 = __floats2bfloat162_rn(v2, v3);
            *(uint32_t*)(y0 + col) = *(uint32_t*)&p0;
            *(uint32_t*)(y1 + col) = *(uint32_t*)&p1;
        }
    }
}

// ==================== g3: bf16-in tf32 GEMM, bf16-out =======================
#define APADH 24                           // bf16 row pad (48B, 16B-aligned)
#define ABUFH (128 * APADH)                // bf16 elems per A buffer

__global__ void __launch_bounds__(256, 2)
gmlp_l3(const __nv_bfloat16* __restrict__ X, const float* __restrict__ W,
        const float* __restrict__ bias, __nv_bfloat16* __restrict__ Y) {
    __shared__ __align__(16) __nv_bfloat16 As[2][ABUFH];
    __shared__ __align__(16) float Bs[2][TBUF];
    __shared__ float biasS[128];

    const int tid = threadIdx.x;
    const int wid = tid >> 5;
    const int lane = tid & 31;
    const int wm = wid >> 2;
    const int wn = wid & 3;
    const int n0 = blockIdx.x * 128;
    const size_t mBase = (size_t)blockIdx.y * 128;

    if (tid < 128) biasS[tid] = __ldg(&bias[n0 + tid]);

    const uint32_t aRaw = smem_u32(As);
    const uint32_t bRaw = smem_u32(Bs);
    const __nv_bfloat16* Xt = X + mBase * 256;
    const float* Wt = W + (size_t)n0 * 256;

    const int lr = tid >> 1;
    const int lh = tid & 1;

    auto issue = [&](int buf, int k0) {
        uint32_t ad = aRaw + buf * (ABUFH * 2) + lr * (APADH * 2) + lh * 16;
        uint32_t bd = bRaw + buf * (TBUF * 4) + lr * (TPAD * 4) + lh * 32;
        const __nv_bfloat16* xs = Xt + lr * 256 + k0 + lh * 8;
        const float* wsrc = Wt + lr * 256 + k0 + lh * 8;
        CP_ASYNC16(ad, xs);
        CP_ASYNC16(bd, wsrc);
        CP_ASYNC16(bd + 16, wsrc + 4);
    };

    float acc[4][4][4];
#pragma unroll
    for (int i = 0; i < 4; i++)
#pragma unroll
        for (int j = 0; j < 4; j++)
#pragma unroll
            for (int r = 0; r < 4; r++) acc[i][j][r] = 0.f;

    issue(0, 0);
    CP_COMMIT();

    const int lq = lane >> 2;
    const int lk = lane & 3;

#pragma unroll 1
    for (int kt = 0; kt < 16; kt++) {
        int buf = kt & 1;
        if (kt < 15) { issue(buf ^ 1, (kt + 1) * 16); CP_COMMIT(); CP_WAIT1(); }
        else CP_WAIT0();
        __syncthreads();

#pragma unroll
        for (int ks = 0; ks < 2; ks++) {
            int kk = ks * 8 + lk;
            uint32_t af[4][4];
#pragma unroll
            for (int mf = 0; mf < 4; mf++) {
                const __nv_bfloat16* ap = &As[buf][(wm * 64 + mf * 16 + lq) * APADH + kk];
                af[mf][0] = bf2f(ap);
                af[mf][1] = bf2f(ap + 8 * APADH);
                af[mf][2] = bf2f(ap + 4);
                af[mf][3] = bf2f(ap + 8 * APADH + 4);
            }
            uint32_t bfr[4][2];
#pragma unroll
            for (int nf = 0; nf < 4; nf++) {
                const float* bp = &Bs[buf][(wn * 32 + nf * 8 + lq) * TPAD + kk];
                bfr[nf][0] = __float_as_uint(bp[0]);
                bfr[nf][1] = __float_as_uint(bp[4]);
            }
#pragma unroll
            for (int mf = 0; mf < 4; mf++)
#pragma unroll
                for (int nf = 0; nf < 4; nf++)
                    mma_tf32(acc[mf][nf], af[mf], bfr[nf]);
        }
        __syncthreads();
    }

#pragma unroll
    for (int mf = 0; mf < 4; mf++) {
        size_t r0 = mBase + wm * 64 + mf * 16 + lq;
        __nv_bfloat16* y0 = Y + r0 * 256 + n0;
        __nv_bfloat16* y1 = y0 + 8 * 256;
#pragma unroll
        for (int nf = 0; nf < 4; nf++) {
            int col = wn * 32 + nf * 8 + 2 * lk;
            float b0 = biasS[col], b1 = biasS[col + 1];
            float v0 = fmaxf(acc[mf][nf][0] + b0, 0.f);
            float v1 = fmaxf(acc[mf][nf][1] + b1, 0.f);
            float v2 = fmaxf(acc[mf][nf][2] + b0, 0.f);
            float v3 = fmaxf(acc[mf][nf][3] + b1, 0.f);
            __nv_bfloat162 p0 = __floats2bfloat162_rn(v0, v1);
            __nv_bfloat162 p1 = __floats2bfloat162_rn(v2, v3);
            *(uint32_t*)(y0 + col) = *(uint32_t*)&p0;
            *(uint32_t*)(y1 + col) = *(uint32_t*)&p1;
        }
    }
}

// ==================== g4: bf16-in tf32 GEMM + fused pairsum =================
__global__ void __launch_bounds__(256, 2)
gmlp_l4(const __nv_bfloat16* __restrict__ X, const float* __restrict__ W,
        const float* __restrict__ bias, float* __restrict__ xg) {
    __shared__ __align__(16) __nv_bfloat16 As[2][ABUFH];
    __shared__ __align__(16) float Bs[2][TBUF];
    __shared__ float biasS[128];

    const int tid = threadIdx.x;
    const int wid = tid >> 5;
    const int lane = tid & 31;
    const int wm = wid >> 2;
    const int wn = wid & 3;
    const int n0 = blockIdx.x * 128;
    const size_t mBase = (size_t)blockIdx.y * 128;

    if (tid < 128) biasS[tid] = __ldg(&bias[n0 + tid]);

    const uint32_t aRaw = smem_u32(As);
    const uint32_t bRaw = smem_u32(Bs);
    const __nv_bfloat16* Xt = X + mBase * 256;
    const float* Wt = W + (size_t)n0 * 256;

    const int lr = tid >> 1;
    const int lh = tid & 1;

    auto issue = [&](int buf, int k0) {
        uint32_t ad = aRaw + buf * (ABUFH * 2) + lr * (APADH * 2) + lh * 16;
        uint32_t bd = bRaw + buf * (TBUF * 4) + lr * (TPAD * 4) + lh * 32;
        const __nv_bfloat16* xs = Xt + lr * 256 + k0 + lh * 8;
        const float* wsrc = Wt + lr * 256 + k0 + lh * 8;
        CP_ASYNC16(ad, xs);
        CP_ASYNC16(bd, wsrc);
        CP_ASYNC16(bd + 16, wsrc + 4);
    };

    float acc[4][4][4];
#pragma unroll
    for (int i = 0; i < 4; i++)
#pragma unroll
        for (int j = 0; j < 4; j++)
#pragma unroll
            for (int r = 0; r < 4; r++) acc[i][j][r] = 0.f;

    issue(0, 0);
    CP_COMMIT();

    const int lq = lane >> 2;
    const int lk = lane & 3;

#pragma unroll 1
    for (int kt = 0; kt < 16; kt++) {
        int buf = kt & 1;
        if (kt < 15) { issue(buf ^ 1, (kt + 1) * 16); CP_COMMIT(); CP_WAIT1(); }
        else CP_WAIT0();
        __syncthreads();

#pragma unroll
        for (int ks = 0; ks < 2; ks++) {
            int kk = ks * 8 + lk;
            uint32_t af[4][4];
#pragma unroll
            for (int mf = 0; mf < 4; mf++) {
                const __nv_bfloat16* ap = &As[buf][(wm * 64 + mf * 16 + lq) * APADH + kk];
                af[mf][0] = bf2f(ap);
                af[mf][1] = bf2f(ap + 8 * APADH);
                af[mf][2] = bf2f(ap + 4);
                af[mf][3] = bf2f(ap + 8 * APADH + 4);
            }
            uint32_t bfr[4][2];
#pragma unroll
            for (int nf = 0; nf < 4; nf++) {
                const float* bp = &Bs[buf][(wn * 32 + nf * 8 + lq) * TPAD + kk];
                bfr[nf][0] = __float_as_uint(bp[0]);
                bfr[nf][1] = __float_as_uint(bp[4]);
            }
#pragma unroll
            for (int mf = 0; mf < 4; mf++)
#pragma unroll
                for (int nf = 0; nf < 4; nf++)
                    mma_tf32(acc[mf][nf], af[mf], bfr[nf]);
        }
        __syncthreads();
    }

    // ---- fused pairsum epilogue ----
    int b0 = (int)(mBase / 625);
    int split = (b0 + 1) * 625;
    bool hasSplit = split < (int)mBase + 128;

    float cs0[4][2], cs1[4][2];
#pragma unroll
    for (int nf = 0; nf < 4; nf++) { cs0[nf][0] = cs0[nf][1] = 0.f; cs1[nf][0] = cs1[nf][1] = 0.f; }

#pragma unroll
    for (int mf = 0; mf < 4; mf++) {
        int rA = (int)mBase + wm * 64 + mf * 16 + lq;
        int rB = rA + 8;
        bool pA = rA >= split;
        bool pB = rB >= split;
#pragma unroll
        for (int nf = 0; nf < 4; nf++) {
            int col = wn * 32 + nf * 8 + 2 * lk;
            float bb0 = biasS[col], bb1 = biasS[col + 1];
            float v0 = fmaxf(acc[mf][nf][0] + bb0, 0.f);
            float v1 = fmaxf(acc[mf][nf][1] + bb1, 0.f);
            float v2 = fmaxf(acc[mf][nf][2] + bb0, 0.f);
            float v3 = fmaxf(acc[mf][nf][3] + bb1, 0.f);
            if (pA) { cs1[nf][0] += v0; cs1[nf][1] += v1; }
            else    { cs0[nf][0] += v0; cs0[nf][1] += v1; }
            if (pB) { cs1[nf][0] += v2; cs1[nf][1] += v3; }
            else    { cs0[nf][0] += v2; cs0[nf][1] += v3; }
        }
    }
#pragma unroll
    for (int off = 4; off <= 16; off <<= 1) {
#pragma unroll
        for (int nf = 0; nf < 4; nf++) {
            cs0[nf][0] += __shfl_xor_sync(0xffffffffu, cs0[nf][0], off);
            cs0[nf][1] += __shfl_xor_sync(0xffffffffu, cs0[nf][1], off);
            cs1[nf][0] += __shfl_xor_sync(0xffffffffu, cs1[nf][0], off);
            cs1[nf][1] += __shfl_xor_sync(0xffffffffu, cs1[nf][1], off);
        }
    }
    if (lq == 0) {
#pragma unroll
        for (int nf = 0; nf < 4; nf++) {
#pragma unroll
            for (int p = 0; p < 2; p++) {
                int col = n0 + wn * 32 + nf * 8 + 2 * lk + p;
                atomicAdd(&xg[b0 * 256 + col], cs0[nf][p]);
                if (hasSplit) atomicAdd(&xg[(b0 + 1) * 256 + col], cs1[nf][p]);
            }
        }
    }
}

// -------------------- fp32 SGEMM (small f-layers) ---------------------------
__global__ void sgemm256(const float* __restrict__ X, const float* __restrict__ W,
                         const float* __restrict__ bias, float* __restrict__ out,
                         int doRelu) {
    __shared__ float Xs[16][128];
    __shared__ float Ws[16][64];
    int bm = blockIdx.y * 128;
    int bn = blockIdx.x * 64;
    int tid = threadIdx.x;
    int tx = tid & 15, ty = tid >> 4;
    float acc[8][4];
#pragma unroll
    for (int i = 0; i < 8; i++)
#pragma unroll
        for (int j = 0; j < 4; j++) acc[i][j] = 0.f;

    int r0 = tid >> 2;
    int c0 = (tid & 3) * 4;
    const float* Xp = X + (size_t)bm * 256;

    for (int k0 = 0; k0 < 256; k0 += 16) {
        float4 x0 = *(const float4*)(Xp + (size_t)r0 * 256 + k0 + c0);
        float4 x1 = *(const float4*)(Xp + (size_t)(r0 + 64) * 256 + k0 + c0);
        float4 wv = *(const float4*)(W + (size_t)(bn + r0) * 256 + k0 + c0);
        Xs[c0 + 0][r0] = x0.x; Xs[c0 + 1][r0] = x0.y; Xs[c0 + 2][r0] = x0.z; Xs[c0 + 3][r0] = x0.w;
        Xs[c0 + 0][r0 + 64] = x1.x; Xs[c0 + 1][r0 + 64] = x1.y; Xs[c0 + 2][r0 + 64] = x1.z; Xs[c0 + 3][r0 + 64] = x1.w;
        Ws[c0 + 0][r0] = wv.x; Ws[c0 + 1][r0] = wv.y; Ws[c0 + 2][r0] = wv.z; Ws[c0 + 3][r0] = wv.w;
        __syncthreads();
#pragma unroll
        for (int k = 0; k < 16; k++) {
            float4 a0 = *(const float4*)&Xs[k][ty * 8];
            float4 a1 = *(const float4*)&Xs[k][ty * 8 + 4];
            float4 b = *(const float4*)&Ws[k][tx * 4];
            acc[0][0] += a0.x * b.x; acc[0][1] += a0.x * b.y; acc[0][2] += a0.x * b.z; acc[0][3] += a0.x * b.w;
            acc[1][0] += a0.y * b.x; acc[1][1] += a0.y * b.y; acc[1][2] += a0.y * b.z; acc[1][3] += a0.y * b.w;
            acc[2][0] += a0.z * b.x; acc[2][1] += a0.z * b.y; acc[2][2] += a0.z * b.z; acc[2][3] += a0.z * b.w;
            acc[3][0] += a0.w * b.x; acc[3][1] += a0.w * b.y; acc[3][2] += a0.w * b.z; acc[3][3] += a0.w * b.w;
            acc[4][0] += a1.x * b.x; acc[4][1] += a1.x * b.y; acc[4][2] += a1.x * b.z; acc[4][3] += a1.x * b.w;
            acc[5][0] += a1.y * b.x; acc[5][1] += a1.y * b.y; acc[5][2] += a1.y * b.z; acc[5][3] += a1.y * b.w;
            acc[6][0] += a1.z * b.x; acc[6][1] += a1.z * b.y; acc[6][2] += a1.z * b.z; acc[6][3] += a1.z * b.w;
            acc[7][0] += a1.w * b.x; acc[7][1] += a1.w * b.y; acc[7][2] += a1.w * b.z; acc[7][3] += a1.w * b.w;
        }
        __syncthreads();
    }
    float4 bv = *(const float4*)&bias[bn + tx * 4];
#pragma unroll
    for (int i = 0; i < 8; i++) {
        int m = bm + ty * 8 + i;
        float4 v;
        v.x = acc[i][0] + bv.x; v.y = acc[i][1] + bv.y;
        v.z = acc[i][2] + bv.z; v.w = acc[i][3] + bv.w;
        if (doRelu) {
            v.x = fmaxf(v.x, 0.f); v.y = fmaxf(v.y, 0.f);
            v.z = fmaxf(v.z, 0.f); v.w = fmaxf(v.w, 0.f);
        }
        *(float4*)(out + (size_t)m * 256 + bn + tx * 4) = v;
    }
}

// -------------------- fc3 + log_softmax -------------------------------------
__global__ void fc3_k(const float* __restrict__ x, const float* __restrict__ w,
                      const float* __restrict__ bias, float* __restrict__ out) {
    int b = blockIdx.x;
    int tid = threadIdx.x; // 320
    int j = tid >> 5, lane = tid & 31;
    __shared__ float lg[10];
    __shared__ float lse;
    const float* xr = x + b * HID;
    const float* wr = w + j * HID;
    float s = 0.f;
    for (int k = lane; k < HID; k += 32) s += xr[k] * wr[k];
#pragma unroll
    for (int o = 16; o > 0; o >>= 1) s += __shfl_xor_sync(0xffffffffu, s, o);
    if (lane == 0) lg[j] = s + bias[j];
    __syncthreads();
    if (tid == 0) {
        float m = lg[0];
#pragma unroll
        for (int t = 1; t < 10; t++) m = fmaxf(m, lg[t]);
        float se = 0.f;
#pragma unroll
        for (int t = 0; t < 10; t++) se += expf(lg[t] - m);
        lse = m + logf(se);
    }
    __syncthreads();
    if (tid < 10) out[b * 10 + tid] = lg[tid] - lse;
}

// ---------------------------------------------------------------------------
extern "C" void kernel_launch(void* const* d_in, const int* in_sizes, int n_in,
                              void* d_out, int out_size) {
    const float* img = (const float*)d_in[0];
    const float* qst = (const float*)d_in[1];
    const float* cw[4] = {(const float*)d_in[2], (const float*)d_in[6], (const float*)d_in[10], (const float*)d_in[14]};
    const float* cb[4] = {(const float*)d_in[3], (const float*)d_in[7], (const float*)d_in[11], (const float*)d_in[15]};
    const float* bg[4] = {(const float*)d_in[4], (const float*)d_in[8], (const float*)d_in[12], (const float*)d_in[16]};
    const float* bb[4] = {(const float*)d_in[5], (const float*)d_in[9], (const float*)d_in[13], (const float*)d_in[17]};
    const float* g1w = (const float*)d_in[18]; const float* g1b = (const float*)d_in[19];
    const float* g2w = (const float*)d_in[20]; const float* g2b = (const float*)d_in[21];
    const float* g3w = (const float*)d_in[22]; const float* g3b = (const float*)d_in[23];
    const float* g4w = (const float*)d_in[24]; const float* g4b = (const float*)d_in[25];
    const float* f1w = (const float*)d_in[26]; const float* f1b = (const float*)d_in[27];
    const float* fc2w = (const float*)d_in[28]; const float* fc2b = (const float*)d_in[29];
    const float* fc3w = (const float*)d_in[30]; const float* fc3b = (const float*)d_in[31];
    float* out = (float*)d_out;

    float *buf1, *buf2, *buf3, *buf4, *obj, *A, *B, *Cb, *xg, *xf1, *xf2, *stats, *wt;
    __nv_bfloat16 *hA, *hB;
    double *psum, *psq;
    cudaGetSymbolAddress((void**)&buf1, g_buf1);
    cudaGetSymbolAddress((void**)&buf2, g_buf2);
    cudaGetSymbolAddress((void**)&buf3, g_buf3);
    cudaGetSymbolAddress((void**)&buf4, g_buf4);
    cudaGetSymbolAddress((void**)&obj, g_obj);
    cudaGetSymbolAddress((void**)&A, g_A);
    cudaGetSymbolAddress((void**)&B, g_B);
    cudaGetSymbolAddress((void**)&Cb, g_Cb);
    cudaGetSymbolAddress((void**)&xg, g_xg);
    cudaGetSymbolAddress((void**)&xf1, g_xf1);
    cudaGetSymbolAddress((void**)&xf2, g_xf2);
    cudaGetSymbolAddress((void**)&stats, g_stats);
    cudaGetSymbolAddress((void**)&psum, g_psum);
    cudaGetSymbolAddress((void**)&psq, g_psq);
    cudaGetSymbolAddress((void**)&wt, g_wt);
    cudaGetSymbolAddress((void**)&hA, g_hbufA);
    cudaGetSymbolAddress((void**)&hB, g_hbufB);

    cudaFuncSetAttribute(gmlp_l2, cudaFuncAttributeMaxDynamicSharedMemorySize, GL2_SMEM);

    // ---- zero accumulators + weight prep ----
    zerod_k<<<1, 128>>>(psum, 96);
    zerod_k<<<1, 128>>>(psq, 96);
    zerof_k<<<512, 256>>>(xg, BATCH * HID);
    wtf32_all<<<768, 256>>>(g2w, g3w, g4w, wt);

    // ---- conv stack (fused BN, pixel-blocked) ----
    conv1_f4<<<800, 256>>>(img, cw[0], cb[0], buf1, psum, psq);
    bn_final_f<<<1, 32>>>(psum, psq, 512.0 * 1600.0, bg[0], stats);
    conv24_fP<40, 20, 4><<<200, 256>>>(buf1, cw[1], cb[1], stats, bb[0], buf2, psum + 24, psq + 24);
    bn_final_f<<<1, 32>>>(psum + 24, psq + 24, 512.0 * 400.0, bg[1], stats + 48);
    conv24_fP<20, 10, 2><<<100, 256>>>(buf2, cw[2], cb[2], stats + 48, bb[1], buf3, psum + 48, psq + 48);
    bn_final_f<<<1, 32>>>(psum + 48, psq + 48, 512.0 * 100.0, bg[2], stats + 96);
    conv24_fP<10, 5, 1><<<50, 256>>>(buf3, cw[3], cb[3], stats + 96, bb[2], buf4, psum + 72, psq + 72);
    bn_final_f<<<1, 32>>>(psum + 72, psq + 72, 512.0 * 25.0, bg[3], stats + 144);

    // ---- objects + decomposed g1 ----
    obj_f<<<(BATCH * OBJ * 26 + 255) / 256, 256>>>(buf4, stats + 144, bb[3], obj);
    ab_k<<<BATCH * OBJ, 256>>>(obj, g1w, A, B);
    cb_k<<<BATCH, 256>>>(qst, g1w, g1b, Cb);

    // ---- g2 (fused h1) -> g3 -> g4 (fused pairsum), bf16 intermediates ----
    dim3 ggrid(2, BATCH * OBJ * OBJ / 128);  // (2, 2500)
    gmlp_l2<<<ggrid, 256, GL2_SMEM>>>(A, B, Cb, wt, g2b, hB);
    gmlp_l3<<<ggrid, 256>>>(hB, wt + HID * HID, g3b, hA);
    gmlp_l4<<<ggrid, 256>>>(hA, wt + 2 * HID * HID, g4b, xg);

    // ---- f-MLP (fp32) ----
    dim3 fgrid(256 / 64, BATCH / 128);
    sgemm256<<<fgrid, 256>>>(xg, f1w, f1b, xf1, 1);
    sgemm256<<<fgrid, 256>>>(xf1, fc2w, fc2b, xf2, 1);
    fc3_k<<<BATCH, 320>>>(xf2, fc3w, fc3b, out);
}

// round 14
// speedup vs baseline: 1.4846x; 1.2274x over previous
#include <cuda_runtime.h>
#include <cuda_bf16.h>
#include <cuda_fp16.h>
#include <math.h>
#include <stdint.h>

#define BATCH 512
#define FS 24
#define QDIM 11
#define HID 256
#define OBJ 25
#define EPS 1e-5f

// -------------------- scratch (device globals; no allocation) --------------
__device__ __align__(16) float g_buf1[BATCH * FS * 40 * 40];
__device__ __align__(16) float g_buf2[BATCH * FS * 20 * 20];
__device__ __align__(16) float g_buf3[BATCH * FS * 10 * 10];
__device__ __align__(16) float g_buf4[BATCH * FS * 5 * 5];
__device__ float g_obj[BATCH * OBJ * 26];
__device__ __align__(16) float g_A[BATCH * OBJ * HID];
__device__ __align__(16) float g_B[BATCH * OBJ * HID];
__device__ __align__(16) float g_Cb[BATCH * HID];
__device__ __align__(16) __half g_wh[3][HID * HID];   // fp16 g weights
__device__ float g_xg[BATCH * HID];
__device__ float g_xf1[BATCH * HID];
__device__ float g_xf2[BATCH * HID];
__device__ double g_psum[4 * 24];
__device__ double g_psq[4 * 24];
__device__ float g_stats[4 * 48];
// intermediate activations in fp16 (g2 out / g3 out)
__device__ __align__(16) __half g_hbufA[BATCH * OBJ * OBJ * HID];
__device__ __align__(16) __half g_hbufB[BATCH * OBJ * OBJ * HID];

// ===================== helpers ==============================================
__device__ __forceinline__ uint32_t smem_u32(const void* p) {
    uint32_t a;
    asm("{ .reg .u64 tmp; cvta.to.shared.u64 tmp, %1; cvt.u32.u64 %0, tmp; }"
        : "=r"(a) : "l"(p));
    return a;
}

#define CP_ASYNC16(dst, src) \
    asm volatile("cp.async.cg.shared.global [%0], [%1], 16;" :: "r"(dst), "l"(src))
#define CP_COMMIT() asm volatile("cp.async.commit_group;")
#define CP_WAIT1() asm volatile("cp.async.wait_group 1;")
#define CP_WAIT0() asm volatile("cp.async.wait_group 0;")

// f16 MMA, fp32 accum: D(16x8) += A(16x16,row) * B(16x8,col)
__device__ __forceinline__ void mma_f16(float* d, const uint32_t* a, const uint32_t* b) {
    asm volatile(
        "mma.sync.aligned.m16n8k16.row.col.f32.f16.f16.f32 "
        "{%0,%1,%2,%3}, {%4,%5,%6,%7}, {%8,%9}, {%0,%1,%2,%3};"
        : "+f"(d[0]), "+f"(d[1]), "+f"(d[2]), "+f"(d[3])
        : "r"(a[0]), "r"(a[1]), "r"(a[2]), "r"(a[3]), "r"(b[0]), "r"(b[1]));
}

__device__ __forceinline__ uint32_t pack_h2(float a, float b) {
    __half2 h = __floats2half2_rn(a, b);
    return *(uint32_t*)&h;
}

// -------------------- zero / prep kernels -----------------------------------
__global__ void zerof_k(float* p, int n) {
    int i = blockIdx.x * blockDim.x + threadIdx.x;
    if (i < n) p[i] = 0.f;
}
__global__ void zerod_k(double* p, int n) {
    int i = blockIdx.x * blockDim.x + threadIdx.x;
    if (i < n) p[i] = 0.0;
}
__global__ void whalf_all(const float* __restrict__ w2, const float* __restrict__ w3,
                          const float* __restrict__ w4, __half* __restrict__ o) {
    int idx = blockIdx.x * blockDim.x + threadIdx.x;
    if (idx >= 3 * HID * HID) return;
    int sel = idx >> 16;
    int off = idx & 0xFFFF;
    const float* src = (sel == 0) ? w2 : (sel == 1) ? w3 : w4;
    o[idx] = __float2half_rn(src[off]);
}

// -------------------- conv1: Cin=3, 80->40, P=4 pixels/thread ---------------
__global__ void __launch_bounds__(256)
conv1_f4(const float* __restrict__ in, const float* __restrict__ w,
         const float* __restrict__ bias, float* __restrict__ out,
         double* __restrict__ psum, double* __restrict__ psq) {
    __shared__ float ws[648];
    __shared__ float bs[24];
    __shared__ float srs[8][24];
    __shared__ float srq[8][24];
    int tid = threadIdx.x;
    for (int i = tid; i < 648; i += 256) ws[i] = w[i];
    if (tid < 24) bs[tid] = bias[tid];
    __syncthreads();

    int idx = blockIdx.x * 256 + tid;
    int chunk = idx % 400;
    int b = idx / 400;
    int oy = chunk / 10;
    int ox0 = (chunk % 10) * 4;
    int iy0 = 2 * oy - 1;
    int ix0 = 2 * ox0 - 1;

    float acc[24][4];
#pragma unroll
    for (int c = 0; c < 24; c++)
#pragma unroll
        for (int p = 0; p < 4; p++) acc[c][p] = bs[c];

    const float* ip = in + (size_t)b * 3 * 6400;
#pragma unroll
    for (int ci = 0; ci < 3; ci++) {
        const float* ic = ip + ci * 6400;
#pragma unroll
        for (int ky = 0; ky < 3; ky++) {
            int iy = iy0 + ky;
            bool vy = (unsigned)iy < 80u;
            float iv[9];
#pragma unroll
            for (int j = 0; j < 9; j++) {
                int ix = ix0 + j;
                iv[j] = (vy && (unsigned)ix < 80u) ? ic[iy * 80 + ix] : 0.f;
            }
#pragma unroll
            for (int kx = 0; kx < 3; kx++) {
                int t = ci * 9 + ky * 3 + kx;
#pragma unroll
                for (int co = 0; co < 24; co++) {
                    float wv = ws[co * 27 + t];
#pragma unroll
                    for (int p = 0; p < 4; p++)
                        acc[co][p] = fmaf(iv[2 * p + kx], wv, acc[co][p]);
                }
            }
        }
    }

    int wid = tid >> 5, lane = tid & 31;
    float* op = out + (size_t)b * 24 * 1600 + oy * 40 + ox0;
#pragma unroll
    for (int co = 0; co < 24; co++) {
        float4 y4;
        float* yp = (float*)&y4;
        float s = 0.f, q = 0.f;
#pragma unroll
        for (int p = 0; p < 4; p++) {
            float y = fmaxf(acc[co][p], 0.f);
            yp[p] = y;
            s += y; q += y * y;
        }
        *(float4*)(op + co * 1600) = y4;
#pragma unroll
        for (int off = 16; off > 0; off >>= 1) {
            s += __shfl_xor_sync(0xffffffffu, s, off);
            q += __shfl_xor_sync(0xffffffffu, q, off);
        }
        if (lane == 0) { srs[wid][co] = s; srq[wid][co] = q; }
    }
    __syncthreads();
    if (tid < 24) {
        double S = 0.0, Q = 0.0;
#pragma unroll
        for (int wk = 0; wk < 8; wk++) { S += srs[wk][tid]; Q += srq[wk][tid]; }
        atomicAdd(&psum[tid], S);
        atomicAdd(&psq[tid], Q);
    }
}

// -------------------- convN: Cin=24, P pixels/thread, BN fused --------------
template <int HIN, int HOUT, int P>
__global__ void __launch_bounds__(256)
conv24_fP(const float* __restrict__ in, const float* __restrict__ w,
          const float* __restrict__ bias,
          const float* __restrict__ statsPrev, const float* __restrict__ betaPrev,
          float* __restrict__ out,
          double* __restrict__ psum, double* __restrict__ psq) {
    __shared__ float ws[5184];
    __shared__ float bs[24];
    __shared__ float ab[24];
    __shared__ float dd[24];
    __shared__ float srs[8][24];
    __shared__ float srq[8][24];
    int tid = threadIdx.x;
    for (int i = tid; i < 5184; i += 256) ws[i] = w[i];
    if (tid < 24) {
        bs[tid] = bias[tid];
        float sc = statsPrev[24 + tid];
        ab[tid] = sc;
        dd[tid] = betaPrev[tid] - statsPrev[tid] * sc;
    }
    __syncthreads();

    const int PIX = HOUT * HOUT;
    const int CHW = HOUT / P;
    int idx = blockIdx.x * 256 + tid;
    int chunk = idx % (PIX / P);
    int b = idx / (PIX / P);
    int oy = chunk / CHW;
    int ox0 = (chunk % CHW) * P;
    int iy0 = 2 * oy - 1;
    int ix0 = 2 * ox0 - 1;

    float acc[24][P];
#pragma unroll
    for (int c = 0; c < 24; c++)
#pragma unroll
        for (int p = 0; p < P; p++) acc[c][p] = bs[c];

    const float* ip = in + (size_t)b * 24 * HIN * HIN;
    for (int ci = 0; ci < 24; ci++) {
        float ai = ab[ci], di = dd[ci];
        const float* ic = ip + ci * HIN * HIN;
#pragma unroll
        for (int ky = 0; ky < 3; ky++) {
            int iy = iy0 + ky;
            bool vy = (unsigned)iy < (unsigned)HIN;
            float iv[2 * P + 1];
#pragma unroll
            for (int j = 0; j < 2 * P + 1; j++) {
                int ix = ix0 + j;
                iv[j] = (vy && (unsigned)ix < (unsigned)HIN)
                            ? fmaf(ic[iy * HIN + ix], ai, di) : 0.f;
            }
#pragma unroll
            for (int kx = 0; kx < 3; kx++) {
                int t = ci * 9 + ky * 3 + kx;
#pragma unroll
                for (int co = 0; co < 24; co++) {
                    float wv = ws[co * 216 + t];
#pragma unroll
                    for (int p = 0; p < P; p++)
                        acc[co][p] = fmaf(iv[2 * p + kx], wv, acc[co][p]);
                }
            }
        }
    }

    int wid = tid >> 5, lane = tid & 31;
    float* op = out + (size_t)b * 24 * PIX + oy * HOUT + ox0;
#pragma unroll
    for (int co = 0; co < 24; co++) {
        float yv[P];
        float s = 0.f, q = 0.f;
#pragma unroll
        for (int p = 0; p < P; p++) {
            float y = fmaxf(acc[co][p], 0.f);
            yv[p] = y;
            s += y; q += y * y;
        }
        if (P == 4) {
            float4 y4 = {yv[0], yv[1], yv[2], yv[3]};
            *(float4*)(op + co * PIX) = y4;
        } else if (P == 2) {
            float2 y2 = {yv[0], yv[1]};
            *(float2*)(op + co * PIX) = y2;
        } else {
#pragma unroll
            for (int p = 0; p < P; p++) op[co * PIX + p] = yv[p];
        }
#pragma unroll
        for (int off = 16; off > 0; off >>= 1) {
            s += __shfl_xor_sync(0xffffffffu, s, off);
            q += __shfl_xor_sync(0xffffffffu, q, off);
        }
        if (lane == 0) { srs[wid][co] = s; srq[wid][co] = q; }
    }
    __syncthreads();
    if (tid < 24) {
        double S = 0.0, Q = 0.0;
#pragma unroll
        for (int wk = 0; wk < 8; wk++) { S += srs[wk][tid]; Q += srq[wk][tid]; }
        atomicAdd(&psum[tid], S);
        atomicAdd(&psq[tid], Q);
    }
}

// -------------------- finalize BN stats -------------------------------------
__global__ void bn_final_f(const double* __restrict__ psum, const double* __restrict__ psq,
                           double N, const float* __restrict__ gamma,
                           float* __restrict__ stats) {
    int c = threadIdx.x;
    if (c >= 24) return;
    double mean = psum[c] / N;
    double var = psq[c] / N - mean * mean;
    stats[c] = (float)mean;
    stats[24 + c] = gamma[c] * rsqrtf((float)var + EPS);
}

// -------------------- object extraction (applies BN4) -----------------------
__global__ void obj_f(const float* __restrict__ x4, const float* __restrict__ stats4,
                      const float* __restrict__ beta4, float* __restrict__ obj) {
    int idx = blockIdx.x * blockDim.x + threadIdx.x;
    const int total = BATCH * OBJ * 26;
    if (idx >= total) return;
    int f = idx % 26; int t = idx / 26;
    int o = t % OBJ; int b = t / OBJ;
    float v;
    if (f < FS) {
        float y = x4[((size_t)b * FS + f) * OBJ + o];
        v = (y - stats4[f]) * stats4[24 + f] + beta4[f];
    } else if (f == FS) v = ((float)(o / 5) - 2.f) * 0.5f;
    else v = ((float)(o % 5) - 2.f) * 0.5f;
    obj[idx] = v;
}

// -------------------- g1 decomposition --------------------------------------
__global__ void ab_k(const float* __restrict__ obj, const float* __restrict__ g1w,
                     float* __restrict__ A, float* __restrict__ B) {
    int m = blockIdx.x;
    int n = threadIdx.x;
    __shared__ float os[26];
    if (n < 26) os[n] = obj[m * 26 + n];
    __syncthreads();
    const float* wr = g1w + n * 63;
    float sa = 0.f, sb = 0.f;
#pragma unroll
    for (int f = 0; f < 26; f++) {
        float o = os[f];
        sa += o * __ldg(&wr[f]);
        sb += o * __ldg(&wr[26 + f]);
    }
    A[m * HID + n] = sa;
    B[m * HID + n] = sb;
}

__global__ void cb_k(const float* __restrict__ qst, const float* __restrict__ g1w,
                     const float* __restrict__ g1b, float* __restrict__ Cb) {
    int b = blockIdx.x;
    int n = threadIdx.x;
    __shared__ float qs[QDIM];
    if (n < QDIM) qs[n] = qst[n * BATCH + b];
    __syncthreads();
    const float* wr = g1w + n * 63 + 52;
    float s = g1b[n];
#pragma unroll
    for (int d = 0; d < QDIM; d++) s += qs[d] * __ldg(&wr[d]);
    Cb[b * HID + n] = s;
}

// ==================== fp16 MMA g-path =======================================
// Fragment layout m16n8k16.row.col:
//  A: af0 = A[row][2lk..+1], af1 = A[row+8][..], af2 = A[row][2lk+8..], af3 = A[row+8][2lk+8..]
//  B: bf0 = W[n][2lk..+1],  bf1 = W[n][2lk+8..+1]
//  D: rows {lq, lq+8}, cols 2lk, 2lk+1 (same as tf32 epilogues)
#define HPAD16 264               // h1 smem row pad (halves); 528B rows, conflict-free
#define APAD16 24                // streamed K-chunk buffer pad (halves); 48B rows
#define ABUF16 (128 * APAD16)    // halves per buffer

// ---- g2: fused h1 build (fp16 smem) + f16 MMA; grid (2, 2500), 256 thr ----
#define GL2_SMEM (128 * HPAD16 * 2 + 2 * ABUF16 * 2 + 128 * 4)

__global__ void __launch_bounds__(256, 2)
gmlp_l2(const float* __restrict__ Ag, const float* __restrict__ Bg,
        const float* __restrict__ Cg, const __half* __restrict__ W,
        const float* __restrict__ bias, __half* __restrict__ Y) {
    extern __shared__ char smraw[];
    __half* h1s = (__half*)smraw;                       // [128 * HPAD16]
    __half* Ws = (__half*)(smraw + 128 * HPAD16 * 2);   // [2][ABUF16]
    float* biasS = (float*)(smraw + 128 * HPAD16 * 2 + 2 * ABUF16 * 2);

    const int tid = threadIdx.x;
    const int wid = tid >> 5;
    const int lane = tid & 31;
    const int wm = wid >> 2;
    const int wn = wid & 3;
    const int n0 = blockIdx.x * 128;
    const size_t mBase = (size_t)blockIdx.y * 128;

    if (tid < 128) biasS[tid] = __ldg(&bias[n0 + tid]);

    const int lr = tid >> 1;
    const int lh = tid & 1;

    // ---- build h1 tile (fp16) ----
    {
        int r = (int)mBase + lr;
        int b = r / 625;
        int rem = r - b * 625;
        int ko = rem / 25;
        int ii = rem - ko * 25;
        const float4* pA = (const float4*)(Ag + (b * 25 + ii) * 256);
        const float4* pB = (const float4*)(Bg + (b * 25 + ko) * 256);
        const float4* pC = (const float4*)(Cg + b * 256);
        __half* hrow = h1s + lr * HPAD16 + lh * 128;
        int cbase = lh * 32;     // float4 index base
#pragma unroll 4
        for (int j = 0; j < 16; j++) {
            float4 a = __ldg(pA + cbase + 2 * j), a1 = __ldg(pA + cbase + 2 * j + 1);
            float4 b4 = __ldg(pB + cbase + 2 * j), b1 = __ldg(pB + cbase + 2 * j + 1);
            float4 c = __ldg(pC + cbase + 2 * j), c1 = __ldg(pC + cbase + 2 * j + 1);
            uint4 o;
            o.x = pack_h2(fmaxf(a.x + b4.x + c.x, 0.f), fmaxf(a.y + b4.y + c.y, 0.f));
            o.y = pack_h2(fmaxf(a.z + b4.z + c.z, 0.f), fmaxf(a.w + b4.w + c.w, 0.f));
            o.z = pack_h2(fmaxf(a1.x + b1.x + c1.x, 0.f), fmaxf(a1.y + b1.y + c1.y, 0.f));
            o.w = pack_h2(fmaxf(a1.z + b1.z + c1.z, 0.f), fmaxf(a1.w + b1.w + c1.w, 0.f));
            *(uint4*)(hrow + j * 8) = o;
        }
    }

    const __half* Wt = W + (size_t)n0 * 256;
    const uint32_t wRaw = smem_u32(Ws);
    auto issue = [&](int buf, int k0) {
        uint32_t bd = wRaw + buf * (ABUF16 * 2) + lr * (APAD16 * 2) + lh * 16;
        CP_ASYNC16(bd, Wt + lr * 256 + k0 + lh * 8);
    };

    float acc[4][4][4];
#pragma unroll
    for (int i = 0; i < 4; i++)
#pragma unroll
        for (int j = 0; j < 4; j++)
#pragma unroll
            for (int r = 0; r < 4; r++) acc[i][j][r] = 0.f;

    issue(0, 0);
    CP_COMMIT();
    __syncthreads();   // h1s visible

    const int lq = lane >> 2;
    const int lk = lane & 3;

#pragma unroll 1
    for (int kt = 0; kt < 16; kt++) {
        int buf = kt & 1;
        if (kt < 15) { issue(buf ^ 1, (kt + 1) * 16); CP_COMMIT(); CP_WAIT1(); }
        else CP_WAIT0();
        __syncthreads();

        int kk = kt * 16 + 2 * lk;
        uint32_t af[4][4];
#pragma unroll
        for (int mf = 0; mf < 4; mf++) {
            const __half* ap = &h1s[(wm * 64 + mf * 16 + lq) * HPAD16 + kk];
            af[mf][0] = *(const uint32_t*)ap;
            af[mf][1] = *(const uint32_t*)(ap + 8 * HPAD16);
            af[mf][2] = *(const uint32_t*)(ap + 8);
            af[mf][3] = *(const uint32_t*)(ap + 8 * HPAD16 + 8);
        }
        int kw = 2 * lk;
#pragma unroll
        for (int nf = 0; nf < 4; nf++) {
            const __half* bp = &Ws[buf * ABUF16 + (wn * 32 + nf * 8 + lq) * APAD16 + kw];
            uint32_t bfr[2];
            bfr[0] = *(const uint32_t*)bp;
            bfr[1] = *(const uint32_t*)(bp + 8);
#pragma unroll
            for (int mf = 0; mf < 4; mf++)
                mma_f16(acc[mf][nf], af[mf], bfr);
        }
        __syncthreads();
    }

#pragma unroll
    for (int mf = 0; mf < 4; mf++) {
        size_t r0 = mBase + wm * 64 + mf * 16 + lq;
        __half* y0 = Y + r0 * 256 + n0;
        __half* y1 = y0 + 8 * 256;
#pragma unroll
        for (int nf = 0; nf < 4; nf++) {
            int col = wn * 32 + nf * 8 + 2 * lk;
            float b0 = biasS[col], b1 = biasS[col + 1];
            uint32_t p0 = pack_h2(fmaxf(acc[mf][nf][0] + b0, 0.f),
                                  fmaxf(acc[mf][nf][1] + b1, 0.f));
            uint32_t p1 = pack_h2(fmaxf(acc[mf][nf][2] + b0, 0.f),
                                  fmaxf(acc[mf][nf][3] + b1, 0.f));
            *(uint32_t*)(y0 + col) = p0;
            *(uint32_t*)(y1 + col) = p1;
        }
    }
}

// ---- g3: fp16 in/out, f16 MMA, grid (2, 2500) ----
__global__ void __launch_bounds__(256, 2)
gmlp_l3(const __half* __restrict__ X, const __half* __restrict__ W,
        const float* __restrict__ bias, __half* __restrict__ Y) {
    __shared__ __align__(16) __half As[2][ABUF16];
    __shared__ __align__(16) __half Bs[2][ABUF16];
    __shared__ float biasS[128];

    const int tid = threadIdx.x;
    const int wid = tid >> 5;
    const int lane = tid & 31;
    const int wm = wid >> 2;
    const int wn = wid & 3;
    const int n0 = blockIdx.x * 128;
    const size_t mBase = (size_t)blockIdx.y * 128;

    if (tid < 128) biasS[tid] = __ldg(&bias[n0 + tid]);

    const uint32_t aRaw = smem_u32(As);
    const uint32_t bRaw = smem_u32(Bs);
    const __half* Xt = X + mBase * 256;
    const __half* Wt = W + (size_t)n0 * 256;

    const int lr = tid >> 1;
    const int lh = tid & 1;

    auto issue = [&](int buf, int k0) {
        uint32_t ad = aRaw + buf * (ABUF16 * 2) + lr * (APAD16 * 2) + lh * 16;
        uint32_t bd = bRaw + buf * (ABUF16 * 2) + lr * (APAD16 * 2) + lh * 16;
        CP_ASYNC16(ad, Xt + lr * 256 + k0 + lh * 8);
        CP_ASYNC16(bd, Wt + lr * 256 + k0 + lh * 8);
    };

    float acc[4][4][4];
#pragma unroll
    for (int i = 0; i < 4; i++)
#pragma unroll
        for (int j = 0; j < 4; j++)
#pragma unroll
            for (int r = 0; r < 4; r++) acc[i][j][r] = 0.f;

    issue(0, 0);
    CP_COMMIT();

    const int lq = lane >> 2;
    const int lk = lane & 3;

#pragma unroll 1
    for (int kt = 0; kt < 16; kt++) {
        int buf = kt & 1;
        if (kt < 15) { issue(buf ^ 1, (kt + 1) * 16); CP_COMMIT(); CP_WAIT1(); }
        else CP_WAIT0();
        __syncthreads();

        int kw = 2 * lk;
        uint32_t af[4][4];
#pragma unroll
        for (int mf = 0; mf < 4; mf++) {
            const __half* ap = &As[buf][(wm * 64 + mf * 16 + lq) * APAD16 + kw];
            af[mf][0] = *(const uint32_t*)ap;
            af[mf][1] = *(const uint32_t*)(ap + 8 * APAD16);
            af[mf][2] = *(const uint32_t*)(ap + 8);
            af[mf][3] = *(const uint32_t*)(ap + 8 * APAD16 + 8);
        }
#pragma unroll
        for (int nf = 0; nf < 4; nf++) {
            const __half* bp = &Bs[buf][(wn * 32 + nf * 8 + lq) * APAD16 + kw];
            uint32_t bfr[2];
            bfr[0] = *(const uint32_t*)bp;
            bfr[1] = *(const uint32_t*)(bp + 8);
#pragma unroll
            for (int mf = 0; mf < 4; mf++)
                mma_f16(acc[mf][nf], af[mf], bfr);
        }
        __syncthreads();
    }

#pragma unroll
    for (int mf = 0; mf < 4; mf++) {
        size_t r0 = mBase + wm * 64 + mf * 16 + lq;
        __half* y0 = Y + r0 * 256 + n0;
        __half* y1 = y0 + 8 * 256;
#pragma unroll
        for (int nf = 0; nf < 4; nf++) {
            int col = wn * 32 + nf * 8 + 2 * lk;
            float b0 = biasS[col], b1 = biasS[col + 1];
            uint32_t p0 = pack_h2(fmaxf(acc[mf][nf][0] + b0, 0.f),
                                  fmaxf(acc[mf][nf][1] + b1, 0.f));
            uint32_t p1 = pack_h2(fmaxf(acc[mf][nf][2] + b0, 0.f),
                                  fmaxf(acc[mf][nf][3] + b1, 0.f));
            *(uint32_t*)(y0 + col) = p0;
            *(uint32_t*)(y1 + col) = p1;
        }
    }
}

// ---- g4: fp16 in, f16 MMA + fused pairsum (atomic) ----
__global__ void __launch_bounds__(256, 2)
gmlp_l4(const __half* __restrict__ X, const __half* __restrict__ W,
        const float* __restrict__ bias, float* __restrict__ xg) {
    __shared__ __align__(16) __half As[2][ABUF16];
    __shared__ __align__(16) __half Bs[2][ABUF16];
    __shared__ float biasS[128];

    const int tid = threadIdx.x;
    const int wid = tid >> 5;
    const int lane = tid & 31;
    const int wm = wid >> 2;
    const int wn = wid & 3;
    const int n0 = blockIdx.x * 128;
    const size_t mBase = (size_t)blockIdx.y * 128;

    if (tid < 128) biasS[tid] = __ldg(&bias[n0 + tid]);

    const uint32_t aRaw = smem_u32(As);
    const uint32_t bRaw = smem_u32(Bs);
    const __half* Xt = X + mBase * 256;
    const __half* Wt = W + (size_t)n0 * 256;

    const int lr = tid >> 1;
    const int lh = tid & 1;

    auto issue = [&](int buf, int k0) {
        uint32_t ad = aRaw + buf * (ABUF16 * 2) + lr * (APAD16 * 2) + lh * 16;
        uint32_t bd = bRaw + buf * (ABUF16 * 2) + lr * (APAD16 * 2) + lh * 16;
        CP_ASYNC16(ad, Xt + lr * 256 + k0 + lh * 8);
        CP_ASYNC16(bd, Wt + lr * 256 + k0 + lh * 8);
    };

    float acc[4][4][4];
#pragma unroll
    for (int i = 0; i < 4; i++)
#pragma unroll
        for (int j = 0; j < 4; j++)
#pragma unroll
            for (int r = 0; r < 4; r++) acc[i][j][r] = 0.f;

    issue(0, 0);
    CP_COMMIT();

    const int lq = lane >> 2;
    const int lk = lane & 3;

#pragma unroll 1
    for (int kt = 0; kt < 16; kt++) {
        int buf = kt & 1;
        if (kt < 15) { issue(buf ^ 1, (kt + 1) * 16); CP_COMMIT(); CP_WAIT1(); }
        else CP_WAIT0();
        __syncthreads();

        int kw = 2 * lk;
        uint32_t af[4][4];
#pragma unroll
        for (int mf = 0; mf < 4; mf++) {
            const __half* ap = &As[buf][(wm * 64 + mf * 16 + lq) * APAD16 + kw];
            af[mf][0] = *(const uint32_t*)ap;
            af[mf][1] = *(const uint32_t*)(ap + 8 * APAD16);
            af[mf][2] = *(const uint32_t*)(ap + 8);
            af[mf][3] = *(const uint32_t*)(ap + 8 * APAD16 + 8);
        }
#pragma unroll
        for (int nf = 0; nf < 4; nf++) {
            const __half* bp = &Bs[buf][(wn * 32 + nf * 8 + lq) * APAD16 + kw];
            uint32_t bfr[2];
            bfr[0] = *(const uint32_t*)bp;
            bfr[1] = *(const uint32_t*)(bp + 8);
#pragma unroll
            for (int mf = 0; mf < 4; mf++)
                mma_f16(acc[mf][nf], af[mf], bfr);
        }
        __syncthreads();
    }

    // ---- fused pairsum epilogue ----
    int b0 = (int)(mBase / 625);
    int split = (b0 + 1) * 625;
    bool hasSplit = split < (int)mBase + 128;

    float cs0[4][2], cs1[4][2];
#pragma unroll
    for (int nf = 0; nf < 4; nf++) { cs0[nf][0] = cs0[nf][1] = 0.f; cs1[nf][0] = cs1[nf][1] = 0.f; }

#pragma unroll
    for (int mf = 0; mf < 4; mf++) {
        int rA = (int)mBase + wm * 64 + mf * 16 + lq;
        int rB = rA + 8;
        bool pA = rA >= split;
        bool pB = rB >= split;
#pragma unroll
        for (int nf = 0; nf < 4; nf++) {
            int col = wn * 32 + nf * 8 + 2 * lk;
            float bb0 = biasS[col], bb1 = biasS[col + 1];
            float v0 = fmaxf(acc[mf][nf][0] + bb0, 0.f);
            float v1 = fmaxf(acc[mf][nf][1] + bb1, 0.f);
            float v2 = fmaxf(acc[mf][nf][2] + bb0, 0.f);
            float v3 = fmaxf(acc[mf][nf][3] + bb1, 0.f);
            if (pA) { cs1[nf][0] += v0; cs1[nf][1] += v1; }
            else    { cs0[nf][0] += v0; cs0[nf][1] += v1; }
            if (pB) { cs1[nf][0] += v2; cs1[nf][1] += v3; }
            else    { cs0[nf][0] += v2; cs0[nf][1] += v3; }
        }
    }
#pragma unroll
    for (int off = 4; off <= 16; off <<= 1) {
#pragma unroll
        for (int nf = 0; nf < 4; nf++) {
            cs0[nf][0] += __shfl_xor_sync(0xffffffffu, cs0[nf][0], off);
            cs0[nf][1] += __shfl_xor_sync(0xffffffffu, cs0[nf][1], off);
            cs1[nf][0] += __shfl_xor_sync(0xffffffffu, cs1[nf][0], off);
            cs1[nf][1] += __shfl_xor_sync(0xffffffffu, cs1[nf][1], off);
        }
    }
    if (lq == 0) {
#pragma unroll
        for (int nf = 0; nf < 4; nf++) {
#pragma unroll
            for (int p = 0; p < 2; p++) {
                int col = n0 + wn * 32 + nf * 8 + 2 * lk + p;
                atomicAdd(&xg[b0 * 256 + col], cs0[nf][p]);
                if (hasSplit) atomicAdd(&xg[(b0 + 1) * 256 + col], cs1[nf][p]);
            }
        }
    }
}

// -------------------- fp32 SGEMM (small f-layers) ---------------------------
__global__ void sgemm256(const float* __restrict__ X, const float* __restrict__ W,
                         const float* __restrict__ bias, float* __restrict__ out,
                         int doRelu) {
    __shared__ float Xs[16][128];
    __shared__ float Ws[16][64];
    int bm = blockIdx.y * 128;
    int bn = blockIdx.x * 64;
    int tid = threadIdx.x;
    int tx = tid & 15, ty = tid >> 4;
    float acc[8][4];
#pragma unroll
    for (int i = 0; i < 8; i++)
#pragma unroll
        for (int j = 0; j < 4; j++) acc[i][j] = 0.f;

    int r0 = tid >> 2;
    int c0 = (tid & 3) * 4;
    const float* Xp = X + (size_t)bm * 256;

    for (int k0 = 0; k0 < 256; k0 += 16) {
        float4 x0 = *(const float4*)(Xp + (size_t)r0 * 256 + k0 + c0);
        float4 x1 = *(const float4*)(Xp + (size_t)(r0 + 64) * 256 + k0 + c0);
        float4 wv = *(const float4*)(W + (size_t)(bn + r0) * 256 + k0 + c0);
        Xs[c0 + 0][r0] = x0.x; Xs[c0 + 1][r0] = x0.y; Xs[c0 + 2][r0] = x0.z; Xs[c0 + 3][r0] = x0.w;
        Xs[c0 + 0][r0 + 64] = x1.x; Xs[c0 + 1][r0 + 64] = x1.y; Xs[c0 + 2][r0 + 64] = x1.z; Xs[c0 + 3][r0 + 64] = x1.w;
        Ws[c0 + 0][r0] = wv.x; Ws[c0 + 1][r0] = wv.y; Ws[c0 + 2][r0] = wv.z; Ws[c0 + 3][r0] = wv.w;
        __syncthreads();
#pragma unroll
        for (int k = 0; k < 16; k++) {
            float4 a0 = *(const float4*)&Xs[k][ty * 8];
            float4 a1 = *(const float4*)&Xs[k][ty * 8 + 4];
            float4 b = *(const float4*)&Ws[k][tx * 4];
            acc[0][0] += a0.x * b.x; acc[0][1] += a0.x * b.y; acc[0][2] += a0.x * b.z; acc[0][3] += a0.x * b.w;
            acc[1][0] += a0.y * b.x; acc[1][1] += a0.y * b.y; acc[1][2] += a0.y * b.z; acc[1][3] += a0.y * b.w;
            acc[2][0] += a0.z * b.x; acc[2][1] += a0.z * b.y; acc[2][2] += a0.z * b.z; acc[2][3] += a0.z * b.w;
            acc[3][0] += a0.w * b.x; acc[3][1] += a0.w * b.y; acc[3][2] += a0.w * b.z; acc[3][3] += a0.w * b.w;
            acc[4][0] += a1.x * b.x; acc[4][1] += a1.x * b.y; acc[4][2] += a1.x * b.z; acc[4][3] += a1.x * b.w;
            acc[5][0] += a1.y * b.x; acc[5][1] += a1.y * b.y; acc[5][2] += a1.y * b.z; acc[5][3] += a1.y * b.w;
            acc[6][0] += a1.z * b.x; acc[6][1] += a1.z * b.y; acc[6][2] += a1.z * b.z; acc[6][3] += a1.z * b.w;
            acc[7][0] += a1.w * b.x; acc[7][1] += a1.w * b.y; acc[7][2] += a1.w * b.z; acc[7][3] += a1.w * b.w;
        }
        __syncthreads();
    }
    float4 bv = *(const float4*)&bias[bn + tx * 4];
#pragma unroll
    for (int i = 0; i < 8; i++) {
        int m = bm + ty * 8 + i;
        float4 v;
        v.x = acc[i][0] + bv.x; v.y = acc[i][1] + bv.y;
        v.z = acc[i][2] + bv.z; v.w = acc[i][3] + bv.w;
        if (doRelu) {
            v.x = fmaxf(v.x, 0.f); v.y = fmaxf(v.y, 0.f);
            v.z = fmaxf(v.z, 0.f); v.w = fmaxf(v.w, 0.f);
        }
        *(float4*)(out + (size_t)m * 256 + bn + tx * 4) = v;
    }
}

// -------------------- fc3 + log_softmax -------------------------------------
__global__ void fc3_k(const float* __restrict__ x, const float* __restrict__ w,
                      const float* __restrict__ bias, float* __restrict__ out) {
    int b = blockIdx.x;
    int tid = threadIdx.x; // 320
    int j = tid >> 5, lane = tid & 31;
    __shared__ float lg[10];
    __shared__ float lse;
    const float* xr = x + b * HID;
    const float* wr = w + j * HID;
    float s = 0.f;
    for (int k = lane; k < HID; k += 32) s += xr[k] * wr[k];
#pragma unroll
    for (int o = 16; o > 0; o >>= 1) s += __shfl_xor_sync(0xffffffffu, s, o);
    if (lane == 0) lg[j] = s + bias[j];
    __syncthreads();
    if (tid == 0) {
        float m = lg[0];
#pragma unroll
        for (int t = 1; t < 10; t++) m = fmaxf(m, lg[t]);
        float se = 0.f;
#pragma unroll
        for (int t = 0; t < 10; t++) se += expf(lg[t] - m);
        lse = m + logf(se);
    }
    __syncthreads();
    if (tid < 10) out[b * 10 + tid] = lg[tid] - lse;
}

// ---------------------------------------------------------------------------
extern "C" void kernel_launch(void* const* d_in, const int* in_sizes, int n_in,
                              void* d_out, int out_size) {
    const float* img = (const float*)d_in[0];
    const float* qst = (const float*)d_in[1];
    const float* cw[4] = {(const float*)d_in[2], (const float*)d_in[6], (const float*)d_in[10], (const float*)d_in[14]};
    const float* cb[4] = {(const float*)d_in[3], (const float*)d_in[7], (const float*)d_in[11], (const float*)d_in[15]};
    const float* bg[4] = {(const float*)d_in[4], (const float*)d_in[8], (const float*)d_in[12], (const float*)d_in[16]};
    const float* bb[4] = {(const float*)d_in[5], (const float*)d_in[9], (const float*)d_in[13], (const float*)d_in[17]};
    const float* g1w = (const float*)d_in[18]; const float* g1b = (const float*)d_in[19];
    const float* g2w = (const float*)d_in[20]; const float* g2b = (const float*)d_in[21];
    const float* g3w = (const float*)d_in[22]; const float* g3b = (const float*)d_in[23];
    const float* g4w = (const float*)d_in[24]; const float* g4b = (const float*)d_in[25];
    const float* f1w = (const float*)d_in[26]; const float* f1b = (const float*)d_in[27];
    const float* fc2w = (const float*)d_in[28]; const float* fc2b = (const float*)d_in[29];
    const float* fc3w = (const float*)d_in[30]; const float* fc3b = (const float*)d_in[31];
    float* out = (float*)d_out;

    float *buf1, *buf2, *buf3, *buf4, *obj, *A, *B, *Cb, *xg, *xf1, *xf2, *stats;
    __half *wh, *hA, *hB;
    double *psum, *psq;
    cudaGetSymbolAddress((void**)&buf1, g_buf1);
    cudaGetSymbolAddress((void**)&buf2, g_buf2);
    cudaGetSymbolAddress((void**)&buf3, g_buf3);
    cudaGetSymbolAddress((void**)&buf4, g_buf4);
    cudaGetSymbolAddress((void**)&obj, g_obj);
    cudaGetSymbolAddress((void**)&A, g_A);
    cudaGetSymbolAddress((void**)&B, g_B);
    cudaGetSymbolAddress((void**)&Cb, g_Cb);
    cudaGetSymbolAddress((void**)&xg, g_xg);
    cudaGetSymbolAddress((void**)&xf1, g_xf1);
    cudaGetSymbolAddress((void**)&xf2, g_xf2);
    cudaGetSymbolAddress((void**)&stats, g_stats);
    cudaGetSymbolAddress((void**)&psum, g_psum);
    cudaGetSymbolAddress((void**)&psq, g_psq);
    cudaGetSymbolAddress((void**)&wh, g_wh);
    cudaGetSymbolAddress((void**)&hA, g_hbufA);
    cudaGetSymbolAddress((void**)&hB, g_hbufB);

    cudaFuncSetAttribute(gmlp_l2, cudaFuncAttributeMaxDynamicSharedMemorySize, GL2_SMEM);

    // ---- zero accumulators + weight prep ----
    zerod_k<<<1, 128>>>(psum, 96);
    zerod_k<<<1, 128>>>(psq, 96);
    zerof_k<<<512, 256>>>(xg, BATCH * HID);
    whalf_all<<<768, 256>>>(g2w, g3w, g4w, wh);

    // ---- conv stack (fused BN, pixel-blocked) ----
    conv1_f4<<<800, 256>>>(img, cw[0], cb[0], buf1, psum, psq);
    bn_final_f<<<1, 32>>>(psum, psq, 512.0 * 1600.0, bg[0], stats);
    conv24_fP<40, 20, 4><<<200, 256>>>(buf1, cw[1], cb[1], stats, bb[0], buf2, psum + 24, psq + 24);
    bn_final_f<<<1, 32>>>(psum + 24, psq + 24, 512.0 * 400.0, bg[1], stats + 48);
    conv24_fP<20, 10, 2><<<100, 256>>>(buf2, cw[2], cb[2], stats + 48, bb[1], buf3, psum + 48, psq + 48);
    bn_final_f<<<1, 32>>>(psum + 48, psq + 48, 512.0 * 100.0, bg[2], stats + 96);
    conv24_fP<10, 5, 1><<<50, 256>>>(buf3, cw[3], cb[3], stats + 96, bb[2], buf4, psum + 72, psq + 72);
    bn_final_f<<<1, 32>>>(psum + 72, psq + 72, 512.0 * 25.0, bg[3], stats + 144);

    // ---- objects + decomposed g1 ----
    obj_f<<<(BATCH * OBJ * 26 + 255) / 256, 256>>>(buf4, stats + 144, bb[3], obj);
    ab_k<<<BATCH * OBJ, 256>>>(obj, g1w, A, B);
    cb_k<<<BATCH, 256>>>(qst, g1w, g1b, Cb);

    // ---- g2 (fused h1) -> g3 -> g4 (fused pairsum), fp16 MMA path ----
    dim3 ggrid(2, BATCH * OBJ * OBJ / 128);  // (2, 2500)
    gmlp_l2<<<ggrid, 256, GL2_SMEM>>>(A, B, Cb, wh, g2b, hB);
    gmlp_l3<<<ggrid, 256>>>(hB, wh + HID * HID, g3b, hA);
    gmlp_l4<<<ggrid, 256>>>(hA, wh + 2 * HID * HID, g4b, xg);

    // ---- f-MLP (fp32) ----
    dim3 fgrid(256 / 64, BATCH / 128);
    sgemm256<<<fgrid, 256>>>(xg, f1w, f1b, xf1, 1);
    sgemm256<<<fgrid, 256>>>(xf1, fc2w, fc2b, xf2, 1);
    fc3_k<<<BATCH, 320>>>(xf2, fc3w, fc3b, out);
}

// round 15
// speedup vs baseline: 1.5743x; 1.0604x over previous
#include <cuda_runtime.h>
#include <cuda_bf16.h>
#include <cuda_fp16.h>
#include <math.h>
#include <stdint.h>

#define BATCH 512
#define FS 24
#define QDIM 11
#define HID 256
#define OBJ 25
#define EPS 1e-5f

// -------------------- scratch (device globals; no allocation) --------------
__device__ __align__(16) float g_buf1[BATCH * FS * 40 * 40];
__device__ __align__(16) float g_buf2[BATCH * FS * 20 * 20];
__device__ __align__(16) float g_buf3[BATCH * FS * 10 * 10];
__device__ __align__(16) float g_buf4[BATCH * FS * 5 * 5];
__device__ float g_obj[BATCH * OBJ * 26];
__device__ __align__(16) float g_A[BATCH * OBJ * HID];
__device__ __align__(16) float g_B[BATCH * OBJ * HID];
__device__ __align__(16) float g_Cb[BATCH * HID];
__device__ __align__(16) __half g_wh[3][HID * HID];   // fp16 g weights
__device__ float g_xg[BATCH * HID];
__device__ float g_xf1[BATCH * HID];
__device__ float g_xf2[BATCH * HID];
__device__ double g_psum[4 * 24];
__device__ double g_psq[4 * 24];
__device__ float g_stats[4 * 48];
// intermediate activations in fp16 (g2 out / g3 out)
__device__ __align__(16) __half g_hbufA[BATCH * OBJ * OBJ * HID];
__device__ __align__(16) __half g_hbufB[BATCH * OBJ * OBJ * HID];

// ===================== helpers ==============================================
__device__ __forceinline__ uint32_t smem_u32(const void* p) {
    uint32_t a;
    asm("{ .reg .u64 tmp; cvta.to.shared.u64 tmp, %1; cvt.u32.u64 %0, tmp; }"
        : "=r"(a) : "l"(p));
    return a;
}

#define CP_ASYNC16(dst, src) \
    asm volatile("cp.async.cg.shared.global [%0], [%1], 16;" :: "r"(dst), "l"(src))
#define CP_COMMIT() asm volatile("cp.async.commit_group;")
#define CP_WAIT1() asm volatile("cp.async.wait_group 1;")
#define CP_WAIT0() asm volatile("cp.async.wait_group 0;")

__device__ __forceinline__ void ldsm_x4(uint32_t& r0, uint32_t& r1, uint32_t& r2,
                                        uint32_t& r3, uint32_t addr) {
    asm volatile("ldmatrix.sync.aligned.m8n8.x4.shared.b16 {%0,%1,%2,%3}, [%4];"
        : "=r"(r0), "=r"(r1), "=r"(r2), "=r"(r3) : "r"(addr));
}

// f16 MMA, fp32 accum: D(16x8) += A(16x16,row) * B(16x8,col)
__device__ __forceinline__ void mma_f16(float* d, const uint32_t* a, const uint32_t* b) {
    asm volatile(
        "mma.sync.aligned.m16n8k16.row.col.f32.f16.f16.f32 "
        "{%0,%1,%2,%3}, {%4,%5,%6,%7}, {%8,%9}, {%0,%1,%2,%3};"
        : "+f"(d[0]), "+f"(d[1]), "+f"(d[2]), "+f"(d[3])
        : "r"(a[0]), "r"(a[1]), "r"(a[2]), "r"(a[3]), "r"(b[0]), "r"(b[1]));
}

__device__ __forceinline__ uint32_t pack_h2(float a, float b) {
    __half2 h = __floats2half2_rn(a, b);
    return *(uint32_t*)&h;
}

// -------------------- zero / prep kernels -----------------------------------
__global__ void zerof_k(float* p, int n) {
    int i = blockIdx.x * blockDim.x + threadIdx.x;
    if (i < n) p[i] = 0.f;
}
__global__ void zerod_k(double* p, int n) {
    int i = blockIdx.x * blockDim.x + threadIdx.x;
    if (i < n) p[i] = 0.0;
}
__global__ void whalf_all(const float* __restrict__ w2, const float* __restrict__ w3,
                          const float* __restrict__ w4, __half* __restrict__ o) {
    int idx = blockIdx.x * blockDim.x + threadIdx.x;
    if (idx >= 3 * HID * HID) return;
    int sel = idx >> 16;
    int off = idx & 0xFFFF;
    const float* src = (sel == 0) ? w2 : (sel == 1) ? w3 : w4;
    o[idx] = __float2half_rn(src[off]);
}

// -------------------- conv1: Cin=3, 80->40, P=4 pixels/thread ---------------
__global__ void __launch_bounds__(256)
conv1_f4(const float* __restrict__ in, const float* __restrict__ w,
         const float* __restrict__ bias, float* __restrict__ out,
         double* __restrict__ psum, double* __restrict__ psq) {
    __shared__ float ws[648];
    __shared__ float bs[24];
    __shared__ float srs[8][24];
    __shared__ float srq[8][24];
    int tid = threadIdx.x;
    for (int i = tid; i < 648; i += 256) ws[i] = w[i];
    if (tid < 24) bs[tid] = bias[tid];
    __syncthreads();

    int idx = blockIdx.x * 256 + tid;
    int chunk = idx % 400;
    int b = idx / 400;
    int oy = chunk / 10;
    int ox0 = (chunk % 10) * 4;
    int iy0 = 2 * oy - 1;
    int ix0 = 2 * ox0 - 1;

    float acc[24][4];
#pragma unroll
    for (int c = 0; c < 24; c++)
#pragma unroll
        for (int p = 0; p < 4; p++) acc[c][p] = bs[c];

    const float* ip = in + (size_t)b * 3 * 6400;
#pragma unroll
    for (int ci = 0; ci < 3; ci++) {
        const float* ic = ip + ci * 6400;
#pragma unroll
        for (int ky = 0; ky < 3; ky++) {
            int iy = iy0 + ky;
            bool vy = (unsigned)iy < 80u;
            float iv[9];
#pragma unroll
            for (int j = 0; j < 9; j++) {
                int ix = ix0 + j;
                iv[j] = (vy && (unsigned)ix < 80u) ? ic[iy * 80 + ix] : 0.f;
            }
#pragma unroll
            for (int kx = 0; kx < 3; kx++) {
                int t = ci * 9 + ky * 3 + kx;
#pragma unroll
                for (int co = 0; co < 24; co++) {
                    float wv = ws[co * 27 + t];
#pragma unroll
                    for (int p = 0; p < 4; p++)
                        acc[co][p] = fmaf(iv[2 * p + kx], wv, acc[co][p]);
                }
            }
        }
    }

    int wid = tid >> 5, lane = tid & 31;
    float* op = out + (size_t)b * 24 * 1600 + oy * 40 + ox0;
#pragma unroll
    for (int co = 0; co < 24; co++) {
        float4 y4;
        float* yp = (float*)&y4;
        float s = 0.f, q = 0.f;
#pragma unroll
        for (int p = 0; p < 4; p++) {
            float y = fmaxf(acc[co][p], 0.f);
            yp[p] = y;
            s += y; q += y * y;
        }
        *(float4*)(op + co * 1600) = y4;
#pragma unroll
        for (int off = 16; off > 0; off >>= 1) {
            s += __shfl_xor_sync(0xffffffffu, s, off);
            q += __shfl_xor_sync(0xffffffffu, q, off);
        }
        if (lane == 0) { srs[wid][co] = s; srq[wid][co] = q; }
    }
    __syncthreads();
    if (tid < 24) {
        double S = 0.0, Q = 0.0;
#pragma unroll
        for (int wk = 0; wk < 8; wk++) { S += srs[wk][tid]; Q += srq[wk][tid]; }
        atomicAdd(&psum[tid], S);
        atomicAdd(&psq[tid], Q);
    }
}

// -------------------- convN: Cin=24, P pixels/thread, BN fused --------------
template <int HIN, int HOUT, int P>
__global__ void __launch_bounds__(256)
conv24_fP(const float* __restrict__ in, const float* __restrict__ w,
          const float* __restrict__ bias,
          const float* __restrict__ statsPrev, const float* __restrict__ betaPrev,
          float* __restrict__ out,
          double* __restrict__ psum, double* __restrict__ psq) {
    __shared__ float ws[5184];
    __shared__ float bs[24];
    __shared__ float ab[24];
    __shared__ float dd[24];
    __shared__ float srs[8][24];
    __shared__ float srq[8][24];
    int tid = threadIdx.x;
    for (int i = tid; i < 5184; i += 256) ws[i] = w[i];
    if (tid < 24) {
        bs[tid] = bias[tid];
        float sc = statsPrev[24 + tid];
        ab[tid] = sc;
        dd[tid] = betaPrev[tid] - statsPrev[tid] * sc;
    }
    __syncthreads();

    const int PIX = HOUT * HOUT;
    const int CHW = HOUT / P;
    int idx = blockIdx.x * 256 + tid;
    int chunk = idx % (PIX / P);
    int b = idx / (PIX / P);
    int oy = chunk / CHW;
    int ox0 = (chunk % CHW) * P;
    int iy0 = 2 * oy - 1;
    int ix0 = 2 * ox0 - 1;

    float acc[24][P];
#pragma unroll
    for (int c = 0; c < 24; c++)
#pragma unroll
        for (int p = 0; p < P; p++) acc[c][p] = bs[c];

    const float* ip = in + (size_t)b * 24 * HIN * HIN;
    for (int ci = 0; ci < 24; ci++) {
        float ai = ab[ci], di = dd[ci];
        const float* ic = ip + ci * HIN * HIN;
#pragma unroll
        for (int ky = 0; ky < 3; ky++) {
            int iy = iy0 + ky;
            bool vy = (unsigned)iy < (unsigned)HIN;
            float iv[2 * P + 1];
#pragma unroll
            for (int j = 0; j < 2 * P + 1; j++) {
                int ix = ix0 + j;
                iv[j] = (vy && (unsigned)ix < (unsigned)HIN)
                            ? fmaf(ic[iy * HIN + ix], ai, di) : 0.f;
            }
#pragma unroll
            for (int kx = 0; kx < 3; kx++) {
                int t = ci * 9 + ky * 3 + kx;
#pragma unroll
                for (int co = 0; co < 24; co++) {
                    float wv = ws[co * 216 + t];
#pragma unroll
                    for (int p = 0; p < P; p++)
                        acc[co][p] = fmaf(iv[2 * p + kx], wv, acc[co][p]);
                }
            }
        }
    }

    int wid = tid >> 5, lane = tid & 31;
    float* op = out + (size_t)b * 24 * PIX + oy * HOUT + ox0;
#pragma unroll
    for (int co = 0; co < 24; co++) {
        float yv[P];
        float s = 0.f, q = 0.f;
#pragma unroll
        for (int p = 0; p < P; p++) {
            float y = fmaxf(acc[co][p], 0.f);
            yv[p] = y;
            s += y; q += y * y;
        }
        if (P == 4) {
            float4 y4 = {yv[0], yv[1], yv[2], yv[3]};
            *(float4*)(op + co * PIX) = y4;
        } else if (P == 2) {
            float2 y2 = {yv[0], yv[1]};
            *(float2*)(op + co * PIX) = y2;
        } else {
#pragma unroll
            for (int p = 0; p < P; p++) op[co * PIX + p] = yv[p];
        }
#pragma unroll
        for (int off = 16; off > 0; off >>= 1) {
            s += __shfl_xor_sync(0xffffffffu, s, off);
            q += __shfl_xor_sync(0xffffffffu, q, off);
        }
        if (lane == 0) { srs[wid][co] = s; srq[wid][co] = q; }
    }
    __syncthreads();
    if (tid < 24) {
        double S = 0.0, Q = 0.0;
#pragma unroll
        for (int wk = 0; wk < 8; wk++) { S += srs[wk][tid]; Q += srq[wk][tid]; }
        atomicAdd(&psum[tid], S);
        atomicAdd(&psq[tid], Q);
    }
}

// -------------------- finalize BN stats -------------------------------------
__global__ void bn_final_f(const double* __restrict__ psum, const double* __restrict__ psq,
                           double N, const float* __restrict__ gamma,
                           float* __restrict__ stats) {
    int c = threadIdx.x;
    if (c >= 24) return;
    double mean = psum[c] / N;
    double var = psq[c] / N - mean * mean;
    stats[c] = (float)mean;
    stats[24 + c] = gamma[c] * rsqrtf((float)var + EPS);
}

// -------------------- object extraction (applies BN4) -----------------------
__global__ void obj_f(const float* __restrict__ x4, const float* __restrict__ stats4,
                      const float* __restrict__ beta4, float* __restrict__ obj) {
    int idx = blockIdx.x * blockDim.x + threadIdx.x;
    const int total = BATCH * OBJ * 26;
    if (idx >= total) return;
    int f = idx % 26; int t = idx / 26;
    int o = t % OBJ; int b = t / OBJ;
    float v;
    if (f < FS) {
        float y = x4[((size_t)b * FS + f) * OBJ + o];
        v = (y - stats4[f]) * stats4[24 + f] + beta4[f];
    } else if (f == FS) v = ((float)(o / 5) - 2.f) * 0.5f;
    else v = ((float)(o % 5) - 2.f) * 0.5f;
    obj[idx] = v;
}

// -------------------- g1 decomposition --------------------------------------
__global__ void ab_k(const float* __restrict__ obj, const float* __restrict__ g1w,
                     float* __restrict__ A, float* __restrict__ B) {
    int m = blockIdx.x;
    int n = threadIdx.x;
    __shared__ float os[26];
    if (n < 26) os[n] = obj[m * 26 + n];
    __syncthreads();
    const float* wr = g1w + n * 63;
    float sa = 0.f, sb = 0.f;
#pragma unroll
    for (int f = 0; f < 26; f++) {
        float o = os[f];
        sa += o * __ldg(&wr[f]);
        sb += o * __ldg(&wr[26 + f]);
    }
    A[m * HID + n] = sa;
    B[m * HID + n] = sb;
}

__global__ void cb_k(const float* __restrict__ qst, const float* __restrict__ g1w,
                     const float* __restrict__ g1b, float* __restrict__ Cb) {
    int b = blockIdx.x;
    int n = threadIdx.x;
    __shared__ float qs[QDIM];
    if (n < QDIM) qs[n] = qst[n * BATCH + b];
    __syncthreads();
    const float* wr = g1w + n * 63 + 52;
    float s = g1b[n];
#pragma unroll
    for (int d = 0; d < QDIM; d++) s += qs[d] * __ldg(&wr[d]);
    Cb[b * HID + n] = s;
}

// ==================== fp16 MMA g-path (ldmatrix, K-chunk 32) ================
#define HPAD16 264               // h1 smem row pad (halves); 528B rows
#define KCH 32                   // K elements per streamed chunk
#define SPAD 40                  // streamed buffer row pad (halves); 80B rows
#define SBUF (128 * SPAD)        // halves per buffer

// A fragment via ldmatrix.x4: lane -> (tile t = lane>>3, row r = lane&7)
//   row = rowBase + (t&1)*8 + r ; kof = (t>>1)*8
// B fragment pair via ldmatrix.x4: lanes map two n-tiles x two k-tiles:
//   nrow = nBase + ((lane>>4)&1)*8 + (lane&7) ; kof = ((lane>>3)&1)*8

// ---- g2: fused h1 build (fp16 smem) + f16 MMA; grid (2, 2500), 256 thr ----
#define GL2_SMEM (128 * HPAD16 * 2 + 2 * SBUF * 2 + 128 * 4)

__global__ void __launch_bounds__(256, 2)
gmlp_l2(const float* __restrict__ Ag, const float* __restrict__ Bg,
        const float* __restrict__ Cg, const __half* __restrict__ W,
        const float* __restrict__ bias, __half* __restrict__ Y) {
    extern __shared__ char smraw[];
    __half* h1s = (__half*)smraw;                       // [128 * HPAD16]
    __half* Ws = (__half*)(smraw + 128 * HPAD16 * 2);   // [2][SBUF]
    float* biasS = (float*)(smraw + 128 * HPAD16 * 2 + 2 * SBUF * 2);

    const int tid = threadIdx.x;
    const int wid = tid >> 5;
    const int lane = tid & 31;
    const int wm = wid >> 2;
    const int wn = wid & 3;
    const int n0 = blockIdx.x * 128;
    const size_t mBase = (size_t)blockIdx.y * 128;

    if (tid < 128) biasS[tid] = __ldg(&bias[n0 + tid]);

    const int lr = tid >> 1;
    const int lh = tid & 1;

    // ---- build h1 tile (fp16) ----
    {
        int r = (int)mBase + lr;
        int b = r / 625;
        int rem = r - b * 625;
        int ko = rem / 25;
        int ii = rem - ko * 25;
        const float4* pA = (const float4*)(Ag + (b * 25 + ii) * 256);
        const float4* pB = (const float4*)(Bg + (b * 25 + ko) * 256);
        const float4* pC = (const float4*)(Cg + b * 256);
        __half* hrow = h1s + lr * HPAD16 + lh * 128;
        int cbase = lh * 32;
#pragma unroll 4
        for (int j = 0; j < 16; j++) {
            float4 a = __ldg(pA + cbase + 2 * j), a1 = __ldg(pA + cbase + 2 * j + 1);
            float4 b4 = __ldg(pB + cbase + 2 * j), b1 = __ldg(pB + cbase + 2 * j + 1);
            float4 c = __ldg(pC + cbase + 2 * j), c1 = __ldg(pC + cbase + 2 * j + 1);
            uint4 o;
            o.x = pack_h2(fmaxf(a.x + b4.x + c.x, 0.f), fmaxf(a.y + b4.y + c.y, 0.f));
            o.y = pack_h2(fmaxf(a.z + b4.z + c.z, 0.f), fmaxf(a.w + b4.w + c.w, 0.f));
            o.z = pack_h2(fmaxf(a1.x + b1.x + c1.x, 0.f), fmaxf(a1.y + b1.y + c1.y, 0.f));
            o.w = pack_h2(fmaxf(a1.z + b1.z + c1.z, 0.f), fmaxf(a1.w + b1.w + c1.w, 0.f));
            *(uint4*)(hrow + j * 8) = o;
        }
    }

    const __half* Wt = W + (size_t)n0 * 256;
    const uint32_t hRaw = smem_u32(h1s);
    const uint32_t wRaw = smem_u32(Ws);
    auto issue = [&](int buf, int k0) {
        uint32_t bd = wRaw + buf * (SBUF * 2) + lr * (SPAD * 2) + lh * 32;
        const __half* s = Wt + lr * 256 + k0 + lh * 16;
        CP_ASYNC16(bd, s);
        CP_ASYNC16(bd + 16, s + 8);
    };

    float acc[4][4][4];
#pragma unroll
    for (int i = 0; i < 4; i++)
#pragma unroll
        for (int j = 0; j < 4; j++)
#pragma unroll
            for (int r = 0; r < 4; r++) acc[i][j][r] = 0.f;

    issue(0, 0);
    CP_COMMIT();
    __syncthreads();   // h1s visible

    const int lq = lane >> 2;
    const int lk = lane & 3;
    const int at = lane >> 3, ar = lane & 7;          // A-frag lane mapping
    const int aRowOff = (at & 1) * 8 + ar;
    const int aKOff = (at >> 1) * 8;
    const int bRowOff = ((lane >> 4) & 1) * 8 + (lane & 7);
    const int bKOff = ((lane >> 3) & 1) * 8;

#pragma unroll 1
    for (int kt = 0; kt < 8; kt++) {                  // 8 chunks of K=32
        int buf = kt & 1;
        if (kt < 7) { issue(buf ^ 1, (kt + 1) * KCH); CP_COMMIT(); CP_WAIT1(); }
        else CP_WAIT0();
        __syncthreads();

#pragma unroll
        for (int ks = 0; ks < 2; ks++) {
            int kk = kt * KCH + ks * 16;
            uint32_t af[4][4];
#pragma unroll
            for (int mf = 0; mf < 4; mf++) {
                uint32_t addr = hRaw +
                    ((wm * 64 + mf * 16 + aRowOff) * HPAD16 + kk + aKOff) * 2;
                ldsm_x4(af[mf][0], af[mf][1], af[mf][2], af[mf][3], addr);
            }
            uint32_t bfr[4][2];
#pragma unroll
            for (int nfp = 0; nfp < 2; nfp++) {
                uint32_t addr = wRaw + buf * (SBUF * 2) +
                    ((wn * 32 + nfp * 16 + bRowOff) * SPAD + ks * 16 + bKOff) * 2;
                ldsm_x4(bfr[2 * nfp][0], bfr[2 * nfp][1],
                        bfr[2 * nfp + 1][0], bfr[2 * nfp + 1][1], addr);
            }
#pragma unroll
            for (int mf = 0; mf < 4; mf++)
#pragma unroll
                for (int nf = 0; nf < 4; nf++)
                    mma_f16(acc[mf][nf], af[mf], bfr[nf]);
        }
        __syncthreads();
    }

#pragma unroll
    for (int mf = 0; mf < 4; mf++) {
        size_t r0 = mBase + wm * 64 + mf * 16 + lq;
        __half* y0 = Y + r0 * 256 + n0;
        __half* y1 = y0 + 8 * 256;
#pragma unroll
        for (int nf = 0; nf < 4; nf++) {
            int col = wn * 32 + nf * 8 + 2 * lk;
            float b0 = biasS[col], b1 = biasS[col + 1];
            uint32_t p0 = pack_h2(fmaxf(acc[mf][nf][0] + b0, 0.f),
                                  fmaxf(acc[mf][nf][1] + b1, 0.f));
            uint32_t p1 = pack_h2(fmaxf(acc[mf][nf][2] + b0, 0.f),
                                  fmaxf(acc[mf][nf][3] + b1, 0.f));
            *(uint32_t*)(y0 + col) = p0;
            *(uint32_t*)(y1 + col) = p1;
        }
    }
}

// ---- g3: fp16 in/out, f16 MMA + ldmatrix, grid (2, 2500) ----
__global__ void __launch_bounds__(256, 2)
gmlp_l3(const __half* __restrict__ X, const __half* __restrict__ W,
        const float* __restrict__ bias, __half* __restrict__ Y) {
    __shared__ __align__(16) __half As[2][SBUF];
    __shared__ __align__(16) __half Bs[2][SBUF];
    __shared__ float biasS[128];

    const int tid = threadIdx.x;
    const int wid = tid >> 5;
    const int lane = tid & 31;
    const int wm = wid >> 2;
    const int wn = wid & 3;
    const int n0 = blockIdx.x * 128;
    const size_t mBase = (size_t)blockIdx.y * 128;

    if (tid < 128) biasS[tid] = __ldg(&bias[n0 + tid]);

    const uint32_t aRaw = smem_u32(As);
    const uint32_t bRaw = smem_u32(Bs);
    const __half* Xt = X + mBase * 256;
    const __half* Wt = W + (size_t)n0 * 256;

    const int lr = tid >> 1;
    const int lh = tid & 1;

    auto issue = [&](int buf, int k0) {
        uint32_t ad = aRaw + buf * (SBUF * 2) + lr * (SPAD * 2) + lh * 32;
        uint32_t bd = bRaw + buf * (SBUF * 2) + lr * (SPAD * 2) + lh * 32;
        const __half* xs = Xt + lr * 256 + k0 + lh * 16;
        const __half* wsrc = Wt + lr * 256 + k0 + lh * 16;
        CP_ASYNC16(ad, xs);
        CP_ASYNC16(ad + 16, xs + 8);
        CP_ASYNC16(bd, wsrc);
        CP_ASYNC16(bd + 16, wsrc + 8);
    };

    float acc[4][4][4];
#pragma unroll
    for (int i = 0; i < 4; i++)
#pragma unroll
        for (int j = 0; j < 4; j++)
#pragma unroll
            for (int r = 0; r < 4; r++) acc[i][j][r] = 0.f;

    issue(0, 0);
    CP_COMMIT();

    const int lq = lane >> 2;
    const int lk = lane & 3;
    const int at = lane >> 3, ar = lane & 7;
    const int aRowOff = (at & 1) * 8 + ar;
    const int aKOff = (at >> 1) * 8;
    const int bRowOff = ((lane >> 4) & 1) * 8 + (lane & 7);
    const int bKOff = ((lane >> 3) & 1) * 8;

#pragma unroll 1
    for (int kt = 0; kt < 8; kt++) {
        int buf = kt & 1;
        if (kt < 7) { issue(buf ^ 1, (kt + 1) * KCH); CP_COMMIT(); CP_WAIT1(); }
        else CP_WAIT0();
        __syncthreads();

#pragma unroll
        for (int ks = 0; ks < 2; ks++) {
            uint32_t af[4][4];
#pragma unroll
            for (int mf = 0; mf < 4; mf++) {
                uint32_t addr = aRaw + buf * (SBUF * 2) +
                    ((wm * 64 + mf * 16 + aRowOff) * SPAD + ks * 16 + aKOff) * 2;
                ldsm_x4(af[mf][0], af[mf][1], af[mf][2], af[mf][3], addr);
            }
            uint32_t bfr[4][2];
#pragma unroll
            for (int nfp = 0; nfp < 2; nfp++) {
                uint32_t addr = bRaw + buf * (SBUF * 2) +
                    ((wn * 32 + nfp * 16 + bRowOff) * SPAD + ks * 16 + bKOff) * 2;
                ldsm_x4(bfr[2 * nfp][0], bfr[2 * nfp][1],
                        bfr[2 * nfp + 1][0], bfr[2 * nfp + 1][1], addr);
            }
#pragma unroll
            for (int mf = 0; mf < 4; mf++)
#pragma unroll
                for (int nf = 0; nf < 4; nf++)
                    mma_f16(acc[mf][nf], af[mf], bfr[nf]);
        }
        __syncthreads();
    }

#pragma unroll
    for (int mf = 0; mf < 4; mf++) {
        size_t r0 = mBase + wm * 64 + mf * 16 + lq;
        __half* y0 = Y + r0 * 256 + n0;
        __half* y1 = y0 + 8 * 256;
#pragma unroll
        for (int nf = 0; nf < 4; nf++) {
            int col = wn * 32 + nf * 8 + 2 * lk;
            float b0 = biasS[col], b1 = biasS[col + 1];
            uint32_t p0 = pack_h2(fmaxf(acc[mf][nf][0] + b0, 0.f),
                                  fmaxf(acc[mf][nf][1] + b1, 0.f));
            uint32_t p1 = pack_h2(fmaxf(acc[mf][nf][2] + b0, 0.f),
                                  fmaxf(acc[mf][nf][3] + b1, 0.f));
            *(uint32_t*)(y0 + col) = p0;
            *(uint32_t*)(y1 + col) = p1;
        }
    }
}

// ---- g4: fp16 in, f16 MMA + ldmatrix + fused pairsum (atomic) ----
__global__ void __launch_bounds__(256, 2)
gmlp_l4(const __half* __restrict__ X, const __half* __restrict__ W,
        const float* __restrict__ bias, float* __restrict__ xg) {
    __shared__ __align__(16) __half As[2][SBUF];
    __shared__ __align__(16) __half Bs[2][SBUF];
    __shared__ float biasS[128];

    const int tid = threadIdx.x;
    const int wid = tid >> 5;
    const int lane = tid & 31;
    const int wm = wid >> 2;
    const int wn = wid & 3;
    const int n0 = blockIdx.x * 128;
    const size_t mBase = (size_t)blockIdx.y * 128;

    if (tid < 128) biasS[tid] = __ldg(&bias[n0 + tid]);

    const uint32_t aRaw = smem_u32(As);
    const uint32_t bRaw = smem_u32(Bs);
    const __half* Xt = X + mBase * 256;
    const __half* Wt = W + (size_t)n0 * 256;

    const int lr = tid >> 1;
    const int lh = tid & 1;

    auto issue = [&](int buf, int k0) {
        uint32_t ad = aRaw + buf * (SBUF * 2) + lr * (SPAD * 2) + lh * 32;
        uint32_t bd = bRaw + buf * (SBUF * 2) + lr * (SPAD * 2) + lh * 32;
        const __half* xs = Xt + lr * 256 + k0 + lh * 16;
        const __half* wsrc = Wt + lr * 256 + k0 + lh * 16;
        CP_ASYNC16(ad, xs);
        CP_ASYNC16(ad + 16, xs + 8);
        CP_ASYNC16(bd, wsrc);
        CP_ASYNC16(bd + 16, wsrc + 8);
    };

    float acc[4][4][4];
#pragma unroll
    for (int i = 0; i < 4; i++)
#pragma unroll
        for (int j = 0; j < 4; j++)
#pragma unroll
            for (int r = 0; r < 4; r++) acc[i][j][r] = 0.f;

    issue(0, 0);
    CP_COMMIT();

    const int lq = lane >> 2;
    const int lk = lane & 3;
    const int at = lane >> 3, ar = lane & 7;
    const int aRowOff = (at & 1) * 8 + ar;
    const int aKOff = (at >> 1) * 8;
    const int bRowOff = ((lane >> 4) & 1) * 8 + (lane & 7);
    const int bKOff = ((lane >> 3) & 1) * 8;

#pragma unroll 1
    for (int kt = 0; kt < 8; kt++) {
        int buf = kt & 1;
        if (kt < 7) { issue(buf ^ 1, (kt + 1) * KCH); CP_COMMIT(); CP_WAIT1(); }
        else CP_WAIT0();
        __syncthreads();

#pragma unroll
        for (int ks = 0; ks < 2; ks++) {
            uint32_t af[4][4];
#pragma unroll
            for (int mf = 0; mf < 4; mf++) {
                uint32_t addr = aRaw + buf * (SBUF * 2) +
                    ((wm * 64 + mf * 16 + aRowOff) * SPAD + ks * 16 + aKOff) * 2;
                ldsm_x4(af[mf][0], af[mf][1], af[mf][2], af[mf][3], addr);
            }
            uint32_t bfr[4][2];
#pragma unroll
            for (int nfp = 0; nfp < 2; nfp++) {
                uint32_t addr = bRaw + buf * (SBUF * 2) +
                    ((wn * 32 + nfp * 16 + bRowOff) * SPAD + ks * 16 + bKOff) * 2;
                ldsm_x4(bfr[2 * nfp][0], bfr[2 * nfp][1],
                        bfr[2 * nfp + 1][0], bfr[2 * nfp + 1][1], addr);
            }
#pragma unroll
            for (int mf = 0; mf < 4; mf++)
#pragma unroll
                for (int nf = 0; nf < 4; nf++)
                    mma_f16(acc[mf][nf], af[mf], bfr[nf]);
        }
        __syncthreads();
    }

    // ---- fused pairsum epilogue ----
    int b0 = (int)(mBase / 625);
    int split = (b0 + 1) * 625;
    bool hasSplit = split < (int)mBase + 128;

    float cs0[4][2], cs1[4][2];
#pragma unroll
    for (int nf = 0; nf < 4; nf++) { cs0[nf][0] = cs0[nf][1] = 0.f; cs1[nf][0] = cs1[nf][1] = 0.f; }

#pragma unroll
    for (int mf = 0; mf < 4; mf++) {
        int rA = (int)mBase + wm * 64 + mf * 16 + lq;
        int rB = rA + 8;
        bool pA = rA >= split;
        bool pB = rB >= split;
#pragma unroll
        for (int nf = 0; nf < 4; nf++) {
            int col = wn * 32 + nf * 8 + 2 * lk;
            float bb0 = biasS[col], bb1 = biasS[col + 1];
            float v0 = fmaxf(acc[mf][nf][0] + bb0, 0.f);
            float v1 = fmaxf(acc[mf][nf][1] + bb1, 0.f);
            float v2 = fmaxf(acc[mf][nf][2] + bb0, 0.f);
            float v3 = fmaxf(acc[mf][nf][3] + bb1, 0.f);
            if (pA) { cs1[nf][0] += v0; cs1[nf][1] += v1; }
            else    { cs0[nf][0] += v0; cs0[nf][1] += v1; }
            if (pB) { cs1[nf][0] += v2; cs1[nf][1] += v3; }
            else    { cs0[nf][0] += v2; cs0[nf][1] += v3; }
        }
    }
#pragma unroll
    for (int off = 4; off <= 16; off <<= 1) {
#pragma unroll
        for (int nf = 0; nf < 4; nf++) {
            cs0[nf][0] += __shfl_xor_sync(0xffffffffu, cs0[nf][0], off);
            cs0[nf][1] += __shfl_xor_sync(0xffffffffu, cs0[nf][1], off);
            cs1[nf][0] += __shfl_xor_sync(0xffffffffu, cs1[nf][0], off);
            cs1[nf][1] += __shfl_xor_sync(0xffffffffu, cs1[nf][1], off);
        }
    }
    if (lq == 0) {
#pragma unroll
        for (int nf = 0; nf < 4; nf++) {
#pragma unroll
            for (int p = 0; p < 2; p++) {
                int col = n0 + wn * 32 + nf * 8 + 2 * lk + p;
                atomicAdd(&xg[b0 * 256 + col], cs0[nf][p]);
                if (hasSplit) atomicAdd(&xg[(b0 + 1) * 256 + col], cs1[nf][p]);
            }
        }
    }
}

// -------------------- fp32 SGEMM (small f-layers) ---------------------------
__global__ void sgemm256(const float* __restrict__ X, const float* __restrict__ W,
                         const float* __restrict__ bias, float* __restrict__ out,
                         int doRelu) {
    __shared__ float Xs[16][128];
    __shared__ float Ws[16][64];
    int bm = blockIdx.y * 128;
    int bn = blockIdx.x * 64;
    int tid = threadIdx.x;
    int tx = tid & 15, ty = tid >> 4;
    float acc[8][4];
#pragma unroll
    for (int i = 0; i < 8; i++)
#pragma unroll
        for (int j = 0; j < 4; j++) acc[i][j] = 0.f;

    int r0 = tid >> 2;
    int c0 = (tid & 3) * 4;
    const float* Xp = X + (size_t)bm * 256;

    for (int k0 = 0; k0 < 256; k0 += 16) {
        float4 x0 = *(const float4*)(Xp + (size_t)r0 * 256 + k0 + c0);
        float4 x1 = *(const float4*)(Xp + (size_t)(r0 + 64) * 256 + k0 + c0);
        float4 wv = *(const float4*)(W + (size_t)(bn + r0) * 256 + k0 + c0);
        Xs[c0 + 0][r0] = x0.x; Xs[c0 + 1][r0] = x0.y; Xs[c0 + 2][r0] = x0.z; Xs[c0 + 3][r0] = x0.w;
        Xs[c0 + 0][r0 + 64] = x1.x; Xs[c0 + 1][r0 + 64] = x1.y; Xs[c0 + 2][r0 + 64] = x1.z; Xs[c0 + 3][r0 + 64] = x1.w;
        Ws[c0 + 0][r0] = wv.x; Ws[c0 + 1][r0] = wv.y; Ws[c0 + 2][r0] = wv.z; Ws[c0 + 3][r0] = wv.w;
        __syncthreads();
#pragma unroll
        for (int k = 0; k < 16; k++) {
            float4 a0 = *(const float4*)&Xs[k][ty * 8];
            float4 a1 = *(const float4*)&Xs[k][ty * 8 + 4];
            float4 b = *(const float4*)&Ws[k][tx * 4];
            acc[0][0] += a0.x * b.x; acc[0][1] += a0.x * b.y; acc[0][2] += a0.x * b.z; acc[0][3] += a0.x * b.w;
            acc[1][0] += a0.y * b.x; acc[1][1] += a0.y * b.y; acc[1][2] += a0.y * b.z; acc[1][3] += a0.y * b.w;
            acc[2][0] += a0.z * b.x; acc[2][1] += a0.z * b.y; acc[2][2] += a0.z * b.z; acc[2][3] += a0.z * b.w;
            acc[3][0] += a0.w * b.x; acc[3][1] += a0.w * b.y; acc[3][2] += a0.w * b.z; acc[3][3] += a0.w * b.w;
            acc[4][0] += a1.x * b.x; acc[4][1] += a1.x * b.y; acc[4][2] += a1.x * b.z; acc[4][3] += a1.x * b.w;
            acc[5][0] += a1.y * b.x; acc[5][1] += a1.y * b.y; acc[5][2] += a1.y * b.z; acc[5][3] += a1.y * b.w;
            acc[6][0] += a1.z * b.x; acc[6][1] += a1.z * b.y; acc[6][2] += a1.z * b.z; acc[6][3] += a1.z * b.w;
            acc[7][0] += a1.w * b.x; acc[7][1] += a1.w * b.y; acc[7][2] += a1.w * b.z; acc[7][3] += a1.w * b.w;
        }
        __syncthreads();
    }
    float4 bv = *(const float4*)&bias[bn + tx * 4];
#pragma unroll
    for (int i = 0; i < 8; i++) {
        int m = bm + ty * 8 + i;
        float4 v;
        v.x = acc[i][0] + bv.x; v.y = acc[i][1] + bv.y;
        v.z = acc[i][2] + bv.z; v.w = acc[i][3] + bv.w;
        if (doRelu) {
            v.x = fmaxf(v.x, 0.f); v.y = fmaxf(v.y, 0.f);
            v.z = fmaxf(v.z, 0.f); v.w = fmaxf(v.w, 0.f);
        }
        *(float4*)(out + (size_t)m * 256 + bn + tx * 4) = v;
    }
}

// -------------------- fc3 + log_softmax -------------------------------------
__global__ void fc3_k(const float* __restrict__ x, const float* __restrict__ w,
                      const float* __restrict__ bias, float* __restrict__ out) {
    int b = blockIdx.x;
    int tid = threadIdx.x; // 320
    int j = tid >> 5, lane = tid & 31;
    __shared__ float lg[10];
    __shared__ float lse;
    const float* xr = x + b * HID;
    const float* wr = w + j * HID;
    float s = 0.f;
    for (int k = lane; k < HID; k += 32) s += xr[k] * wr[k];
#pragma unroll
    for (int o = 16; o > 0; o >>= 1) s += __shfl_xor_sync(0xffffffffu, s, o);
    if (lane == 0) lg[j] = s + bias[j];
    __syncthreads();
    if (tid == 0) {
        float m = lg[0];
#pragma unroll
        for (int t = 1; t < 10; t++) m = fmaxf(m, lg[t]);
        float se = 0.f;
#pragma unroll
        for (int t = 0; t < 10; t++) se += expf(lg[t] - m);
        lse = m + logf(se);
    }
    __syncthreads();
    if (tid < 10) out[b * 10 + tid] = lg[tid] - lse;
}

// ---------------------------------------------------------------------------
extern "C" void kernel_launch(void* const* d_in, const int* in_sizes, int n_in,
                              void* d_out, int out_size) {
    const float* img = (const float*)d_in[0];
    const float* qst = (const float*)d_in[1];
    const float* cw[4] = {(const float*)d_in[2], (const float*)d_in[6], (const float*)d_in[10], (const float*)d_in[14]};
    const float* cb[4] = {(const float*)d_in[3], (const float*)d_in[7], (const float*)d_in[11], (const float*)d_in[15]};
    const float* bg[4] = {(const float*)d_in[4], (const float*)d_in[8], (const float*)d_in[12], (const float*)d_in[16]};
    const float* bb[4] = {(const float*)d_in[5], (const float*)d_in[9], (const float*)d_in[13], (const float*)d_in[17]};
    const float* g1w = (const float*)d_in[18]; const float* g1b = (const float*)d_in[19];
    const float* g2w = (const float*)d_in[20]; const float* g2b = (const float*)d_in[21];
    const float* g3w = (const float*)d_in[22]; const float* g3b = (const float*)d_in[23];
    const float* g4w = (const float*)d_in[24]; const float* g4b = (const float*)d_in[25];
    const float* f1w = (const float*)d_in[26]; const float* f1b = (const float*)d_in[27];
    const float* fc2w = (const float*)d_in[28]; const float* fc2b = (const float*)d_in[29];
    const float* fc3w = (const float*)d_in[30]; const float* fc3b = (const float*)d_in[31];
    float* out = (float*)d_out;

    float *buf1, *buf2, *buf3, *buf4, *obj, *A, *B, *Cb, *xg, *xf1, *xf2, *stats;
    __half *wh, *hA, *hB;
    double *psum, *psq;
    cudaGetSymbolAddress((void**)&buf1, g_buf1);
    cudaGetSymbolAddress((void**)&buf2, g_buf2);
    cudaGetSymbolAddress((void**)&buf3, g_buf3);
    cudaGetSymbolAddress((void**)&buf4, g_buf4);
    cudaGetSymbolAddress((void**)&obj, g_obj);
    cudaGetSymbolAddress((void**)&A, g_A);
    cudaGetSymbolAddress((void**)&B, g_B);
    cudaGetSymbolAddress((void**)&Cb, g_Cb);
    cudaGetSymbolAddress((void**)&xg, g_xg);
    cudaGetSymbolAddress((void**)&xf1, g_xf1);
    cudaGetSymbolAddress((void**)&xf2, g_xf2);
    cudaGetSymbolAddress((void**)&stats, g_stats);
    cudaGetSymbolAddress((void**)&psum, g_psum);
    cudaGetSymbolAddress((void**)&psq, g_psq);
    cudaGetSymbolAddress((void**)&wh, g_wh);
    cudaGetSymbolAddress((void**)&hA, g_hbufA);
    cudaGetSymbolAddress((void**)&hB, g_hbufB);

    cudaFuncSetAttribute(gmlp_l2, cudaFuncAttributeMaxDynamicSharedMemorySize, GL2_SMEM);

    // ---- zero accumulators + weight prep ----
    zerod_k<<<1, 128>>>(psum, 96);
    zerod_k<<<1, 128>>>(psq, 96);
    zerof_k<<<512, 256>>>(xg, BATCH * HID);
    whalf_all<<<768, 256>>>(g2w, g3w, g4w, wh);

    // ---- conv stack (fused BN, pixel-blocked) ----
    conv1_f4<<<800, 256>>>(img, cw[0], cb[0], buf1, psum, psq);
    bn_final_f<<<1, 32>>>(psum, psq, 512.0 * 1600.0, bg[0], stats);
    conv24_fP<40, 20, 4><<<200, 256>>>(buf1, cw[1], cb[1], stats, bb[0], buf2, psum + 24, psq + 24);
    bn_final_f<<<1, 32>>>(psum + 24, psq + 24, 512.0 * 400.0, bg[1], stats + 48);
    conv24_fP<20, 10, 2><<<100, 256>>>(buf2, cw[2], cb[2], stats + 48, bb[1], buf3, psum + 48, psq + 48);
    bn_final_f<<<1, 32>>>(psum + 48, psq + 48, 512.0 * 100.0, bg[2], stats + 96);
    conv24_fP<10, 5, 1><<<50, 256>>>(buf3, cw[3], cb[3], stats + 96, bb[2], buf4, psum + 72, psq + 72);
    bn_final_f<<<1, 32>>>(psum + 72, psq + 72, 512.0 * 25.0, bg[3], stats + 144);

    // ---- objects + decomposed g1 ----
    obj_f<<<(BATCH * OBJ * 26 + 255) / 256, 256>>>(buf4, stats + 144, bb[3], obj);
    ab_k<<<BATCH * OBJ, 256>>>(obj, g1w, A, B);
    cb_k<<<BATCH, 256>>>(qst, g1w, g1b, Cb);

    // ---- g2 (fused h1) -> g3 -> g4 (fused pairsum), fp16 MMA + ldmatrix ----
    dim3 ggrid(2, BATCH * OBJ * OBJ / 128);  // (2, 2500)
    gmlp_l2<<<ggrid, 256, GL2_SMEM>>>(A, B, Cb, wh, g2b, hB);
    gmlp_l3<<<ggrid, 256>>>(hB, wh + HID * HID, g3b, hA);
    gmlp_l4<<<ggrid, 256>>>(hA, wh + 2 * HID * HID, g4b, xg);

    // ---- f-MLP (fp32) ----
    dim3 fgrid(256 / 64, BATCH / 128);
    sgemm256<<<fgrid, 256>>>(xg, f1w, f1b, xf1, 1);
    sgemm256<<<fgrid, 256>>>(xf1, fc2w, fc2b, xf2, 1);
    fc3_k<<<BATCH, 320>>>(xf2, fc3w, fc3b, out);
}